// round 2
// baseline (speedup 1.0000x reference)
#include <cuda_runtime.h>
#include <math.h>

#define Bd 4
#define Sd 2048
#define Dd 512
#define Hd 8
#define DHd 64
#define Ed 8
#define HFd 2048
#define Td (Bd*Sd)        /* 8192 tokens */
#define NSLOT (2*Td)      /* 16384 expert-slots */
#define MAXTILES 144

// ---------------- scratch (device globals; no allocation allowed) ----------
__device__ float g_xn[Td*Dd];
__device__ float g_q[Td*Dd];
__device__ float g_k[Td*Dd];
__device__ float g_v[Td*Dd];
__device__ float g_att[Td*Dd];
__device__ float g_h[Td*Dd];
__device__ float g_hn[Td*Dd];
__device__ float g_gate[Td*2];
__device__ int   g_eidx[Td*2];
__device__ int   g_slot_of[Td*2];
__device__ int   g_slot_token[NSLOT];
__device__ int   g_cnt[Ed];
__device__ int   g_off[Ed+1];
__device__ int   g_pos[Ed];
__device__ int   g_tile_e[MAXTILES];
__device__ int   g_tile_row[MAXTILES];
__device__ int   g_tile_end[MAXTILES];
__device__ int   g_ntiles;
__device__ float g_hidden[(size_t)NSLOT*HFd];  /* 128 MB */
__device__ float g_yslot[(size_t)NSLOT*Dd];    /* 32 MB  */

// ---------------- rmsnorm ---------------------------------------------------
__global__ void rmsnorm_k(const float* __restrict__ in, const float* __restrict__ w,
                          float* __restrict__ out) {
    int t = blockIdx.x;
    int tid = threadIdx.x;
    const float* row = in + (size_t)t * Dd;
    float v0 = row[tid], v1 = row[tid + 256];
    float ss = v0 * v0 + v1 * v1;
    #pragma unroll
    for (int o = 16; o; o >>= 1) ss += __shfl_xor_sync(0xffffffffu, ss, o);
    __shared__ float red[8];
    __shared__ float sc;
    if ((tid & 31) == 0) red[tid >> 5] = ss;
    __syncthreads();
    if (tid == 0) {
        float s = 0.f;
        #pragma unroll
        for (int i = 0; i < 8; i++) s += red[i];
        sc = rsqrtf(s / (float)Dd + 1e-5f);
    }
    __syncthreads();
    out[(size_t)t * Dd + tid]       = v0 * sc * w[tid];
    out[(size_t)t * Dd + tid + 256] = v1 * sc * w[tid + 256];
}

// ---------------- generic 128x128x8 SGEMM (double-buffered) ----------------
// MODE 0: C = A@B ; MODE 1: C = A@B + Res
template<int MODE>
__global__ __launch_bounds__(256, 2)
void sgemm_k(const float* __restrict__ A, const float* __restrict__ Bm,
             float* __restrict__ C, const float* __restrict__ Res,
             int M, int N, int K) {
    __shared__ float As[2][8][128];
    __shared__ float Bs[2][8][128];
    int m0 = blockIdx.x * 128, n0 = blockIdx.y * 128;
    int tid = threadIdx.x;
    int tx = tid & 15, ty = tid >> 4;
    int aRow = tid >> 1, aCol = (tid & 1) * 4;
    int bRow = tid >> 5, bCol = (tid & 31) * 4;
    const float* aPtr = A + (size_t)(m0 + aRow) * K + aCol;
    const float* bPtr = Bm + (size_t)bRow * N + n0 + bCol;

    float acc[8][8];
    #pragma unroll
    for (int i = 0; i < 8; i++)
        #pragma unroll
        for (int j = 0; j < 8; j++) acc[i][j] = 0.f;

    int nkt = K >> 3;
    // prologue load tile 0 -> buf 0
    {
        float4 av = *(const float4*)(aPtr);
        As[0][aCol+0][aRow] = av.x; As[0][aCol+1][aRow] = av.y;
        As[0][aCol+2][aRow] = av.z; As[0][aCol+3][aRow] = av.w;
        float4 bv = *(const float4*)(bPtr);
        *(float4*)&Bs[0][bRow][bCol] = bv;
    }
    __syncthreads();
    for (int kt = 0; kt < nkt; kt++) {
        int cur = kt & 1;
        if (kt + 1 < nkt) {
            float4 av = *(const float4*)(aPtr + (size_t)(kt + 1) * 8);
            As[cur^1][aCol+0][aRow] = av.x; As[cur^1][aCol+1][aRow] = av.y;
            As[cur^1][aCol+2][aRow] = av.z; As[cur^1][aCol+3][aRow] = av.w;
            float4 bv = *(const float4*)(bPtr + (size_t)(kt + 1) * 8 * N);
            *(float4*)&Bs[cur^1][bRow][bCol] = bv;
        }
        #pragma unroll
        for (int kk = 0; kk < 8; kk++) {
            float a[8], b[8];
            *(float4*)&a[0] = *(const float4*)&As[cur][kk][ty * 4];
            *(float4*)&a[4] = *(const float4*)&As[cur][kk][64 + ty * 4];
            *(float4*)&b[0] = *(const float4*)&Bs[cur][kk][tx * 4];
            *(float4*)&b[4] = *(const float4*)&Bs[cur][kk][64 + tx * 4];
            #pragma unroll
            for (int i = 0; i < 8; i++)
                #pragma unroll
                for (int j = 0; j < 8; j++) acc[i][j] += a[i] * b[j];
        }
        __syncthreads();
    }
    #pragma unroll
    for (int i = 0; i < 8; i++) {
        int r = (i < 4) ? (ty * 4 + i) : (64 + ty * 4 + (i - 4));
        int grow = m0 + r;
        float* crow = C + (size_t)grow * N + n0;
        float4 lo, hi;
        lo.x = acc[i][0]; lo.y = acc[i][1]; lo.z = acc[i][2]; lo.w = acc[i][3];
        hi.x = acc[i][4]; hi.y = acc[i][5]; hi.z = acc[i][6]; hi.w = acc[i][7];
        if (MODE == 1) {
            const float* rr = Res + (size_t)grow * N + n0;
            float4 r0 = *(const float4*)(rr + tx * 4);
            float4 r1 = *(const float4*)(rr + 64 + tx * 4);
            lo.x += r0.x; lo.y += r0.y; lo.z += r0.z; lo.w += r0.w;
            hi.x += r1.x; hi.y += r1.y; hi.z += r1.z; hi.w += r1.w;
        }
        *(float4*)(crow + tx * 4) = lo;
        *(float4*)(crow + 64 + tx * 4) = hi;
    }
}

// ---------------- grouped expert SGEMM (gather rows, optional gelu) --------
__device__ __forceinline__ float gelu_f(float x) {
    return 0.5f * x * (1.0f + erff(x * 0.70710678118654752f));
}

template<bool GATHER, bool GELU>
__global__ __launch_bounds__(256, 2)
void sgemm_grp(const float* __restrict__ Abase, const float* __restrict__ W,
               float* __restrict__ C, int N, int K) {
    int bx = blockIdx.x;
    if (bx >= g_ntiles) return;
    int e    = g_tile_e[bx];
    int row0 = g_tile_row[bx];
    int rend = g_tile_end[bx];
    int n0   = blockIdx.y * 128;
    const float* Bm = W + (size_t)e * K * N;

    __shared__ float As[2][8][128];
    __shared__ float Bs[2][8][128];
    int tid = threadIdx.x;
    int tx = tid & 15, ty = tid >> 4;
    int aRow = tid >> 1, aCol = (tid & 1) * 4;
    int bRow = tid >> 5, bCol = (tid & 31) * 4;

    int slot = row0 + aRow;
    bool aok = slot < rend;
    const float* aPtr = Abase;
    if (aok) {
        int arow_g = GATHER ? g_slot_token[slot] : slot;
        aPtr = Abase + (size_t)arow_g * K + aCol;
    }
    const float* bPtr = Bm + (size_t)bRow * N + n0 + bCol;

    float acc[8][8];
    #pragma unroll
    for (int i = 0; i < 8; i++)
        #pragma unroll
        for (int j = 0; j < 8; j++) acc[i][j] = 0.f;

    int nkt = K >> 3;
    {
        float4 av = aok ? *(const float4*)(aPtr) : make_float4(0,0,0,0);
        As[0][aCol+0][aRow] = av.x; As[0][aCol+1][aRow] = av.y;
        As[0][aCol+2][aRow] = av.z; As[0][aCol+3][aRow] = av.w;
        float4 bv = *(const float4*)(bPtr);
        *(float4*)&Bs[0][bRow][bCol] = bv;
    }
    __syncthreads();
    for (int kt = 0; kt < nkt; kt++) {
        int cur = kt & 1;
        if (kt + 1 < nkt) {
            float4 av = aok ? *(const float4*)(aPtr + (size_t)(kt + 1) * 8)
                            : make_float4(0,0,0,0);
            As[cur^1][aCol+0][aRow] = av.x; As[cur^1][aCol+1][aRow] = av.y;
            As[cur^1][aCol+2][aRow] = av.z; As[cur^1][aCol+3][aRow] = av.w;
            float4 bv = *(const float4*)(bPtr + (size_t)(kt + 1) * 8 * N);
            *(float4*)&Bs[cur^1][bRow][bCol] = bv;
        }
        #pragma unroll
        for (int kk = 0; kk < 8; kk++) {
            float a[8], b[8];
            *(float4*)&a[0] = *(const float4*)&As[cur][kk][ty * 4];
            *(float4*)&a[4] = *(const float4*)&As[cur][kk][64 + ty * 4];
            *(float4*)&b[0] = *(const float4*)&Bs[cur][kk][tx * 4];
            *(float4*)&b[4] = *(const float4*)&Bs[cur][kk][64 + tx * 4];
            #pragma unroll
            for (int i = 0; i < 8; i++)
                #pragma unroll
                for (int j = 0; j < 8; j++) acc[i][j] += a[i] * b[j];
        }
        __syncthreads();
    }
    #pragma unroll
    for (int i = 0; i < 8; i++) {
        int r = (i < 4) ? (ty * 4 + i) : (64 + ty * 4 + (i - 4));
        int so = row0 + r;
        if (so < rend) {
            float* crow = C + (size_t)so * N + n0;
            float4 lo, hi;
            if (GELU) {
                lo.x = gelu_f(acc[i][0]); lo.y = gelu_f(acc[i][1]);
                lo.z = gelu_f(acc[i][2]); lo.w = gelu_f(acc[i][3]);
                hi.x = gelu_f(acc[i][4]); hi.y = gelu_f(acc[i][5]);
                hi.z = gelu_f(acc[i][6]); hi.w = gelu_f(acc[i][7]);
            } else {
                lo.x = acc[i][0]; lo.y = acc[i][1]; lo.z = acc[i][2]; lo.w = acc[i][3];
                hi.x = acc[i][4]; hi.y = acc[i][5]; hi.z = acc[i][6]; hi.w = acc[i][7];
            }
            *(float4*)(crow + tx * 4) = lo;
            *(float4*)(crow + 64 + tx * 4) = hi;
        }
    }
}

// ---------------- RoPE ------------------------------------------------------
__global__ void rope_k(float* __restrict__ qk) {
    int gid = blockIdx.x * blockDim.x + threadIdx.x;  // Td*256 threads
    if (gid >= Td * 256) return;
    int t = gid >> 8;
    int within = gid & 255;     // h*32 + i
    int i = within & 31;
    int s = t & (Sd - 1);
    float freq = expf(-(float)(2 * i) * (9.210340371976184f / 64.f));
    float ang = (float)s * freq;
    float sn, cs;
    sincosf(ang, &sn, &cs);
    size_t base = (size_t)t * Dd + within * 2;
    float x1 = qk[base], x2 = qk[base + 1];
    qk[base]     = x1 * cs - x2 * sn;
    qk[base + 1] = x1 * sn + x2 * cs;
}

// ---------------- flash-style causal attention (64x64 tiles, fp32) ---------
__global__ __launch_bounds__(256)
void attn_k(const float* __restrict__ q, const float* __restrict__ k,
            const float* __restrict__ v, float* __restrict__ o) {
    __shared__ float QsT[64][64];
    __shared__ float KPs[64][64];   // K^T, then reused for P^T
    __shared__ float Vs[64][64];
    int bh = blockIdx.x;
    int b = bh >> 3, h = bh & 7;
    int qt = blockIdx.y;
    int tid = threadIdx.x, tx = tid & 15, ty = tid >> 4;
    size_t tok0 = (size_t)b * Sd;

    // load Q tile transposed
    #pragma unroll
    for (int l = 0; l < 4; l++) {
        int fidx = tid + l * 256;
        int r = fidx >> 4, dbase = (fidx & 15) * 4;
        float4 qv = *(const float4*)(q + (tok0 + qt * 64 + r) * Dd + h * DHd + dbase);
        QsT[dbase + 0][r] = qv.x; QsT[dbase + 1][r] = qv.y;
        QsT[dbase + 2][r] = qv.z; QsT[dbase + 3][r] = qv.w;
    }

    float m[4], lsum[4], accO[4][4];
    #pragma unroll
    for (int i = 0; i < 4; i++) {
        m[i] = -1e30f; lsum[i] = 0.f;
        #pragma unroll
        for (int j = 0; j < 4; j++) accO[i][j] = 0.f;
    }

    for (int kt = 0; kt <= qt; kt++) {
        __syncthreads();   // prior-iter reads of KPs/Vs done
        #pragma unroll
        for (int l = 0; l < 4; l++) {
            int fidx = tid + l * 256;
            int r = fidx >> 4, dbase = (fidx & 15) * 4;
            size_t gi = (tok0 + kt * 64 + r) * Dd + h * DHd + dbase;
            float4 kv = *(const float4*)(k + gi);
            KPs[dbase + 0][r] = kv.x; KPs[dbase + 1][r] = kv.y;
            KPs[dbase + 2][r] = kv.z; KPs[dbase + 3][r] = kv.w;
            float4 vv = *(const float4*)(v + gi);
            *(float4*)&Vs[r][dbase] = vv;
        }
        __syncthreads();

        float sc[4][4];
        #pragma unroll
        for (int i = 0; i < 4; i++)
            #pragma unroll
            for (int j = 0; j < 4; j++) sc[i][j] = 0.f;
        #pragma unroll 8
        for (int d = 0; d < 64; d++) {
            float a[4], bb[4];
            *(float4*)a  = *(const float4*)&QsT[d][ty * 4];
            *(float4*)bb = *(const float4*)&KPs[d][tx * 4];
            #pragma unroll
            for (int i = 0; i < 4; i++)
                #pragma unroll
                for (int j = 0; j < 4; j++) sc[i][j] += a[i] * bb[j];
        }
        const float SCALE = 0.125f;  // 1/sqrt(64)
        if (kt == qt) {
            #pragma unroll
            for (int i = 0; i < 4; i++)
                #pragma unroll
                for (int j = 0; j < 4; j++) {
                    int qr = ty * 4 + i, kc = tx * 4 + j;
                    sc[i][j] = (kc <= qr) ? sc[i][j] * SCALE : -1e30f;
                }
        } else {
            #pragma unroll
            for (int i = 0; i < 4; i++)
                #pragma unroll
                for (int j = 0; j < 4; j++) sc[i][j] *= SCALE;
        }

        float p[4][4];
        #pragma unroll
        for (int i = 0; i < 4; i++) {
            float tm = sc[i][0];
            tm = fmaxf(tm, sc[i][1]); tm = fmaxf(tm, sc[i][2]); tm = fmaxf(tm, sc[i][3]);
            #pragma unroll
            for (int ofs = 8; ofs; ofs >>= 1)
                tm = fmaxf(tm, __shfl_xor_sync(0xffffffffu, tm, ofs));
            float mn = fmaxf(m[i], tm);
            float alpha = expf(m[i] - mn);
            float rs = 0.f;
            #pragma unroll
            for (int j = 0; j < 4; j++) { p[i][j] = expf(sc[i][j] - mn); rs += p[i][j]; }
            #pragma unroll
            for (int ofs = 8; ofs; ofs >>= 1)
                rs += __shfl_xor_sync(0xffffffffu, rs, ofs);
            lsum[i] = lsum[i] * alpha + rs;
            m[i] = mn;
            #pragma unroll
            for (int j = 0; j < 4; j++) accO[i][j] *= alpha;
        }

        __syncthreads();  // done reading KPs as K^T
        #pragma unroll
        for (int i = 0; i < 4; i++)
            #pragma unroll
            for (int j = 0; j < 4; j++)
                KPs[tx * 4 + j][ty * 4 + i] = p[i][j];   // store P^T
        __syncthreads();

        #pragma unroll 8
        for (int kk = 0; kk < 64; kk++) {
            float a[4], bb[4];
            *(float4*)a  = *(const float4*)&KPs[kk][ty * 4];
            *(float4*)bb = *(const float4*)&Vs[kk][tx * 4];
            #pragma unroll
            for (int i = 0; i < 4; i++)
                #pragma unroll
                for (int j = 0; j < 4; j++) accO[i][j] += a[i] * bb[j];
        }
    }

    #pragma unroll
    for (int i = 0; i < 4; i++) {
        float inv = 1.0f / lsum[i];
        float4 ov;
        ov.x = accO[i][0] * inv; ov.y = accO[i][1] * inv;
        ov.z = accO[i][2] * inv; ov.w = accO[i][3] * inv;
        *(float4*)(o + (tok0 + qt * 64 + ty * 4 + i) * Dd + h * DHd + tx * 4) = ov;
    }
}

// ---------------- router / scatter -----------------------------------------
__global__ void zero_cnt_k() { if (threadIdx.x < Ed) g_cnt[threadIdx.x] = 0; }

__global__ void router_k(const float* __restrict__ hn, const float* __restrict__ rw) {
    int warp = (blockIdx.x * blockDim.x + threadIdx.x) >> 5;
    int lane = threadIdx.x & 31;
    if (warp >= Td) return;
    const float* row = hn + (size_t)warp * Dd;
    float acc[Ed];
    #pragma unroll
    for (int e = 0; e < Ed; e++) acc[e] = 0.f;
    for (int d = lane; d < Dd; d += 32) {
        float x = row[d];
        #pragma unroll
        for (int e = 0; e < Ed; e++) acc[e] += x * rw[d * Ed + e];
    }
    #pragma unroll
    for (int e = 0; e < Ed; e++)
        #pragma unroll
        for (int o = 16; o; o >>= 1)
            acc[e] += __shfl_xor_sync(0xffffffffu, acc[e], o);
    if (lane == 0) {
        int i0 = 0;
        #pragma unroll
        for (int e = 1; e < Ed; e++) if (acc[e] > acc[i0]) i0 = e;
        int i1 = (i0 == 0) ? 1 : 0;
        #pragma unroll
        for (int e = 0; e < Ed; e++) if (e != i0 && acc[e] > acc[i1]) i1 = e;
        float ex = expf(acc[i1] - acc[i0]);
        float g0 = 1.f / (1.f + ex);
        float g1 = ex / (1.f + ex);
        g_eidx[warp * 2] = i0; g_eidx[warp * 2 + 1] = i1;
        g_gate[warp * 2] = g0; g_gate[warp * 2 + 1] = g1;
        atomicAdd(&g_cnt[i0], 1);
        atomicAdd(&g_cnt[i1], 1);
    }
}

__global__ void tiles_k() {
    int off = 0, nt = 0;
    for (int e = 0; e < Ed; e++) {
        g_off[e] = off; g_pos[e] = 0;
        int c = g_cnt[e];
        for (int r = 0; r < c; r += 128) {
            g_tile_e[nt] = e; g_tile_row[nt] = off + r; g_tile_end[nt] = off + c; nt++;
        }
        off += c;
    }
    g_off[Ed] = off;
    g_ntiles = nt;
}

__global__ void assign_k() {
    int t = blockIdx.x * blockDim.x + threadIdx.x;
    if (t >= Td) return;
    #pragma unroll
    for (int kk = 0; kk < 2; kk++) {
        int e = g_eidx[t * 2 + kk];
        int p = atomicAdd(&g_pos[e], 1);
        int slot = g_off[e] + p;
        g_slot_token[slot] = t;
        g_slot_of[t * 2 + kk] = slot;
    }
}

__global__ void final_k(float* __restrict__ out) {
    int idx = blockIdx.x * blockDim.x + threadIdx.x;
    if (idx >= Td * Dd) return;
    int t = idx >> 9, d = idx & 511;
    float r = g_h[idx];
    r += g_gate[t * 2]     * g_yslot[(size_t)g_slot_of[t * 2]     * Dd + d];
    r += g_gate[t * 2 + 1] * g_yslot[(size_t)g_slot_of[t * 2 + 1] * Dd + d];
    out[idx] = r;
}

// ---------------- launch -----------------------------------------------------
extern "C" void kernel_launch(void* const* d_in, const int* in_sizes, int n_in,
                              void* d_out, int out_size) {
    const float* x   = (const float*)d_in[0];
    const float* anw = (const float*)d_in[1];
    const float* wq  = (const float*)d_in[2];
    const float* wk  = (const float*)d_in[3];
    const float* wv  = (const float*)d_in[4];
    const float* wo  = (const float*)d_in[5];
    const float* fnw = (const float*)d_in[6];
    const float* rw  = (const float*)d_in[7];
    const float* w1  = (const float*)d_in[8];
    const float* w2  = (const float*)d_in[9];
    float* out = (float*)d_out;

    float *p_xn, *p_q, *p_k, *p_v, *p_att, *p_h, *p_hn, *p_hidden, *p_yslot;
    cudaGetSymbolAddress((void**)&p_xn, g_xn);
    cudaGetSymbolAddress((void**)&p_q, g_q);
    cudaGetSymbolAddress((void**)&p_k, g_k);
    cudaGetSymbolAddress((void**)&p_v, g_v);
    cudaGetSymbolAddress((void**)&p_att, g_att);
    cudaGetSymbolAddress((void**)&p_h, g_h);
    cudaGetSymbolAddress((void**)&p_hn, g_hn);
    cudaGetSymbolAddress((void**)&p_hidden, g_hidden);
    cudaGetSymbolAddress((void**)&p_yslot, g_yslot);

    // 1) rmsnorm(x)
    rmsnorm_k<<<Td, 256>>>(x, anw, p_xn);
    // 2) q,k,v GEMMs
    dim3 gqkv(Td / 128, Dd / 128);
    sgemm_k<0><<<gqkv, 256>>>(p_xn, wq, p_q, nullptr, Td, Dd, Dd);
    sgemm_k<0><<<gqkv, 256>>>(p_xn, wk, p_k, nullptr, Td, Dd, Dd);
    sgemm_k<0><<<gqkv, 256>>>(p_xn, wv, p_v, nullptr, Td, Dd, Dd);
    // 3) RoPE on q,k
    rope_k<<<(Td * 256) / 256, 256>>>(p_q);
    rope_k<<<(Td * 256) / 256, 256>>>(p_k);
    // 4) causal attention
    attn_k<<<dim3(Bd * Hd, Sd / 64), 256>>>(p_q, p_k, p_v, p_att);
    // 5) O projection + residual
    sgemm_k<1><<<gqkv, 256>>>(p_att, wo, p_h, x, Td, Dd, Dd);
    // 6) rmsnorm(h)
    rmsnorm_k<<<Td, 256>>>(p_h, fnw, p_hn);
    // 7) router + expert grouping
    zero_cnt_k<<<1, 32>>>();
    router_k<<<Td / 8, 256>>>(p_hn, rw);
    tiles_k<<<1, 1>>>();
    assign_k<<<Td / 256, 256>>>();
    // 8) expert GEMM 1: hidden = gelu(hn @ w1[e])
    sgemm_grp<true, true><<<dim3(MAXTILES, HFd / 128), 256>>>(p_hn, w1, p_hidden, HFd, Dd);
    // 9) expert GEMM 2: y = hidden @ w2[e]
    sgemm_grp<false, false><<<dim3(MAXTILES, Dd / 128), 256>>>(p_hidden, w2, p_yslot, Dd, HFd);
    // 10) final gather + residual
    final_k<<<(Td * Dd) / 256, 256>>>(out);
}

// round 3
// speedup vs baseline: 1.6160x; 1.6160x over previous
#include <cuda_runtime.h>
#include <math.h>
#include <stdint.h>

#define Bd 4
#define Sd 2048
#define Dd 512
#define Hd 8
#define DHd 64
#define Ed 8
#define HFd 2048
#define Td (Bd*Sd)        /* 8192 tokens */
#define NSLOT (2*Td)      /* 16384 expert-slots */
#define MAXTILES 144

// ---------------- scratch (device globals; no allocation allowed) ----------
__device__ float g_xn[Td*Dd];
__device__ float g_q[Td*Dd];
__device__ float g_k[Td*Dd];
__device__ float g_v[Td*Dd];
__device__ float g_att[Td*Dd];
__device__ float g_h[Td*Dd];
__device__ float g_hn[Td*Dd];
__device__ float g_gate[Td*2];
__device__ int   g_eidx[Td*2];
__device__ int   g_slot_of[Td*2];
__device__ int   g_slot_token[NSLOT];
__device__ int   g_cnt[Ed];
__device__ int   g_off[Ed+1];
__device__ int   g_pos[Ed];
__device__ int   g_tile_e[MAXTILES];
__device__ int   g_tile_row[MAXTILES];
__device__ int   g_tile_end[MAXTILES];
__device__ int   g_ntiles;
__device__ float g_hidden[(size_t)NSLOT*HFd];  /* 128 MB */
__device__ float g_yslot[(size_t)NSLOT*Dd];    /* 32 MB  */

// ---------------- rmsnorm ---------------------------------------------------
__global__ void rmsnorm_k(const float* __restrict__ in, const float* __restrict__ w,
                          float* __restrict__ out) {
    int t = blockIdx.x;
    int tid = threadIdx.x;
    const float* row = in + (size_t)t * Dd;
    float v0 = row[tid], v1 = row[tid + 256];
    float ss = v0 * v0 + v1 * v1;
    #pragma unroll
    for (int o = 16; o; o >>= 1) ss += __shfl_xor_sync(0xffffffffu, ss, o);
    __shared__ float red[8];
    __shared__ float sc;
    if ((tid & 31) == 0) red[tid >> 5] = ss;
    __syncthreads();
    if (tid == 0) {
        float s = 0.f;
        #pragma unroll
        for (int i = 0; i < 8; i++) s += red[i];
        sc = rsqrtf(s / (float)Dd + 1e-5f);
    }
    __syncthreads();
    out[(size_t)t * Dd + tid]       = v0 * sc * w[tid];
    out[(size_t)t * Dd + tid + 256] = v1 * sc * w[tid + 256];
}

// ---------------- generic 128x128x8 SGEMM (double-buffered, fp32) ----------
// MODE 0: C = A@B ; MODE 1: C = A@B + Res
template<int MODE>
__global__ __launch_bounds__(256, 2)
void sgemm_k(const float* __restrict__ A, const float* __restrict__ Bm,
             float* __restrict__ C, const float* __restrict__ Res,
             int M, int N, int K) {
    __shared__ float As[2][8][128];
    __shared__ float Bs[2][8][128];
    int m0 = blockIdx.x * 128, n0 = blockIdx.y * 128;
    int tid = threadIdx.x;
    int tx = tid & 15, ty = tid >> 4;
    int aRow = tid >> 1, aCol = (tid & 1) * 4;
    int bRow = tid >> 5, bCol = (tid & 31) * 4;
    const float* aPtr = A + (size_t)(m0 + aRow) * K + aCol;
    const float* bPtr = Bm + (size_t)bRow * N + n0 + bCol;

    float acc[8][8];
    #pragma unroll
    for (int i = 0; i < 8; i++)
        #pragma unroll
        for (int j = 0; j < 8; j++) acc[i][j] = 0.f;

    int nkt = K >> 3;
    {
        float4 av = *(const float4*)(aPtr);
        As[0][aCol+0][aRow] = av.x; As[0][aCol+1][aRow] = av.y;
        As[0][aCol+2][aRow] = av.z; As[0][aCol+3][aRow] = av.w;
        float4 bv = *(const float4*)(bPtr);
        *(float4*)&Bs[0][bRow][bCol] = bv;
    }
    __syncthreads();
    for (int kt = 0; kt < nkt; kt++) {
        int cur = kt & 1;
        if (kt + 1 < nkt) {
            float4 av = *(const float4*)(aPtr + (size_t)(kt + 1) * 8);
            As[cur^1][aCol+0][aRow] = av.x; As[cur^1][aCol+1][aRow] = av.y;
            As[cur^1][aCol+2][aRow] = av.z; As[cur^1][aCol+3][aRow] = av.w;
            float4 bv = *(const float4*)(bPtr + (size_t)(kt + 1) * 8 * N);
            *(float4*)&Bs[cur^1][bRow][bCol] = bv;
        }
        #pragma unroll
        for (int kk = 0; kk < 8; kk++) {
            float a[8], b[8];
            *(float4*)&a[0] = *(const float4*)&As[cur][kk][ty * 4];
            *(float4*)&a[4] = *(const float4*)&As[cur][kk][64 + ty * 4];
            *(float4*)&b[0] = *(const float4*)&Bs[cur][kk][tx * 4];
            *(float4*)&b[4] = *(const float4*)&Bs[cur][kk][64 + tx * 4];
            #pragma unroll
            for (int i = 0; i < 8; i++)
                #pragma unroll
                for (int j = 0; j < 8; j++) acc[i][j] += a[i] * b[j];
        }
        __syncthreads();
    }
    #pragma unroll
    for (int i = 0; i < 8; i++) {
        int r = (i < 4) ? (ty * 4 + i) : (64 + ty * 4 + (i - 4));
        int grow = m0 + r;
        float* crow = C + (size_t)grow * N + n0;
        float4 lo, hi;
        lo.x = acc[i][0]; lo.y = acc[i][1]; lo.z = acc[i][2]; lo.w = acc[i][3];
        hi.x = acc[i][4]; hi.y = acc[i][5]; hi.z = acc[i][6]; hi.w = acc[i][7];
        if (MODE == 1) {
            const float* rr = Res + (size_t)grow * N + n0;
            float4 r0 = *(const float4*)(rr + tx * 4);
            float4 r1 = *(const float4*)(rr + 64 + tx * 4);
            lo.x += r0.x; lo.y += r0.y; lo.z += r0.z; lo.w += r0.w;
            hi.x += r1.x; hi.y += r1.y; hi.z += r1.z; hi.w += r1.w;
        }
        *(float4*)(crow + tx * 4) = lo;
        *(float4*)(crow + 64 + tx * 4) = hi;
    }
}

// ---------------- tf32 tensor-core grouped expert GEMM ---------------------
__device__ __forceinline__ float gelu_f(float x) {
    return 0.5f * x * (1.0f + erff(x * 0.70710678118654752f));
}

__device__ __forceinline__ void cp16(uint32_t dst, const void* src) {
    asm volatile("cp.async.ca.shared.global [%0], [%1], 16;\n" :: "r"(dst), "l"(src));
}

#define AST 36               /* A smem row stride (floats), pad -> conflict-free frags */
#define BST 132              /* B smem row stride (floats) */
#define ASZ (128*AST)        /* floats per A buffer  */
#define BSZ (32*BST)         /* floats per B buffer  */
#define SMEM_GRP ((2*ASZ + 2*BSZ) * 4)

// C[slot, n] = act( A[row(slot), :K] @ W[e, :K, n] )
template<bool GATHER, bool GELU>
__global__ __launch_bounds__(256, 2)
void mma_grp(const float* __restrict__ Abase, const float* __restrict__ W,
             float* __restrict__ Cout, int N, int K) {
    extern __shared__ float sm_[];
    float* As = sm_;              // [2][128][AST]
    float* Bs = sm_ + 2 * ASZ;    // [2][32][BST]
    int bx = blockIdx.x;
    if (bx >= g_ntiles) return;
    const int e = g_tile_e[bx], row0 = g_tile_row[bx], rend = g_tile_end[bx];
    const int n0 = blockIdx.y * 128;
    const float* Bg = W + (size_t)e * K * N + n0;

    const int tid = threadIdx.x;
    const int lane = tid & 31, wid = tid >> 5;
    const int wm = wid >> 2, wn = wid & 3;   // warp tile origin (wm*64, wn*32)
    const int lr = lane >> 2, lc = lane & 3;

    // ---- loader setup ----
    const int aR = tid >> 3, aC = (tid & 7) * 4;   // A: 32 rows/pass x 32 cols
    const float* aSrc[4];
    #pragma unroll
    for (int p = 0; p < 4; p++) {
        int grow = row0 + p * 32 + aR;
        int gsafe = grow < rend ? grow : rend - 1;
        int srow = GATHER ? g_slot_token[gsafe] : gsafe;
        aSrc[p] = Abase + (size_t)srow * K + aC;
    }
    const int bR = tid >> 5, bC = (tid & 31) * 4;  // B: 8 rows/pass x 128 cols
    const float* bSrc = Bg + (size_t)bR * N + bC;

    uint32_t aDst = (uint32_t)__cvta_generic_to_shared(As) + (aR * AST + aC) * 4;
    uint32_t bDst = (uint32_t)__cvta_generic_to_shared(Bs) + (bR * BST + bC) * 4;

    float acc[4][4][4];
    #pragma unroll
    for (int i = 0; i < 4; i++)
        #pragma unroll
        for (int j = 0; j < 4; j++)
            #pragma unroll
            for (int r = 0; r < 4; r++) acc[i][j][r] = 0.f;

    const int nkb = K >> 5;
    // prologue: stage k-block 0 into buffer 0
    #pragma unroll
    for (int p = 0; p < 4; p++) cp16(aDst + p * 32 * AST * 4, aSrc[p]);
    #pragma unroll
    for (int p = 0; p < 4; p++) cp16(bDst + p * 8 * BST * 4, bSrc + (size_t)p * 8 * N);
    asm volatile("cp.async.commit_group;\n");
    asm volatile("cp.async.wait_group 0;\n");
    __syncthreads();

    int buf = 0;
    for (int kb = 0; kb < nkb; kb++) {
        if (kb + 1 < nkb) {
            int ko = (kb + 1) * 32;
            uint32_t ab = aDst + (buf ^ 1) * ASZ * 4;
            uint32_t bb = bDst + (buf ^ 1) * BSZ * 4;
            #pragma unroll
            for (int p = 0; p < 4; p++) cp16(ab + p * 32 * AST * 4, aSrc[p] + ko);
            #pragma unroll
            for (int p = 0; p < 4; p++)
                cp16(bb + p * 8 * BST * 4, bSrc + (size_t)(ko) * N + (size_t)p * 8 * N);
            asm volatile("cp.async.commit_group;\n");
        }
        const float* Ab = As + buf * ASZ;
        const float* Bb = Bs + buf * BSZ;
        #pragma unroll
        for (int kk = 0; kk < 4; kk++) {
            int k0 = kk * 8 + lc;
            uint32_t af[4][4], bf[4][2];
            #pragma unroll
            for (int am = 0; am < 4; am++) {
                int m = wm * 64 + am * 16 + lr;
                af[am][0] = __float_as_uint(Ab[m * AST + k0]);
                af[am][1] = __float_as_uint(Ab[(m + 8) * AST + k0]);
                af[am][2] = __float_as_uint(Ab[m * AST + k0 + 4]);
                af[am][3] = __float_as_uint(Ab[(m + 8) * AST + k0 + 4]);
            }
            #pragma unroll
            for (int an = 0; an < 4; an++) {
                int n = wn * 32 + an * 8 + lr;
                bf[an][0] = __float_as_uint(Bb[k0 * BST + n]);
                bf[an][1] = __float_as_uint(Bb[(k0 + 4) * BST + n]);
            }
            #pragma unroll
            for (int am = 0; am < 4; am++)
                #pragma unroll
                for (int an = 0; an < 4; an++)
                    asm volatile(
                        "mma.sync.aligned.m16n8k8.row.col.f32.tf32.tf32.f32 "
                        "{%0,%1,%2,%3}, {%4,%5,%6,%7}, {%8,%9}, {%0,%1,%2,%3};\n"
                        : "+f"(acc[am][an][0]), "+f"(acc[am][an][1]),
                          "+f"(acc[am][an][2]), "+f"(acc[am][an][3])
                        : "r"(af[am][0]), "r"(af[am][1]), "r"(af[am][2]), "r"(af[am][3]),
                          "r"(bf[an][0]), "r"(bf[an][1]));
        }
        if (kb + 1 < nkb) asm volatile("cp.async.wait_group 0;\n");
        __syncthreads();
        buf ^= 1;
    }

    // ---- epilogue ----
    #pragma unroll
    for (int am = 0; am < 4; am++) {
        int s0 = row0 + wm * 64 + am * 16 + lr;
        #pragma unroll
        for (int an = 0; an < 4; an++) {
            int gc = n0 + wn * 32 + an * 8 + 2 * lc;
            float v0 = acc[am][an][0], v1 = acc[am][an][1];
            float v2 = acc[am][an][2], v3 = acc[am][an][3];
            if (GELU) {
                v0 = gelu_f(v0); v1 = gelu_f(v1);
                v2 = gelu_f(v2); v3 = gelu_f(v3);
            }
            if (s0 < rend) {
                float2 t; t.x = v0; t.y = v1;
                *(float2*)&Cout[(size_t)s0 * N + gc] = t;
            }
            if (s0 + 8 < rend) {
                float2 t; t.x = v2; t.y = v3;
                *(float2*)&Cout[(size_t)(s0 + 8) * N + gc] = t;
            }
        }
    }
}

// ---------------- RoPE ------------------------------------------------------
__global__ void rope_k(float* __restrict__ qk) {
    int gid = blockIdx.x * blockDim.x + threadIdx.x;
    if (gid >= Td * 256) return;
    int t = gid >> 8;
    int within = gid & 255;
    int i = within & 31;
    int s = t & (Sd - 1);
    float freq = expf(-(float)(2 * i) * (9.210340371976184f / 64.f));
    float ang = (float)s * freq;
    float sn, cs;
    sincosf(ang, &sn, &cs);
    size_t base = (size_t)t * Dd + within * 2;
    float x1 = qk[base], x2 = qk[base + 1];
    qk[base]     = x1 * cs - x2 * sn;
    qk[base + 1] = x1 * sn + x2 * cs;
}

// ---------------- flash-style causal attention (64x64 tiles, fp32) ---------
__global__ __launch_bounds__(256)
void attn_k(const float* __restrict__ q, const float* __restrict__ k,
            const float* __restrict__ v, float* __restrict__ o) {
    __shared__ float QsT[64][64];
    __shared__ float KPs[64][64];
    __shared__ float Vs[64][64];
    int bh = blockIdx.x;
    int b = bh >> 3, h = bh & 7;
    int qt = blockIdx.y;
    int tid = threadIdx.x, tx = tid & 15, ty = tid >> 4;
    size_t tok0 = (size_t)b * Sd;

    #pragma unroll
    for (int l = 0; l < 4; l++) {
        int fidx = tid + l * 256;
        int r = fidx >> 4, dbase = (fidx & 15) * 4;
        float4 qv = *(const float4*)(q + (tok0 + qt * 64 + r) * Dd + h * DHd + dbase);
        QsT[dbase + 0][r] = qv.x; QsT[dbase + 1][r] = qv.y;
        QsT[dbase + 2][r] = qv.z; QsT[dbase + 3][r] = qv.w;
    }

    float m[4], lsum[4], accO[4][4];
    #pragma unroll
    for (int i = 0; i < 4; i++) {
        m[i] = -1e30f; lsum[i] = 0.f;
        #pragma unroll
        for (int j = 0; j < 4; j++) accO[i][j] = 0.f;
    }

    for (int kt = 0; kt <= qt; kt++) {
        __syncthreads();
        #pragma unroll
        for (int l = 0; l < 4; l++) {
            int fidx = tid + l * 256;
            int r = fidx >> 4, dbase = (fidx & 15) * 4;
            size_t gi = (tok0 + kt * 64 + r) * Dd + h * DHd + dbase;
            float4 kv = *(const float4*)(k + gi);
            KPs[dbase + 0][r] = kv.x; KPs[dbase + 1][r] = kv.y;
            KPs[dbase + 2][r] = kv.z; KPs[dbase + 3][r] = kv.w;
            float4 vv = *(const float4*)(v + gi);
            *(float4*)&Vs[r][dbase] = vv;
        }
        __syncthreads();

        float sc[4][4];
        #pragma unroll
        for (int i = 0; i < 4; i++)
            #pragma unroll
            for (int j = 0; j < 4; j++) sc[i][j] = 0.f;
        #pragma unroll 8
        for (int d = 0; d < 64; d++) {
            float a[4], bb[4];
            *(float4*)a  = *(const float4*)&QsT[d][ty * 4];
            *(float4*)bb = *(const float4*)&KPs[d][tx * 4];
            #pragma unroll
            for (int i = 0; i < 4; i++)
                #pragma unroll
                for (int j = 0; j < 4; j++) sc[i][j] += a[i] * bb[j];
        }
        const float SCALE = 0.125f;
        if (kt == qt) {
            #pragma unroll
            for (int i = 0; i < 4; i++)
                #pragma unroll
                for (int j = 0; j < 4; j++) {
                    int qr = ty * 4 + i, kc = tx * 4 + j;
                    sc[i][j] = (kc <= qr) ? sc[i][j] * SCALE : -1e30f;
                }
        } else {
            #pragma unroll
            for (int i = 0; i < 4; i++)
                #pragma unroll
                for (int j = 0; j < 4; j++) sc[i][j] *= SCALE;
        }

        float p[4][4];
        #pragma unroll
        for (int i = 0; i < 4; i++) {
            float tm = sc[i][0];
            tm = fmaxf(tm, sc[i][1]); tm = fmaxf(tm, sc[i][2]); tm = fmaxf(tm, sc[i][3]);
            #pragma unroll
            for (int ofs = 8; ofs; ofs >>= 1)
                tm = fmaxf(tm, __shfl_xor_sync(0xffffffffu, tm, ofs));
            float mn = fmaxf(m[i], tm);
            float alpha = expf(m[i] - mn);
            float rs = 0.f;
            #pragma unroll
            for (int j = 0; j < 4; j++) { p[i][j] = expf(sc[i][j] - mn); rs += p[i][j]; }
            #pragma unroll
            for (int ofs = 8; ofs; ofs >>= 1)
                rs += __shfl_xor_sync(0xffffffffu, rs, ofs);
            lsum[i] = lsum[i] * alpha + rs;
            m[i] = mn;
            #pragma unroll
            for (int j = 0; j < 4; j++) accO[i][j] *= alpha;
        }

        __syncthreads();
        #pragma unroll
        for (int i = 0; i < 4; i++)
            #pragma unroll
            for (int j = 0; j < 4; j++)
                KPs[tx * 4 + j][ty * 4 + i] = p[i][j];
        __syncthreads();

        #pragma unroll 8
        for (int kk = 0; kk < 64; kk++) {
            float a[4], bb[4];
            *(float4*)a  = *(const float4*)&KPs[kk][ty * 4];
            *(float4*)bb = *(const float4*)&Vs[kk][tx * 4];
            #pragma unroll
            for (int i = 0; i < 4; i++)
                #pragma unroll
                for (int j = 0; j < 4; j++) accO[i][j] += a[i] * bb[j];
        }
    }

    #pragma unroll
    for (int i = 0; i < 4; i++) {
        float inv = 1.0f / lsum[i];
        float4 ov;
        ov.x = accO[i][0] * inv; ov.y = accO[i][1] * inv;
        ov.z = accO[i][2] * inv; ov.w = accO[i][3] * inv;
        *(float4*)(o + (tok0 + qt * 64 + ty * 4 + i) * Dd + h * DHd + tx * 4) = ov;
    }
}

// ---------------- router / scatter -----------------------------------------
__global__ void zero_cnt_k() { if (threadIdx.x < Ed) g_cnt[threadIdx.x] = 0; }

__global__ void router_k(const float* __restrict__ hn, const float* __restrict__ rw) {
    int warp = (blockIdx.x * blockDim.x + threadIdx.x) >> 5;
    int lane = threadIdx.x & 31;
    if (warp >= Td) return;
    const float* row = hn + (size_t)warp * Dd;
    float acc[Ed];
    #pragma unroll
    for (int e = 0; e < Ed; e++) acc[e] = 0.f;
    for (int d = lane; d < Dd; d += 32) {
        float x = row[d];
        #pragma unroll
        for (int e = 0; e < Ed; e++) acc[e] += x * rw[d * Ed + e];
    }
    #pragma unroll
    for (int e = 0; e < Ed; e++)
        #pragma unroll
        for (int o = 16; o; o >>= 1)
            acc[e] += __shfl_xor_sync(0xffffffffu, acc[e], o);
    if (lane == 0) {
        int i0 = 0;
        #pragma unroll
        for (int e = 1; e < Ed; e++) if (acc[e] > acc[i0]) i0 = e;
        int i1 = (i0 == 0) ? 1 : 0;
        #pragma unroll
        for (int e = 0; e < Ed; e++) if (e != i0 && acc[e] > acc[i1]) i1 = e;
        float ex = expf(acc[i1] - acc[i0]);
        float g0 = 1.f / (1.f + ex);
        float g1 = ex / (1.f + ex);
        g_eidx[warp * 2] = i0; g_eidx[warp * 2 + 1] = i1;
        g_gate[warp * 2] = g0; g_gate[warp * 2 + 1] = g1;
        atomicAdd(&g_cnt[i0], 1);
        atomicAdd(&g_cnt[i1], 1);
    }
}

__global__ void tiles_k() {
    int off = 0, nt = 0;
    for (int e = 0; e < Ed; e++) {
        g_off[e] = off; g_pos[e] = 0;
        int c = g_cnt[e];
        for (int r = 0; r < c; r += 128) {
            g_tile_e[nt] = e; g_tile_row[nt] = off + r; g_tile_end[nt] = off + c; nt++;
        }
        off += c;
    }
    g_off[Ed] = off;
    g_ntiles = nt;
}

__global__ void assign_k() {
    int t = blockIdx.x * blockDim.x + threadIdx.x;
    if (t >= Td) return;
    #pragma unroll
    for (int kk = 0; kk < 2; kk++) {
        int e = g_eidx[t * 2 + kk];
        int p = atomicAdd(&g_pos[e], 1);
        int slot = g_off[e] + p;
        g_slot_token[slot] = t;
        g_slot_of[t * 2 + kk] = slot;
    }
}

__global__ void final_k(float* __restrict__ out) {
    int idx = blockIdx.x * blockDim.x + threadIdx.x;
    if (idx >= Td * Dd) return;
    int t = idx >> 9, d = idx & 511;
    float r = g_h[idx];
    r += g_gate[t * 2]     * g_yslot[(size_t)g_slot_of[t * 2]     * Dd + d];
    r += g_gate[t * 2 + 1] * g_yslot[(size_t)g_slot_of[t * 2 + 1] * Dd + d];
    out[idx] = r;
}

// ---------------- launch -----------------------------------------------------
extern "C" void kernel_launch(void* const* d_in, const int* in_sizes, int n_in,
                              void* d_out, int out_size) {
    const float* x   = (const float*)d_in[0];
    const float* anw = (const float*)d_in[1];
    const float* wq  = (const float*)d_in[2];
    const float* wk  = (const float*)d_in[3];
    const float* wv  = (const float*)d_in[4];
    const float* wo  = (const float*)d_in[5];
    const float* fnw = (const float*)d_in[6];
    const float* rw  = (const float*)d_in[7];
    const float* w1  = (const float*)d_in[8];
    const float* w2  = (const float*)d_in[9];
    float* out = (float*)d_out;

    float *p_xn, *p_q, *p_k, *p_v, *p_att, *p_h, *p_hn, *p_hidden, *p_yslot;
    cudaGetSymbolAddress((void**)&p_xn, g_xn);
    cudaGetSymbolAddress((void**)&p_q, g_q);
    cudaGetSymbolAddress((void**)&p_k, g_k);
    cudaGetSymbolAddress((void**)&p_v, g_v);
    cudaGetSymbolAddress((void**)&p_att, g_att);
    cudaGetSymbolAddress((void**)&p_h, g_h);
    cudaGetSymbolAddress((void**)&p_hn, g_hn);
    cudaGetSymbolAddress((void**)&p_hidden, g_hidden);
    cudaGetSymbolAddress((void**)&p_yslot, g_yslot);

    cudaFuncSetAttribute(mma_grp<true, true>,
                         cudaFuncAttributeMaxDynamicSharedMemorySize, SMEM_GRP);
    cudaFuncSetAttribute(mma_grp<false, false>,
                         cudaFuncAttributeMaxDynamicSharedMemorySize, SMEM_GRP);

    // 1) rmsnorm(x)
    rmsnorm_k<<<Td, 256>>>(x, anw, p_xn);
    // 2) q,k,v GEMMs (fp32 — feeds the router-sensitive path)
    dim3 gqkv(Td / 128, Dd / 128);
    sgemm_k<0><<<gqkv, 256>>>(p_xn, wq, p_q, nullptr, Td, Dd, Dd);
    sgemm_k<0><<<gqkv, 256>>>(p_xn, wk, p_k, nullptr, Td, Dd, Dd);
    sgemm_k<0><<<gqkv, 256>>>(p_xn, wv, p_v, nullptr, Td, Dd, Dd);
    // 3) RoPE on q,k
    rope_k<<<(Td * 256) / 256, 256>>>(p_q);
    rope_k<<<(Td * 256) / 256, 256>>>(p_k);
    // 4) causal attention
    attn_k<<<dim3(Bd * Hd, Sd / 64), 256>>>(p_q, p_k, p_v, p_att);
    // 5) O projection + residual
    sgemm_k<1><<<gqkv, 256>>>(p_att, wo, p_h, x, Td, Dd, Dd);
    // 6) rmsnorm(h)
    rmsnorm_k<<<Td, 256>>>(p_h, fnw, p_hn);
    // 7) router + expert grouping
    zero_cnt_k<<<1, 32>>>();
    router_k<<<Td / 8, 256>>>(p_hn, rw);
    tiles_k<<<1, 1>>>();
    assign_k<<<Td / 256, 256>>>();
    // 8) expert GEMM 1: hidden = gelu(hn @ w1[e])   [tf32 tensor cores]
    mma_grp<true, true><<<dim3(MAXTILES, HFd / 128), 256, SMEM_GRP>>>(p_hn, w1, p_hidden, HFd, Dd);
    // 9) expert GEMM 2: y = hidden @ w2[e]          [tf32 tensor cores]
    mma_grp<false, false><<<dim3(MAXTILES, Dd / 128), 256, SMEM_GRP>>>(p_hidden, w2, p_yslot, Dd, HFd);
    // 10) final gather + residual
    final_k<<<(Td * Dd) / 256, 256>>>(out);
}

// round 5
// speedup vs baseline: 1.7107x; 1.0586x over previous
#include <cuda_runtime.h>
#include <cuda_fp16.h>
#include <math.h>
#include <stdint.h>

#define Bd 4
#define Sd 2048
#define Dd 512
#define Hd 8
#define DHd 64
#define Ed 8
#define HFd 2048
#define Td (Bd*Sd)        /* 8192 tokens */
#define NSLOT (2*Td)      /* 16384 expert-slots */
#define MAXTILES 144

// ---------------- scratch (device globals; no allocation allowed) ----------
__device__ float  g_xn[Td*Dd];
__device__ float  g_q[Td*Dd];
__device__ float  g_k[Td*Dd];
__device__ float  g_v[Td*Dd];
__device__ float  g_att[Td*Dd];
__device__ float  g_h[Td*Dd];
__device__ float  g_hn[Td*Dd];
__device__ __half g_hn16[Td*Dd];
__device__ float  g_gate[Td*2];
__device__ int    g_eidx[Td*2];
__device__ int    g_slot_of[Td*2];
__device__ int    g_slot_token[NSLOT];
__device__ int    g_cnt[Ed];
__device__ int    g_off[Ed+1];
__device__ int    g_pos[Ed];
__device__ int    g_tile_e[MAXTILES];
__device__ int    g_tile_row[MAXTILES];
__device__ int    g_tile_end[MAXTILES];
__device__ int    g_ntiles;
__device__ __half g_hidden16[(size_t)NSLOT*HFd]; /* 64 MB */
__device__ float  g_yslot[(size_t)NSLOT*Dd];     /* 32 MB */
__device__ __half g_w1t[(size_t)Ed*HFd*Dd];      /* 16 MB: [e][n][k] fp16 */
__device__ __half g_w2t[(size_t)Ed*Dd*HFd];      /* 16 MB: [e][n][k] fp16 */

// ---------------- rmsnorm (optionally also emits fp16 copy) ----------------
__global__ void rmsnorm_k(const float* __restrict__ in, const float* __restrict__ w,
                          float* __restrict__ out, __half* __restrict__ out16) {
    int t = blockIdx.x;
    int tid = threadIdx.x;
    const float* row = in + (size_t)t * Dd;
    float v0 = row[tid], v1 = row[tid + 256];
    float ss = v0 * v0 + v1 * v1;
    #pragma unroll
    for (int o = 16; o; o >>= 1) ss += __shfl_xor_sync(0xffffffffu, ss, o);
    __shared__ float red[8];
    __shared__ float sc;
    if ((tid & 31) == 0) red[tid >> 5] = ss;
    __syncthreads();
    if (tid == 0) {
        float s = 0.f;
        #pragma unroll
        for (int i = 0; i < 8; i++) s += red[i];
        sc = rsqrtf(s / (float)Dd + 1e-5f);
    }
    __syncthreads();
    float o0 = v0 * sc * w[tid];
    float o1 = v1 * sc * w[tid + 256];
    out[(size_t)t * Dd + tid]       = o0;
    out[(size_t)t * Dd + tid + 256] = o1;
    if (out16) {
        out16[(size_t)t * Dd + tid]       = __float2half(o0);
        out16[(size_t)t * Dd + tid + 256] = __float2half(o1);
    }
}

// ---------------- generic 128x128x8 SGEMM (double-buffered, fp32) ----------
template<int MODE>
__global__ __launch_bounds__(256, 2)
void sgemm_k(const float* __restrict__ A, const float* __restrict__ Bm,
             float* __restrict__ C, const float* __restrict__ Res,
             int M, int N, int K) {
    __shared__ float As[2][8][128];
    __shared__ float Bs[2][8][128];
    int m0 = blockIdx.x * 128, n0 = blockIdx.y * 128;
    int tid = threadIdx.x;
    int tx = tid & 15, ty = tid >> 4;
    int aRow = tid >> 1, aCol = (tid & 1) * 4;
    int bRow = tid >> 5, bCol = (tid & 31) * 4;
    const float* aPtr = A + (size_t)(m0 + aRow) * K + aCol;
    const float* bPtr = Bm + (size_t)bRow * N + n0 + bCol;

    float acc[8][8];
    #pragma unroll
    for (int i = 0; i < 8; i++)
        #pragma unroll
        for (int j = 0; j < 8; j++) acc[i][j] = 0.f;

    int nkt = K >> 3;
    {
        float4 av = *(const float4*)(aPtr);
        As[0][aCol+0][aRow] = av.x; As[0][aCol+1][aRow] = av.y;
        As[0][aCol+2][aRow] = av.z; As[0][aCol+3][aRow] = av.w;
        float4 bv = *(const float4*)(bPtr);
        *(float4*)&Bs[0][bRow][bCol] = bv;
    }
    __syncthreads();
    for (int kt = 0; kt < nkt; kt++) {
        int cur = kt & 1;
        if (kt + 1 < nkt) {
            float4 av = *(const float4*)(aPtr + (size_t)(kt + 1) * 8);
            As[cur^1][aCol+0][aRow] = av.x; As[cur^1][aCol+1][aRow] = av.y;
            As[cur^1][aCol+2][aRow] = av.z; As[cur^1][aCol+3][aRow] = av.w;
            float4 bv = *(const float4*)(bPtr + (size_t)(kt + 1) * 8 * N);
            *(float4*)&Bs[cur^1][bRow][bCol] = bv;
        }
        #pragma unroll
        for (int kk = 0; kk < 8; kk++) {
            float a[8], b[8];
            *(float4*)&a[0] = *(const float4*)&As[cur][kk][ty * 4];
            *(float4*)&a[4] = *(const float4*)&As[cur][kk][64 + ty * 4];
            *(float4*)&b[0] = *(const float4*)&Bs[cur][kk][tx * 4];
            *(float4*)&b[4] = *(const float4*)&Bs[cur][kk][64 + tx * 4];
            #pragma unroll
            for (int i = 0; i < 8; i++)
                #pragma unroll
                for (int j = 0; j < 8; j++) acc[i][j] += a[i] * b[j];
        }
        __syncthreads();
    }
    #pragma unroll
    for (int i = 0; i < 8; i++) {
        int r = (i < 4) ? (ty * 4 + i) : (64 + ty * 4 + (i - 4));
        int grow = m0 + r;
        float* crow = C + (size_t)grow * N + n0;
        float4 lo, hi;
        lo.x = acc[i][0]; lo.y = acc[i][1]; lo.z = acc[i][2]; lo.w = acc[i][3];
        hi.x = acc[i][4]; hi.y = acc[i][5]; hi.z = acc[i][6]; hi.w = acc[i][7];
        if (MODE == 1) {
            const float* rr = Res + (size_t)grow * N + n0;
            float4 r0 = *(const float4*)(rr + tx * 4);
            float4 r1 = *(const float4*)(rr + 64 + tx * 4);
            lo.x += r0.x; lo.y += r0.y; lo.z += r0.z; lo.w += r0.w;
            hi.x += r1.x; hi.y += r1.y; hi.z += r1.z; hi.w += r1.w;
        }
        *(float4*)(crow + tx * 4) = lo;
        *(float4*)(crow + 64 + tx * 4) = hi;
    }
}

// ------- weight transpose+convert: W[e][K][N] fp32 -> Wt[e][N][K] fp16 ------
__global__ void transpose_w16_k(const float* __restrict__ W, __half* __restrict__ Wt,
                                int K, int N) {
    __shared__ float t[32][33];
    int e = blockIdx.z;
    int k0 = blockIdx.x * 32, n0 = blockIdx.y * 32;
    const float* We = W + (size_t)e * K * N;
    __half* Wte = Wt + (size_t)e * K * N;
    int tx = threadIdx.x, ty = threadIdx.y;   // 32 x 8
    #pragma unroll
    for (int i = 0; i < 32; i += 8)
        t[ty + i][tx] = We[(size_t)(k0 + ty + i) * N + n0 + tx];
    __syncthreads();
    #pragma unroll
    for (int i = 0; i < 32; i += 8)
        Wte[(size_t)(n0 + ty + i) * K + k0 + tx] = __float2half(t[tx][ty + i]);
}

// ---------------- fp16 tensor-core grouped expert GEMM ---------------------
__device__ __forceinline__ float gelu_f(float x) {
    return 0.5f * x * (1.0f + erff(x * 0.70710678118654752f));
}
__device__ __forceinline__ void cp16(uint32_t dst, const void* src) {
    asm volatile("cp.async.cg.shared.global [%0], [%1], 16;\n" :: "r"(dst), "l"(src));
}

#define KC 64                 /* k-chunk in halves */
#define HST 72                /* smem row stride in halves (64 + 8 pad) */
#define TILEB (128*HST*2)     /* bytes per smem tile buffer = 18432 */
#define SMEM_H (4*TILEB)      /* A(2 bufs) + B(2 bufs) = 73728 B */

// C[slot, n0..n0+127] = act( A[row(slot), :K] @ Wt[e, n, :K]^T )
// OUT16: write fp16 C, else fp32
template<bool GATHER, bool GELU, bool OUT16>
__global__ __launch_bounds__(256, 2)
void hgemm_grp(const __half* __restrict__ Abase, const __half* __restrict__ Wt,
               void* __restrict__ Cout, int N, int K) {
    extern __shared__ __half sm16[];
    __half* As = sm16;                    // [2][128][HST]
    __half* Bs = sm16 + 2 * 128 * HST;    // [2][128][HST]
    int bx = blockIdx.x;
    if (bx >= g_ntiles) return;
    const int e = g_tile_e[bx], row0 = g_tile_row[bx], rend = g_tile_end[bx];
    const int n0 = blockIdx.y * 128;

    const int tid = threadIdx.x;
    const int lane = tid & 31, wid = tid >> 5;
    const int wm = wid >> 2, wn = wid & 3;      // warp tile (wm*64, wn*32)
    const int lr = lane >> 2, lc = lane & 3;

    // ---- loader setup: row = tid>>1, each thread 4x16B covering half a row ----
    const int aR = tid >> 1;
    const int aSeg = (tid & 1) * 32;            // half-offset base (4 chunks of 8)
    int grow = row0 + aR;
    int gsafe = grow < rend ? grow : rend - 1;
    int arow = GATHER ? g_slot_token[gsafe] : gsafe;
    const __half* aRow = Abase + (size_t)arow * K + aSeg;
    const __half* bRow = Wt + ((size_t)e * N + n0 + aR) * K + aSeg;
    uint32_t aDst = (uint32_t)__cvta_generic_to_shared(As) + (aR * HST + aSeg) * 2;
    uint32_t bDst = (uint32_t)__cvta_generic_to_shared(Bs) + (aR * HST + aSeg) * 2;

    float acc[4][4][4];
    #pragma unroll
    for (int i = 0; i < 4; i++)
        #pragma unroll
        for (int j = 0; j < 4; j++)
            #pragma unroll
            for (int r = 0; r < 4; r++) acc[i][j][r] = 0.f;

    const int nkb = K / KC;
    // prologue: chunk 0 -> buffer 0
    #pragma unroll
    for (int p = 0; p < 4; p++) {
        cp16(aDst + p * 16, aRow + p * 8);
        cp16(bDst + p * 16, bRow + p * 8);
    }
    asm volatile("cp.async.commit_group;\n");

    int buf = 0;
    for (int kb = 0; kb < nkb; kb++) {
        if (kb + 1 < nkb) {
            int ko = (kb + 1) * KC;
            uint32_t ab = aDst + (buf ^ 1) * TILEB;
            uint32_t bb = bDst + (buf ^ 1) * TILEB;
            #pragma unroll
            for (int p = 0; p < 4; p++) {
                cp16(ab + p * 16, aRow + ko + p * 8);
                cp16(bb + p * 16, bRow + ko + p * 8);
            }
            asm volatile("cp.async.commit_group;\n");
            asm volatile("cp.async.wait_group 1;\n");
        } else {
            asm volatile("cp.async.wait_group 0;\n");
        }
        __syncthreads();

        const __half* Ab = As + buf * 128 * HST;
        const __half* Bb = Bs + buf * 128 * HST;
        #pragma unroll
        for (int ks = 0; ks < 4; ks++) {
            const int k0 = ks * 16 + lc * 2;
            uint32_t af[4][4], bf[4][2];
            #pragma unroll
            for (int am = 0; am < 4; am++) {
                const int m = wm * 64 + am * 16 + lr;
                af[am][0] = *(const uint32_t*)&Ab[m * HST + k0];
                af[am][1] = *(const uint32_t*)&Ab[(m + 8) * HST + k0];
                af[am][2] = *(const uint32_t*)&Ab[m * HST + k0 + 8];
                af[am][3] = *(const uint32_t*)&Ab[(m + 8) * HST + k0 + 8];
            }
            #pragma unroll
            for (int an = 0; an < 4; an++) {
                const int n = wn * 32 + an * 8 + lr;
                bf[an][0] = *(const uint32_t*)&Bb[n * HST + k0];
                bf[an][1] = *(const uint32_t*)&Bb[n * HST + k0 + 8];
            }
            #pragma unroll
            for (int am = 0; am < 4; am++)
                #pragma unroll
                for (int an = 0; an < 4; an++)
                    asm volatile(
                        "mma.sync.aligned.m16n8k16.row.col.f32.f16.f16.f32 "
                        "{%0,%1,%2,%3}, {%4,%5,%6,%7}, {%8,%9}, {%0,%1,%2,%3};\n"
                        : "+f"(acc[am][an][0]), "+f"(acc[am][an][1]),
                          "+f"(acc[am][an][2]), "+f"(acc[am][an][3])
                        : "r"(af[am][0]), "r"(af[am][1]), "r"(af[am][2]), "r"(af[am][3]),
                          "r"(bf[an][0]), "r"(bf[an][1]));
        }
        __syncthreads();
        buf ^= 1;
    }

    // ---- epilogue ----
    #pragma unroll
    for (int am = 0; am < 4; am++) {
        int s0 = row0 + wm * 64 + am * 16 + lr;
        #pragma unroll
        for (int an = 0; an < 4; an++) {
            int gc = n0 + wn * 32 + an * 8 + 2 * lc;
            float v0 = acc[am][an][0], v1 = acc[am][an][1];
            float v2 = acc[am][an][2], v3 = acc[am][an][3];
            if (GELU) {
                v0 = gelu_f(v0); v1 = gelu_f(v1);
                v2 = gelu_f(v2); v3 = gelu_f(v3);
            }
            if (OUT16) {
                __half* Ch = (__half*)Cout;
                if (s0 < rend)
                    *(__half2*)&Ch[(size_t)s0 * N + gc] = __floats2half2_rn(v0, v1);
                if (s0 + 8 < rend)
                    *(__half2*)&Ch[(size_t)(s0 + 8) * N + gc] = __floats2half2_rn(v2, v3);
            } else {
                float* Cf = (float*)Cout;
                if (s0 < rend) {
                    float2 t; t.x = v0; t.y = v1;
                    *(float2*)&Cf[(size_t)s0 * N + gc] = t;
                }
                if (s0 + 8 < rend) {
                    float2 t; t.x = v2; t.y = v3;
                    *(float2*)&Cf[(size_t)(s0 + 8) * N + gc] = t;
                }
            }
        }
    }
}

// ---------------- RoPE ------------------------------------------------------
__global__ void rope_k(float* __restrict__ qk) {
    int gid = blockIdx.x * blockDim.x + threadIdx.x;
    if (gid >= Td * 256) return;
    int t = gid >> 8;
    int within = gid & 255;
    int i = within & 31;
    int s = t & (Sd - 1);
    float freq = expf(-(float)(2 * i) * (9.210340371976184f / 64.f));
    float ang = (float)s * freq;
    float sn, cs;
    sincosf(ang, &sn, &cs);
    size_t base = (size_t)t * Dd + within * 2;
    float x1 = qk[base], x2 = qk[base + 1];
    qk[base]     = x1 * cs - x2 * sn;
    qk[base + 1] = x1 * sn + x2 * cs;
}

// ---------------- flash-style causal attention (64x64 tiles, fp32) ---------
__global__ __launch_bounds__(256)
void attn_k(const float* __restrict__ q, const float* __restrict__ k,
            const float* __restrict__ v, float* __restrict__ o) {
    __shared__ float QsT[64][64];
    __shared__ float KPs[64][64];
    __shared__ float Vs[64][64];
    int bh = blockIdx.x;
    int b = bh >> 3, h = bh & 7;
    int qt = blockIdx.y;
    int tid = threadIdx.x, tx = tid & 15, ty = tid >> 4;
    size_t tok0 = (size_t)b * Sd;

    #pragma unroll
    for (int l = 0; l < 4; l++) {
        int fidx = tid + l * 256;
        int r = fidx >> 4, dbase = (fidx & 15) * 4;
        float4 qv = *(const float4*)(q + (tok0 + qt * 64 + r) * Dd + h * DHd + dbase);
        QsT[dbase + 0][r] = qv.x; QsT[dbase + 1][r] = qv.y;
        QsT[dbase + 2][r] = qv.z; QsT[dbase + 3][r] = qv.w;
    }

    float m[4], lsum[4], accO[4][4];
    #pragma unroll
    for (int i = 0; i < 4; i++) {
        m[i] = -1e30f; lsum[i] = 0.f;
        #pragma unroll
        for (int j = 0; j < 4; j++) accO[i][j] = 0.f;
    }

    for (int kt = 0; kt <= qt; kt++) {
        __syncthreads();
        #pragma unroll
        for (int l = 0; l < 4; l++) {
            int fidx = tid + l * 256;
            int r = fidx >> 4, dbase = (fidx & 15) * 4;
            size_t gi = (tok0 + kt * 64 + r) * Dd + h * DHd + dbase;
            float4 kv = *(const float4*)(k + gi);
            KPs[dbase + 0][r] = kv.x; KPs[dbase + 1][r] = kv.y;
            KPs[dbase + 2][r] = kv.z; KPs[dbase + 3][r] = kv.w;
            float4 vv = *(const float4*)(v + gi);
            *(float4*)&Vs[r][dbase] = vv;
        }
        __syncthreads();

        float sc[4][4];
        #pragma unroll
        for (int i = 0; i < 4; i++)
            #pragma unroll
            for (int j = 0; j < 4; j++) sc[i][j] = 0.f;
        #pragma unroll 8
        for (int d = 0; d < 64; d++) {
            float a[4], bb[4];
            *(float4*)a  = *(const float4*)&QsT[d][ty * 4];
            *(float4*)bb = *(const float4*)&KPs[d][tx * 4];
            #pragma unroll
            for (int i = 0; i < 4; i++)
                #pragma unroll
                for (int j = 0; j < 4; j++) sc[i][j] += a[i] * bb[j];
        }
        const float SCALE = 0.125f;
        if (kt == qt) {
            #pragma unroll
            for (int i = 0; i < 4; i++)
                #pragma unroll
                for (int j = 0; j < 4; j++) {
                    int qr = ty * 4 + i, kc = tx * 4 + j;
                    sc[i][j] = (kc <= qr) ? sc[i][j] * SCALE : -1e30f;
                }
        } else {
            #pragma unroll
            for (int i = 0; i < 4; i++)
                #pragma unroll
                for (int j = 0; j < 4; j++) sc[i][j] *= SCALE;
        }

        float p[4][4];
        #pragma unroll
        for (int i = 0; i < 4; i++) {
            float tm = sc[i][0];
            tm = fmaxf(tm, sc[i][1]); tm = fmaxf(tm, sc[i][2]); tm = fmaxf(tm, sc[i][3]);
            #pragma unroll
            for (int ofs = 8; ofs; ofs >>= 1)
                tm = fmaxf(tm, __shfl_xor_sync(0xffffffffu, tm, ofs));
            float mn = fmaxf(m[i], tm);
            float alpha = expf(m[i] - mn);
            float rs = 0.f;
            #pragma unroll
            for (int j = 0; j < 4; j++) { p[i][j] = expf(sc[i][j] - mn); rs += p[i][j]; }
            #pragma unroll
            for (int ofs = 8; ofs; ofs >>= 1)
                rs += __shfl_xor_sync(0xffffffffu, rs, ofs);
            lsum[i] = lsum[i] * alpha + rs;
            m[i] = mn;
            #pragma unroll
            for (int j = 0; j < 4; j++) accO[i][j] *= alpha;
        }

        __syncthreads();
        #pragma unroll
        for (int i = 0; i < 4; i++)
            #pragma unroll
            for (int j = 0; j < 4; j++)
                KPs[tx * 4 + j][ty * 4 + i] = p[i][j];
        __syncthreads();

        #pragma unroll 8
        for (int kk = 0; kk < 64; kk++) {
            float a[4], bb[4];
            *(float4*)a  = *(const float4*)&KPs[kk][ty * 4];
            *(float4*)bb = *(const float4*)&Vs[kk][tx * 4];
            #pragma unroll
            for (int i = 0; i < 4; i++)
                #pragma unroll
                for (int j = 0; j < 4; j++) accO[i][j] += a[i] * bb[j];
        }
    }

    #pragma unroll
    for (int i = 0; i < 4; i++) {
        float inv = 1.0f / lsum[i];
        float4 ov;
        ov.x = accO[i][0] * inv; ov.y = accO[i][1] * inv;
        ov.z = accO[i][2] * inv; ov.w = accO[i][3] * inv;
        *(float4*)(o + (tok0 + qt * 64 + ty * 4 + i) * Dd + h * DHd + tx * 4) = ov;
    }
}

// ---------------- router / scatter -----------------------------------------
__global__ void zero_cnt_k() { if (threadIdx.x < Ed) g_cnt[threadIdx.x] = 0; }

__global__ void router_k(const float* __restrict__ hn, const float* __restrict__ rw) {
    int warp = (blockIdx.x * blockDim.x + threadIdx.x) >> 5;
    int lane = threadIdx.x & 31;
    if (warp >= Td) return;
    const float* row = hn + (size_t)warp * Dd;
    float acc[Ed];
    #pragma unroll
    for (int e = 0; e < Ed; e++) acc[e] = 0.f;
    for (int d = lane; d < Dd; d += 32) {
        float x = row[d];
        #pragma unroll
        for (int e = 0; e < Ed; e++) acc[e] += x * rw[d * Ed + e];
    }
    #pragma unroll
    for (int e = 0; e < Ed; e++)
        #pragma unroll
        for (int o = 16; o; o >>= 1)
            acc[e] += __shfl_xor_sync(0xffffffffu, acc[e], o);
    if (lane == 0) {
        int i0 = 0;
        #pragma unroll
        for (int e = 1; e < Ed; e++) if (acc[e] > acc[i0]) i0 = e;
        int i1 = (i0 == 0) ? 1 : 0;
        #pragma unroll
        for (int e = 0; e < Ed; e++) if (e != i0 && acc[e] > acc[i1]) i1 = e;
        float ex = expf(acc[i1] - acc[i0]);
        float g0 = 1.f / (1.f + ex);
        float g1 = ex / (1.f + ex);
        g_eidx[warp * 2] = i0; g_eidx[warp * 2 + 1] = i1;
        g_gate[warp * 2] = g0; g_gate[warp * 2 + 1] = g1;
        atomicAdd(&g_cnt[i0], 1);
        atomicAdd(&g_cnt[i1], 1);
    }
}

__global__ void tiles_k() {
    int off = 0, nt = 0;
    for (int e = 0; e < Ed; e++) {
        g_off[e] = off; g_pos[e] = 0;
        int c = g_cnt[e];
        for (int r = 0; r < c; r += 128) {
            g_tile_e[nt] = e; g_tile_row[nt] = off + r; g_tile_end[nt] = off + c; nt++;
        }
        off += c;
    }
    g_off[Ed] = off;
    g_ntiles = nt;
}

__global__ void assign_k() {
    int t = blockIdx.x * blockDim.x + threadIdx.x;
    if (t >= Td) return;
    #pragma unroll
    for (int kk = 0; kk < 2; kk++) {
        int e = g_eidx[t * 2 + kk];
        int p = atomicAdd(&g_pos[e], 1);
        int slot = g_off[e] + p;
        g_slot_token[slot] = t;
        g_slot_of[t * 2 + kk] = slot;
    }
}

__global__ void final_k(float* __restrict__ out) {
    int idx = blockIdx.x * blockDim.x + threadIdx.x;
    if (idx >= Td * Dd) return;
    int t = idx >> 9, d = idx & 511;
    float r = g_h[idx];
    r += g_gate[t * 2]     * g_yslot[(size_t)g_slot_of[t * 2]     * Dd + d];
    r += g_gate[t * 2 + 1] * g_yslot[(size_t)g_slot_of[t * 2 + 1] * Dd + d];
    out[idx] = r;
}

// ---------------- launch -----------------------------------------------------
extern "C" void kernel_launch(void* const* d_in, const int* in_sizes, int n_in,
                              void* d_out, int out_size) {
    const float* x   = (const float*)d_in[0];
    const float* anw = (const float*)d_in[1];
    const float* wq  = (const float*)d_in[2];
    const float* wk  = (const float*)d_in[3];
    const float* wv  = (const float*)d_in[4];
    const float* wo  = (const float*)d_in[5];
    const float* fnw = (const float*)d_in[6];
    const float* rw  = (const float*)d_in[7];
    const float* w1  = (const float*)d_in[8];
    const float* w2  = (const float*)d_in[9];
    float* out = (float*)d_out;

    float *p_xn, *p_q, *p_k, *p_v, *p_att, *p_h, *p_hn, *p_yslot;
    __half *p_hn16, *p_hidden16, *p_w1t, *p_w2t;
    cudaGetSymbolAddress((void**)&p_xn, g_xn);
    cudaGetSymbolAddress((void**)&p_q, g_q);
    cudaGetSymbolAddress((void**)&p_k, g_k);
    cudaGetSymbolAddress((void**)&p_v, g_v);
    cudaGetSymbolAddress((void**)&p_att, g_att);
    cudaGetSymbolAddress((void**)&p_h, g_h);
    cudaGetSymbolAddress((void**)&p_hn, g_hn);
    cudaGetSymbolAddress((void**)&p_hn16, g_hn16);
    cudaGetSymbolAddress((void**)&p_hidden16, g_hidden16);
    cudaGetSymbolAddress((void**)&p_yslot, g_yslot);
    cudaGetSymbolAddress((void**)&p_w1t, g_w1t);
    cudaGetSymbolAddress((void**)&p_w2t, g_w2t);

    cudaFuncSetAttribute(hgemm_grp<true, true, true>,
                         cudaFuncAttributeMaxDynamicSharedMemorySize, SMEM_H);
    cudaFuncSetAttribute(hgemm_grp<false, false, false>,
                         cudaFuncAttributeMaxDynamicSharedMemorySize, SMEM_H);

    // 0) transpose+convert expert weights to fp16 K-major
    transpose_w16_k<<<dim3(Dd / 32, HFd / 32, Ed), dim3(32, 8)>>>(w1, p_w1t, Dd, HFd);
    transpose_w16_k<<<dim3(HFd / 32, Dd / 32, Ed), dim3(32, 8)>>>(w2, p_w2t, HFd, Dd);
    // 1) rmsnorm(x)
    rmsnorm_k<<<Td, 256>>>(x, anw, p_xn, nullptr);
    // 2) q,k,v GEMMs (fp32 — feeds the router-sensitive path)
    dim3 gqkv(Td / 128, Dd / 128);
    sgemm_k<0><<<gqkv, 256>>>(p_xn, wq, p_q, nullptr, Td, Dd, Dd);
    sgemm_k<0><<<gqkv, 256>>>(p_xn, wk, p_k, nullptr, Td, Dd, Dd);
    sgemm_k<0><<<gqkv, 256>>>(p_xn, wv, p_v, nullptr, Td, Dd, Dd);
    // 3) RoPE on q,k
    rope_k<<<(Td * 256) / 256, 256>>>(p_q);
    rope_k<<<(Td * 256) / 256, 256>>>(p_k);
    // 4) causal attention
    attn_k<<<dim3(Bd * Hd, Sd / 64), 256>>>(p_q, p_k, p_v, p_att);
    // 5) O projection + residual
    sgemm_k<1><<<gqkv, 256>>>(p_att, wo, p_h, x, Td, Dd, Dd);
    // 6) rmsnorm(h) + fp16 copy for MoE
    rmsnorm_k<<<Td, 256>>>(p_h, fnw, p_hn, p_hn16);
    // 7) router + expert grouping (fp32 logits — bit-stable routing)
    zero_cnt_k<<<1, 32>>>();
    router_k<<<Td / 8, 256>>>(p_hn, rw);
    tiles_k<<<1, 1>>>();
    assign_k<<<Td / 256, 256>>>();
    // 8) expert GEMM 1: hidden16 = gelu(hn16 @ w1[e])   [fp16 mma.sync]
    hgemm_grp<true, true, true><<<dim3(MAXTILES, HFd / 128), 256, SMEM_H>>>(
        p_hn16, p_w1t, p_hidden16, HFd, Dd);
    // 9) expert GEMM 2: yslot = hidden16 @ w2[e]        [fp16 mma.sync]
    hgemm_grp<false, false, false><<<dim3(MAXTILES, Dd / 128), 256, SMEM_H>>>(
        p_hidden16, p_w2t, p_yslot, Dd, HFd);
    // 10) final gather + residual
    final_k<<<(Td * Dd) / 256, 256>>>(out);
}

// round 7
// speedup vs baseline: 1.7224x; 1.0068x over previous
#include <cuda_runtime.h>
#include <cuda_fp16.h>
#include <math.h>
#include <stdint.h>

#define Bd 4
#define Sd 2048
#define Dd 512
#define Hd 8
#define DHd 64
#define Ed 8
#define HFd 2048
#define Td (Bd*Sd)        /* 8192 tokens */
#define NSLOT (2*Td)      /* 16384 expert-slots */
#define MAXTILES 144

// ---------------- scratch (device globals; no allocation allowed) ----------
__device__ float  g_xn[Td*Dd];
__device__ float  g_q[Td*Dd];
__device__ float  g_k[Td*Dd];
__device__ float  g_v[Td*Dd];
__device__ float  g_att[Td*Dd];
__device__ float  g_h[Td*Dd];
__device__ float  g_hn[Td*Dd];
__device__ __half g_hn16[Td*Dd];
__device__ float  g_gate[Td*2];
__device__ int    g_eidx[Td*2];
__device__ int    g_slot_of[Td*2];
__device__ int    g_slot_token[NSLOT];
__device__ int    g_cnt[Ed];
__device__ int    g_off[Ed+1];
__device__ int    g_pos[Ed];
__device__ int    g_tile_e[MAXTILES];
__device__ int    g_tile_row[MAXTILES];
__device__ int    g_tile_end[MAXTILES];
__device__ int    g_ntiles;
__device__ __half g_hidden16[(size_t)NSLOT*HFd]; /* 64 MB */
__device__ float  g_yslot[(size_t)NSLOT*Dd];     /* 32 MB */
__device__ __half g_w1t[(size_t)Ed*HFd*Dd];      /* 16 MB: [e][n][k] fp16 */
__device__ __half g_w2t[(size_t)Ed*Dd*HFd];      /* 16 MB: [e][n][k] fp16 */

// ---------------- fast exp on the FMA pipe (no MUFU) ------------------------
// rel err ~2e-7 on [-80, 0]; clamps below -80 (returns ~0)
__device__ __forceinline__ float fexp(float x) {
    x = fmaxf(x, -80.0f);
    float i = rintf(x * 1.44269504088896341f);
    float r = fmaf(i, -0.693359375f, x);          // ln2 hi
    r = fmaf(i, 2.12194440e-4f, r);               // ln2 lo
    float z = r * r;
    float p = 1.9875691500e-4f;
    p = fmaf(p, r, 1.3981999507e-3f);
    p = fmaf(p, r, 8.3334519073e-3f);
    p = fmaf(p, r, 4.1665795894e-2f);
    p = fmaf(p, r, 1.6666665459e-1f);
    p = fmaf(p, r, 5.0000001201e-1f);
    float y = fmaf(z, p, r) + 1.0f;
    int j = __float2int_rn(i);
    float sc2 = __int_as_float((j + 127) << 23);
    return y * sc2;
}

// ---------------- rmsnorm (optionally also emits fp16 copy) ----------------
__global__ void rmsnorm_k(const float* __restrict__ in, const float* __restrict__ w,
                          float* __restrict__ out, __half* __restrict__ out16) {
    int t = blockIdx.x;
    int tid = threadIdx.x;
    const float* row = in + (size_t)t * Dd;
    float v0 = row[tid], v1 = row[tid + 256];
    float ss = v0 * v0 + v1 * v1;
    #pragma unroll
    for (int o = 16; o; o >>= 1) ss += __shfl_xor_sync(0xffffffffu, ss, o);
    __shared__ float red[8];
    __shared__ float sc;
    if ((tid & 31) == 0) red[tid >> 5] = ss;
    __syncthreads();
    if (tid == 0) {
        float s = 0.f;
        #pragma unroll
        for (int i = 0; i < 8; i++) s += red[i];
        sc = rsqrtf(s / (float)Dd + 1e-5f);
    }
    __syncthreads();
    float o0 = v0 * sc * w[tid];
    float o1 = v1 * sc * w[tid + 256];
    out[(size_t)t * Dd + tid]       = o0;
    out[(size_t)t * Dd + tid + 256] = o1;
    if (out16) {
        out16[(size_t)t * Dd + tid]       = __float2half(o0);
        out16[(size_t)t * Dd + tid + 256] = __float2half(o1);
    }
}

// ---------------- generic 128x128x8 SGEMM (double-buffered, fp32) ----------
template<int MODE>
__global__ __launch_bounds__(256, 2)
void sgemm_k(const float* __restrict__ A, const float* __restrict__ Bm,
             float* __restrict__ C, const float* __restrict__ Res,
             int M, int N, int K) {
    __shared__ float As[2][8][128];
    __shared__ float Bs[2][8][128];
    int m0 = blockIdx.x * 128, n0 = blockIdx.y * 128;
    int tid = threadIdx.x;
    int tx = tid & 15, ty = tid >> 4;
    int aRow = tid >> 1, aCol = (tid & 1) * 4;
    int bRow = tid >> 5, bCol = (tid & 31) * 4;
    const float* aPtr = A + (size_t)(m0 + aRow) * K + aCol;
    const float* bPtr = Bm + (size_t)bRow * N + n0 + bCol;

    float acc[8][8];
    #pragma unroll
    for (int i = 0; i < 8; i++)
        #pragma unroll
        for (int j = 0; j < 8; j++) acc[i][j] = 0.f;

    int nkt = K >> 3;
    {
        float4 av = *(const float4*)(aPtr);
        As[0][aCol+0][aRow] = av.x; As[0][aCol+1][aRow] = av.y;
        As[0][aCol+2][aRow] = av.z; As[0][aCol+3][aRow] = av.w;
        float4 bv = *(const float4*)(bPtr);
        *(float4*)&Bs[0][bRow][bCol] = bv;
    }
    __syncthreads();
    for (int kt = 0; kt < nkt; kt++) {
        int cur = kt & 1;
        if (kt + 1 < nkt) {
            float4 av = *(const float4*)(aPtr + (size_t)(kt + 1) * 8);
            As[cur^1][aCol+0][aRow] = av.x; As[cur^1][aCol+1][aRow] = av.y;
            As[cur^1][aCol+2][aRow] = av.z; As[cur^1][aCol+3][aRow] = av.w;
            float4 bv = *(const float4*)(bPtr + (size_t)(kt + 1) * 8 * N);
            *(float4*)&Bs[cur^1][bRow][bCol] = bv;
        }
        #pragma unroll
        for (int kk = 0; kk < 8; kk++) {
            float a[8], b[8];
            *(float4*)&a[0] = *(const float4*)&As[cur][kk][ty * 4];
            *(float4*)&a[4] = *(const float4*)&As[cur][kk][64 + ty * 4];
            *(float4*)&b[0] = *(const float4*)&Bs[cur][kk][tx * 4];
            *(float4*)&b[4] = *(const float4*)&Bs[cur][kk][64 + tx * 4];
            #pragma unroll
            for (int i = 0; i < 8; i++)
                #pragma unroll
                for (int j = 0; j < 8; j++) acc[i][j] += a[i] * b[j];
        }
        __syncthreads();
    }
    #pragma unroll
    for (int i = 0; i < 8; i++) {
        int r = (i < 4) ? (ty * 4 + i) : (64 + ty * 4 + (i - 4));
        int grow = m0 + r;
        float* crow = C + (size_t)grow * N + n0;
        float4 lo, hi;
        lo.x = acc[i][0]; lo.y = acc[i][1]; lo.z = acc[i][2]; lo.w = acc[i][3];
        hi.x = acc[i][4]; hi.y = acc[i][5]; hi.z = acc[i][6]; hi.w = acc[i][7];
        if (MODE == 1) {
            const float* rr = Res + (size_t)grow * N + n0;
            float4 r0 = *(const float4*)(rr + tx * 4);
            float4 r1 = *(const float4*)(rr + 64 + tx * 4);
            lo.x += r0.x; lo.y += r0.y; lo.z += r0.z; lo.w += r0.w;
            hi.x += r1.x; hi.y += r1.y; hi.z += r1.z; hi.w += r1.w;
        }
        *(float4*)(crow + tx * 4) = lo;
        *(float4*)(crow + 64 + tx * 4) = hi;
    }
}

// ------- weight transpose+convert: W[e][K][N] fp32 -> Wt[e][N][K] fp16 ------
__global__ void transpose_w16_k(const float* __restrict__ W, __half* __restrict__ Wt,
                                int K, int N) {
    __shared__ float t[32][33];
    int e = blockIdx.z;
    int k0 = blockIdx.x * 32, n0 = blockIdx.y * 32;
    const float* We = W + (size_t)e * K * N;
    __half* Wte = Wt + (size_t)e * K * N;
    int tx = threadIdx.x, ty = threadIdx.y;   // 32 x 8
    #pragma unroll
    for (int i = 0; i < 32; i += 8)
        t[ty + i][tx] = We[(size_t)(k0 + ty + i) * N + n0 + tx];
    __syncthreads();
    #pragma unroll
    for (int i = 0; i < 32; i += 8)
        Wte[(size_t)(n0 + ty + i) * K + k0 + tx] = __float2half(t[tx][ty + i]);
}

// ---------------- fp16 tensor-core grouped expert GEMM ---------------------
__device__ __forceinline__ float gelu_f(float x) {
    return 0.5f * x * (1.0f + erff(x * 0.70710678118654752f));
}
__device__ __forceinline__ void cp16(uint32_t dst, const void* src) {
    asm volatile("cp.async.cg.shared.global [%0], [%1], 16;\n" :: "r"(dst), "l"(src));
}

#define KC 64                 /* k-chunk in halves */
#define HST 72                /* smem row stride in halves (64 + 8 pad) */
#define TILEB (128*HST*2)     /* bytes per smem tile buffer = 18432 */
#define SMEM_H (4*TILEB)      /* A(2 bufs) + B(2 bufs) = 73728 B */

// C[slot, n0..n0+127] = act( A[row(slot), :K] @ Wt[e, n, :K]^T )
template<bool GATHER, bool GELU, bool OUT16>
__global__ __launch_bounds__(256, 2)
void hgemm_grp(const __half* __restrict__ Abase, const __half* __restrict__ Wt,
               void* __restrict__ Cout, int N, int K) {
    extern __shared__ __half sm16[];
    __half* As = sm16;                    // [2][128][HST]
    __half* Bs = sm16 + 2 * 128 * HST;    // [2][128][HST]
    int bx = blockIdx.x;
    if (bx >= g_ntiles) return;
    const int e = g_tile_e[bx], row0 = g_tile_row[bx], rend = g_tile_end[bx];
    const int n0 = blockIdx.y * 128;

    const int tid = threadIdx.x;
    const int lane = tid & 31, wid = tid >> 5;
    const int wm = wid >> 2, wn = wid & 3;      // warp tile (wm*64, wn*32)
    const int lr = lane >> 2, lc = lane & 3;

    const int aR = tid >> 1;
    const int aSeg = (tid & 1) * 32;
    int grow = row0 + aR;
    int gsafe = grow < rend ? grow : rend - 1;
    int arow = GATHER ? g_slot_token[gsafe] : gsafe;
    const __half* aRow = Abase + (size_t)arow * K + aSeg;
    const __half* bRow = Wt + ((size_t)e * N + n0 + aR) * K + aSeg;
    uint32_t aDst = (uint32_t)__cvta_generic_to_shared(As) + (aR * HST + aSeg) * 2;
    uint32_t bDst = (uint32_t)__cvta_generic_to_shared(Bs) + (aR * HST + aSeg) * 2;

    float acc[4][4][4];
    #pragma unroll
    for (int i = 0; i < 4; i++)
        #pragma unroll
        for (int j = 0; j < 4; j++)
            #pragma unroll
            for (int r = 0; r < 4; r++) acc[i][j][r] = 0.f;

    const int nkb = K / KC;
    #pragma unroll
    for (int p = 0; p < 4; p++) {
        cp16(aDst + p * 16, aRow + p * 8);
        cp16(bDst + p * 16, bRow + p * 8);
    }
    asm volatile("cp.async.commit_group;\n");

    int buf = 0;
    for (int kb = 0; kb < nkb; kb++) {
        if (kb + 1 < nkb) {
            int ko = (kb + 1) * KC;
            uint32_t ab = aDst + (buf ^ 1) * TILEB;
            uint32_t bb = bDst + (buf ^ 1) * TILEB;
            #pragma unroll
            for (int p = 0; p < 4; p++) {
                cp16(ab + p * 16, aRow + ko + p * 8);
                cp16(bb + p * 16, bRow + ko + p * 8);
            }
            asm volatile("cp.async.commit_group;\n");
            asm volatile("cp.async.wait_group 1;\n");
        } else {
            asm volatile("cp.async.wait_group 0;\n");
        }
        __syncthreads();

        const __half* Ab = As + buf * 128 * HST;
        const __half* Bb = Bs + buf * 128 * HST;
        #pragma unroll
        for (int ks = 0; ks < 4; ks++) {
            const int k0 = ks * 16 + lc * 2;
            uint32_t af[4][4], bf[4][2];
            #pragma unroll
            for (int am = 0; am < 4; am++) {
                const int m = wm * 64 + am * 16 + lr;
                af[am][0] = *(const uint32_t*)&Ab[m * HST + k0];
                af[am][1] = *(const uint32_t*)&Ab[(m + 8) * HST + k0];
                af[am][2] = *(const uint32_t*)&Ab[m * HST + k0 + 8];
                af[am][3] = *(const uint32_t*)&Ab[(m + 8) * HST + k0 + 8];
            }
            #pragma unroll
            for (int an = 0; an < 4; an++) {
                const int n = wn * 32 + an * 8 + lr;
                bf[an][0] = *(const uint32_t*)&Bb[n * HST + k0];
                bf[an][1] = *(const uint32_t*)&Bb[n * HST + k0 + 8];
            }
            #pragma unroll
            for (int am = 0; am < 4; am++)
                #pragma unroll
                for (int an = 0; an < 4; an++)
                    asm volatile(
                        "mma.sync.aligned.m16n8k16.row.col.f32.f16.f16.f32 "
                        "{%0,%1,%2,%3}, {%4,%5,%6,%7}, {%8,%9}, {%0,%1,%2,%3};\n"
                        : "+f"(acc[am][an][0]), "+f"(acc[am][an][1]),
                          "+f"(acc[am][an][2]), "+f"(acc[am][an][3])
                        : "r"(af[am][0]), "r"(af[am][1]), "r"(af[am][2]), "r"(af[am][3]),
                          "r"(bf[an][0]), "r"(bf[an][1]));
        }
        __syncthreads();
        buf ^= 1;
    }

    #pragma unroll
    for (int am = 0; am < 4; am++) {
        int s0 = row0 + wm * 64 + am * 16 + lr;
        #pragma unroll
        for (int an = 0; an < 4; an++) {
            int gc = n0 + wn * 32 + an * 8 + 2 * lc;
            float v0 = acc[am][an][0], v1 = acc[am][an][1];
            float v2 = acc[am][an][2], v3 = acc[am][an][3];
            if (GELU) {
                v0 = gelu_f(v0); v1 = gelu_f(v1);
                v2 = gelu_f(v2); v3 = gelu_f(v3);
            }
            if (OUT16) {
                __half* Ch = (__half*)Cout;
                if (s0 < rend)
                    *(__half2*)&Ch[(size_t)s0 * N + gc] = __floats2half2_rn(v0, v1);
                if (s0 + 8 < rend)
                    *(__half2*)&Ch[(size_t)(s0 + 8) * N + gc] = __floats2half2_rn(v2, v3);
            } else {
                float* Cf = (float*)Cout;
                if (s0 < rend) {
                    float2 t; t.x = v0; t.y = v1;
                    *(float2*)&Cf[(size_t)s0 * N + gc] = t;
                }
                if (s0 + 8 < rend) {
                    float2 t; t.x = v2; t.y = v3;
                    *(float2*)&Cf[(size_t)(s0 + 8) * N + gc] = t;
                }
            }
        }
    }
}

// ---------------- RoPE ------------------------------------------------------
__global__ void rope_k(float* __restrict__ qk) {
    int gid = blockIdx.x * blockDim.x + threadIdx.x;
    if (gid >= Td * 256) return;
    int t = gid >> 8;
    int within = gid & 255;
    int i = within & 31;
    int s = t & (Sd - 1);
    float freq = expf(-(float)(2 * i) * (9.210340371976184f / 64.f));
    float ang = (float)s * freq;
    float sn, cs;
    sincosf(ang, &sn, &cs);
    size_t base = (size_t)t * Dd + within * 2;
    float x1 = qk[base], x2 = qk[base + 1];
    qk[base]     = x1 * cs - x2 * sn;
    qk[base + 1] = x1 * sn + x2 * cs;
}

// ---------------- flash-style causal attention (64x64 tiles, fp32) ---------
// Q pre-scaled by 1/sqrt(dh) at load; softmax exp on the FMA pipe.
__global__ __launch_bounds__(256)
void attn_k(const float* __restrict__ q, const float* __restrict__ k,
            const float* __restrict__ v, float* __restrict__ o) {
    __shared__ float QsT[64][64];
    __shared__ float KPs[64][64];
    __shared__ float Vs[64][64];
    int bh = blockIdx.x;
    int b = bh >> 3, h = bh & 7;
    int qt = blockIdx.y;
    int tid = threadIdx.x, tx = tid & 15, ty = tid >> 4;
    size_t tok0 = (size_t)b * Sd;

    #pragma unroll
    for (int l = 0; l < 4; l++) {
        int fidx = tid + l * 256;
        int r = fidx >> 4, dbase = (fidx & 15) * 4;
        float4 qv = *(const float4*)(q + (tok0 + qt * 64 + r) * Dd + h * DHd + dbase);
        QsT[dbase + 0][r] = qv.x * 0.125f; QsT[dbase + 1][r] = qv.y * 0.125f;
        QsT[dbase + 2][r] = qv.z * 0.125f; QsT[dbase + 3][r] = qv.w * 0.125f;
    }

    float m[4], lsum[4], accO[4][4];
    #pragma unroll
    for (int i = 0; i < 4; i++) {
        m[i] = -1e30f; lsum[i] = 0.f;
        #pragma unroll
        for (int j = 0; j < 4; j++) accO[i][j] = 0.f;
    }

    for (int kt = 0; kt <= qt; kt++) {
        __syncthreads();
        #pragma unroll
        for (int l = 0; l < 4; l++) {
            int fidx = tid + l * 256;
            int r = fidx >> 4, dbase = (fidx & 15) * 4;
            size_t gi = (tok0 + kt * 64 + r) * Dd + h * DHd + dbase;
            float4 kv = *(const float4*)(k + gi);
            KPs[dbase + 0][r] = kv.x; KPs[dbase + 1][r] = kv.y;
            KPs[dbase + 2][r] = kv.z; KPs[dbase + 3][r] = kv.w;
            float4 vv = *(const float4*)(v + gi);
            *(float4*)&Vs[r][dbase] = vv;
        }
        __syncthreads();

        float sc[4][4];
        #pragma unroll
        for (int i = 0; i < 4; i++)
            #pragma unroll
            for (int j = 0; j < 4; j++) sc[i][j] = 0.f;
        #pragma unroll 8
        for (int d = 0; d < 64; d++) {
            float a[4], bb[4];
            *(float4*)a  = *(const float4*)&QsT[d][ty * 4];
            *(float4*)bb = *(const float4*)&KPs[d][tx * 4];
            #pragma unroll
            for (int i = 0; i < 4; i++)
                #pragma unroll
                for (int j = 0; j < 4; j++) sc[i][j] += a[i] * bb[j];
        }
        if (kt == qt) {
            #pragma unroll
            for (int i = 0; i < 4; i++)
                #pragma unroll
                for (int j = 0; j < 4; j++) {
                    int qr = ty * 4 + i, kc = tx * 4 + j;
                    if (kc > qr) sc[i][j] = -1e30f;
                }
        }

        float p[4][4];
        #pragma unroll
        for (int i = 0; i < 4; i++) {
            float tm = sc[i][0];
            tm = fmaxf(tm, sc[i][1]); tm = fmaxf(tm, sc[i][2]); tm = fmaxf(tm, sc[i][3]);
            #pragma unroll
            for (int ofs = 8; ofs; ofs >>= 1)
                tm = fmaxf(tm, __shfl_xor_sync(0xffffffffu, tm, ofs));
            float mn = fmaxf(m[i], tm);
            float alpha = fexp(m[i] - mn);
            float rs = 0.f;
            #pragma unroll
            for (int j = 0; j < 4; j++) { p[i][j] = fexp(sc[i][j] - mn); rs += p[i][j]; }
            #pragma unroll
            for (int ofs = 8; ofs; ofs >>= 1)
                rs += __shfl_xor_sync(0xffffffffu, rs, ofs);
            lsum[i] = lsum[i] * alpha + rs;
            m[i] = mn;
            #pragma unroll
            for (int j = 0; j < 4; j++) accO[i][j] *= alpha;
        }

        __syncthreads();
        #pragma unroll
        for (int i = 0; i < 4; i++)
            #pragma unroll
            for (int j = 0; j < 4; j++)
                KPs[tx * 4 + j][ty * 4 + i] = p[i][j];
        __syncthreads();

        #pragma unroll 8
        for (int kk = 0; kk < 64; kk++) {
            float a[4], bb[4];
            *(float4*)a  = *(const float4*)&KPs[kk][ty * 4];
            *(float4*)bb = *(const float4*)&Vs[kk][tx * 4];
            #pragma unroll
            for (int i = 0; i < 4; i++)
                #pragma unroll
                for (int j = 0; j < 4; j++) accO[i][j] += a[i] * bb[j];
        }
    }

    #pragma unroll
    for (int i = 0; i < 4; i++) {
        float inv = 1.0f / lsum[i];
        float4 ov;
        ov.x = accO[i][0] * inv; ov.y = accO[i][1] * inv;
        ov.z = accO[i][2] * inv; ov.w = accO[i][3] * inv;
        *(float4*)(o + (tok0 + qt * 64 + ty * 4 + i) * Dd + h * DHd + tx * 4) = ov;
    }
}

// ---------------- router / scatter -----------------------------------------
__global__ void zero_cnt_k() { if (threadIdx.x < Ed) g_cnt[threadIdx.x] = 0; }

__global__ void router_k(const float* __restrict__ hn, const float* __restrict__ rw) {
    int warp = (blockIdx.x * blockDim.x + threadIdx.x) >> 5;
    int lane = threadIdx.x & 31;
    if (warp >= Td) return;
    const float* row = hn + (size_t)warp * Dd;
    float acc[Ed];
    #pragma unroll
    for (int e = 0; e < Ed; e++) acc[e] = 0.f;
    for (int d = lane; d < Dd; d += 32) {
        float x = row[d];
        #pragma unroll
        for (int e = 0; e < Ed; e++) acc[e] += x * rw[d * Ed + e];
    }
    #pragma unroll
    for (int e = 0; e < Ed; e++)
        #pragma unroll
        for (int o = 16; o; o >>= 1)
            acc[e] += __shfl_xor_sync(0xffffffffu, acc[e], o);
    if (lane == 0) {
        int i0 = 0;
        #pragma unroll
        for (int e = 1; e < Ed; e++) if (acc[e] > acc[i0]) i0 = e;
        int i1 = (i0 == 0) ? 1 : 0;
        #pragma unroll
        for (int e = 0; e < Ed; e++) if (e != i0 && acc[e] > acc[i1]) i1 = e;
        float ex = expf(acc[i1] - acc[i0]);
        float g0 = 1.f / (1.f + ex);
        float g1 = ex / (1.f + ex);
        g_eidx[warp * 2] = i0; g_eidx[warp * 2 + 1] = i1;
        g_gate[warp * 2] = g0; g_gate[warp * 2 + 1] = g1;
        atomicAdd(&g_cnt[i0], 1);
        atomicAdd(&g_cnt[i1], 1);
    }
}

__global__ void tiles_k() {
    int off = 0, nt = 0;
    for (int e = 0; e < Ed; e++) {
        g_off[e] = off; g_pos[e] = 0;
        int c = g_cnt[e];
        for (int r = 0; r < c; r += 128) {
            g_tile_e[nt] = e; g_tile_row[nt] = off + r; g_tile_end[nt] = off + c; nt++;
        }
        off += c;
    }
    g_off[Ed] = off;
    g_ntiles = nt;
}

__global__ void assign_k() {
    int t = blockIdx.x * blockDim.x + threadIdx.x;
    if (t >= Td) return;
    #pragma unroll
    for (int kk = 0; kk < 2; kk++) {
        int e = g_eidx[t * 2 + kk];
        int p = atomicAdd(&g_pos[e], 1);
        int slot = g_off[e] + p;
        g_slot_token[slot] = t;
        g_slot_of[t * 2 + kk] = slot;
    }
}

__global__ void final_k(float* __restrict__ out) {
    int idx = blockIdx.x * blockDim.x + threadIdx.x;
    if (idx >= Td * Dd) return;
    int t = idx >> 9, d = idx & 511;
    float r = g_h[idx];
    r += g_gate[t * 2]     * g_yslot[(size_t)g_slot_of[t * 2]     * Dd + d];
    r += g_gate[t * 2 + 1] * g_yslot[(size_t)g_slot_of[t * 2 + 1] * Dd + d];
    out[idx] = r;
}

// ---------------- launch -----------------------------------------------------
extern "C" void kernel_launch(void* const* d_in, const int* in_sizes, int n_in,
                              void* d_out, int out_size) {
    const float* x   = (const float*)d_in[0];
    const float* anw = (const float*)d_in[1];
    const float* wq  = (const float*)d_in[2];
    const float* wk  = (const float*)d_in[3];
    const float* wv  = (const float*)d_in[4];
    const float* wo  = (const float*)d_in[5];
    const float* fnw = (const float*)d_in[6];
    const float* rw  = (const float*)d_in[7];
    const float* w1  = (const float*)d_in[8];
    const float* w2  = (const float*)d_in[9];
    float* out = (float*)d_out;

    float *p_xn, *p_q, *p_k, *p_v, *p_att, *p_h, *p_hn, *p_yslot;
    __half *p_hn16, *p_hidden16, *p_w1t, *p_w2t;
    cudaGetSymbolAddress((void**)&p_xn, g_xn);
    cudaGetSymbolAddress((void**)&p_q, g_q);
    cudaGetSymbolAddress((void**)&p_k, g_k);
    cudaGetSymbolAddress((void**)&p_v, g_v);
    cudaGetSymbolAddress((void**)&p_att, g_att);
    cudaGetSymbolAddress((void**)&p_h, g_h);
    cudaGetSymbolAddress((void**)&p_hn, g_hn);
    cudaGetSymbolAddress((void**)&p_hn16, g_hn16);
    cudaGetSymbolAddress((void**)&p_hidden16, g_hidden16);
    cudaGetSymbolAddress((void**)&p_yslot, g_yslot);
    cudaGetSymbolAddress((void**)&p_w1t, g_w1t);
    cudaGetSymbolAddress((void**)&p_w2t, g_w2t);

    cudaFuncSetAttribute(hgemm_grp<true, true, true>,
                         cudaFuncAttributeMaxDynamicSharedMemorySize, SMEM_H);
    cudaFuncSetAttribute(hgemm_grp<false, false, false>,
                         cudaFuncAttributeMaxDynamicSharedMemorySize, SMEM_H);

    // 0) transpose+convert expert weights to fp16 K-major
    transpose_w16_k<<<dim3(Dd / 32, HFd / 32, Ed), dim3(32, 8)>>>(w1, p_w1t, Dd, HFd);
    transpose_w16_k<<<dim3(HFd / 32, Dd / 32, Ed), dim3(32, 8)>>>(w2, p_w2t, HFd, Dd);
    // 1) rmsnorm(x)
    rmsnorm_k<<<Td, 256>>>(x, anw, p_xn, nullptr);
    // 2) q,k,v GEMMs (fp32 — feeds the router-sensitive path)
    dim3 gqkv(Td / 128, Dd / 128);
    sgemm_k<0><<<gqkv, 256>>>(p_xn, wq, p_q, nullptr, Td, Dd, Dd);
    sgemm_k<0><<<gqkv, 256>>>(p_xn, wk, p_k, nullptr, Td, Dd, Dd);
    sgemm_k<0><<<gqkv, 256>>>(p_xn, wv, p_v, nullptr, Td, Dd, Dd);
    // 3) RoPE on q,k
    rope_k<<<(Td * 256) / 256, 256>>>(p_q);
    rope_k<<<(Td * 256) / 256, 256>>>(p_k);
    // 4) causal attention (FMA-pipe softmax)
    attn_k<<<dim3(Bd * Hd, Sd / 64), 256>>>(p_q, p_k, p_v, p_att);
    // 5) O projection + residual
    sgemm_k<1><<<gqkv, 256>>>(p_att, wo, p_h, x, Td, Dd, Dd);
    // 6) rmsnorm(h) + fp16 copy for MoE
    rmsnorm_k<<<Td, 256>>>(p_h, fnw, p_hn, p_hn16);
    // 7) router + expert grouping (fp32 logits — bit-stable routing)
    zero_cnt_k<<<1, 32>>>();
    router_k<<<Td / 8, 256>>>(p_hn, rw);
    tiles_k<<<1, 1>>>();
    assign_k<<<Td / 256, 256>>>();
    // 8) expert GEMM 1: hidden16 = gelu(hn16 @ w1[e])   [fp16 mma.sync]
    hgemm_grp<true, true, true><<<dim3(MAXTILES, HFd / 128), 256, SMEM_H>>>(
        p_hn16, p_w1t, p_hidden16, HFd, Dd);
    // 9) expert GEMM 2: yslot = hidden16 @ w2[e]        [fp16 mma.sync]
    hgemm_grp<false, false, false><<<dim3(MAXTILES, Dd / 128), 256, SMEM_H>>>(
        p_hidden16, p_w2t, p_yslot, Dd, HFd);
    // 10) final gather + residual
    final_k<<<(Td * Dd) / 256, 256>>>(out);
}

// round 9
// speedup vs baseline: 1.8919x; 1.0985x over previous
#include <cuda_runtime.h>
#include <cuda_fp16.h>
#include <math.h>
#include <stdint.h>

#define Bd 4
#define Sd 2048
#define Dd 512
#define Hd 8
#define DHd 64
#define Ed 8
#define HFd 2048
#define Td (Bd*Sd)        /* 8192 tokens */
#define NSLOT (2*Td)      /* 16384 expert-slots */
#define MAXTILES 144

// ---------------- scratch (device globals; no allocation allowed) ----------
__device__ float  g_xn[Td*Dd];
__device__ float  g_q[Td*Dd];
__device__ float  g_k[Td*Dd];
__device__ float  g_v[Td*Dd];
__device__ float  g_att[Td*Dd];
__device__ float  g_h[Td*Dd];
__device__ float  g_hn[Td*Dd];
__device__ __half g_hn16[Td*Dd];
__device__ float  g_gate[Td*2];
__device__ int    g_eidx[Td*2];
__device__ int    g_slot_of[Td*2];
__device__ int    g_slot_token[NSLOT];
__device__ int    g_cnt[Ed];
__device__ int    g_off[Ed+1];
__device__ int    g_pos[Ed];
__device__ int    g_tile_e[MAXTILES];
__device__ int    g_tile_row[MAXTILES];
__device__ int    g_tile_end[MAXTILES];
__device__ int    g_ntiles;
__device__ __half g_hidden16[(size_t)NSLOT*HFd]; /* 64 MB */
__device__ float  g_yslot[(size_t)NSLOT*Dd];     /* 32 MB */
__device__ __half g_w1t[(size_t)Ed*HFd*Dd];      /* 16 MB: [e][n][k] fp16 */
__device__ __half g_w2t[(size_t)Ed*Dd*HFd];      /* 16 MB: [e][n][k] fp16 */

// ---------------- fast exp on the FMA pipe ----------------------------------
__device__ __forceinline__ float fexp(float x) {
    x = fmaxf(x, -80.0f);
    float i = rintf(x * 1.44269504088896341f);
    float r = fmaf(i, -0.693359375f, x);
    r = fmaf(i, 2.12194440e-4f, r);
    float z = r * r;
    float p = 1.9875691500e-4f;
    p = fmaf(p, r, 1.3981999507e-3f);
    p = fmaf(p, r, 8.3334519073e-3f);
    p = fmaf(p, r, 4.1665795894e-2f);
    p = fmaf(p, r, 1.6666665459e-1f);
    p = fmaf(p, r, 5.0000001201e-1f);
    float y = fmaf(z, p, r) + 1.0f;
    int j = __float2int_rn(i);
    float sc2 = __int_as_float((j + 127) << 23);
    return y * sc2;
}

// ---------------- rmsnorm ---------------------------------------------------
__global__ void rmsnorm_k(const float* __restrict__ in, const float* __restrict__ w,
                          float* __restrict__ out, __half* __restrict__ out16) {
    int t = blockIdx.x;
    int tid = threadIdx.x;
    const float* row = in + (size_t)t * Dd;
    float v0 = row[tid], v1 = row[tid + 256];
    float ss = v0 * v0 + v1 * v1;
    #pragma unroll
    for (int o = 16; o; o >>= 1) ss += __shfl_xor_sync(0xffffffffu, ss, o);
    __shared__ float red[8];
    __shared__ float sc;
    if ((tid & 31) == 0) red[tid >> 5] = ss;
    __syncthreads();
    if (tid == 0) {
        float s = 0.f;
        #pragma unroll
        for (int i = 0; i < 8; i++) s += red[i];
        sc = rsqrtf(s / (float)Dd + 1e-5f);
    }
    __syncthreads();
    float o0 = v0 * sc * w[tid];
    float o1 = v1 * sc * w[tid + 256];
    out[(size_t)t * Dd + tid]       = o0;
    out[(size_t)t * Dd + tid + 256] = o1;
    if (out16) {
        out16[(size_t)t * Dd + tid]       = __float2half(o0);
        out16[(size_t)t * Dd + tid + 256] = __float2half(o1);
    }
}

// ---------------- fused QKV SGEMM (one launch, 3 weight mats) ---------------
__global__ __launch_bounds__(256, 2)
void sgemm_qkv(const float* __restrict__ A,
               const float* __restrict__ B0, const float* __restrict__ B1,
               const float* __restrict__ B2,
               float* __restrict__ C0, float* __restrict__ C1,
               float* __restrict__ C2, int M, int N, int K) {
    const float* Bm = (blockIdx.z == 0) ? B0 : (blockIdx.z == 1) ? B1 : B2;
    float* C = (blockIdx.z == 0) ? C0 : (blockIdx.z == 1) ? C1 : C2;

    __shared__ float As[2][8][128];
    __shared__ float Bs[2][8][128];
    int m0 = blockIdx.x * 128, n0 = blockIdx.y * 128;
    int tid = threadIdx.x;
    int tx = tid & 15, ty = tid >> 4;
    int aRow = tid >> 1, aCol = (tid & 1) * 4;
    int bRow = tid >> 5, bCol = (tid & 31) * 4;
    const float* aPtr = A + (size_t)(m0 + aRow) * K + aCol;
    const float* bPtr = Bm + (size_t)bRow * N + n0 + bCol;

    float acc[8][8];
    #pragma unroll
    for (int i = 0; i < 8; i++)
        #pragma unroll
        for (int j = 0; j < 8; j++) acc[i][j] = 0.f;

    int nkt = K >> 3;
    {
        float4 av = *(const float4*)(aPtr);
        As[0][aCol+0][aRow] = av.x; As[0][aCol+1][aRow] = av.y;
        As[0][aCol+2][aRow] = av.z; As[0][aCol+3][aRow] = av.w;
        float4 bv = *(const float4*)(bPtr);
        *(float4*)&Bs[0][bRow][bCol] = bv;
    }
    __syncthreads();
    for (int kt = 0; kt < nkt; kt++) {
        int cur = kt & 1;
        if (kt + 1 < nkt) {
            float4 av = *(const float4*)(aPtr + (size_t)(kt + 1) * 8);
            As[cur^1][aCol+0][aRow] = av.x; As[cur^1][aCol+1][aRow] = av.y;
            As[cur^1][aCol+2][aRow] = av.z; As[cur^1][aCol+3][aRow] = av.w;
            float4 bv = *(const float4*)(bPtr + (size_t)(kt + 1) * 8 * N);
            *(float4*)&Bs[cur^1][bRow][bCol] = bv;
        }
        #pragma unroll
        for (int kk = 0; kk < 8; kk++) {
            float a[8], b[8];
            *(float4*)&a[0] = *(const float4*)&As[cur][kk][ty * 4];
            *(float4*)&a[4] = *(const float4*)&As[cur][kk][64 + ty * 4];
            *(float4*)&b[0] = *(const float4*)&Bs[cur][kk][tx * 4];
            *(float4*)&b[4] = *(const float4*)&Bs[cur][kk][64 + tx * 4];
            #pragma unroll
            for (int i = 0; i < 8; i++)
                #pragma unroll
                for (int j = 0; j < 8; j++) acc[i][j] += a[i] * b[j];
        }
        __syncthreads();
    }
    #pragma unroll
    for (int i = 0; i < 8; i++) {
        int r = (i < 4) ? (ty * 4 + i) : (64 + ty * 4 + (i - 4));
        int grow = m0 + r;
        float* crow = C + (size_t)grow * N + n0;
        float4 lo, hi;
        lo.x = acc[i][0]; lo.y = acc[i][1]; lo.z = acc[i][2]; lo.w = acc[i][3];
        hi.x = acc[i][4]; hi.y = acc[i][5]; hi.z = acc[i][6]; hi.w = acc[i][7];
        *(float4*)(crow + tx * 4) = lo;
        *(float4*)(crow + 64 + tx * 4) = hi;
    }
}

// ---------------- O-proj SGEMM with residual --------------------------------
__global__ __launch_bounds__(256, 2)
void sgemm_res(const float* __restrict__ A, const float* __restrict__ Bm,
               float* __restrict__ C, const float* __restrict__ Res,
               int M, int N, int K) {
    __shared__ float As[2][8][128];
    __shared__ float Bs[2][8][128];
    int m0 = blockIdx.x * 128, n0 = blockIdx.y * 128;
    int tid = threadIdx.x;
    int tx = tid & 15, ty = tid >> 4;
    int aRow = tid >> 1, aCol = (tid & 1) * 4;
    int bRow = tid >> 5, bCol = (tid & 31) * 4;
    const float* aPtr = A + (size_t)(m0 + aRow) * K + aCol;
    const float* bPtr = Bm + (size_t)bRow * N + n0 + bCol;

    float acc[8][8];
    #pragma unroll
    for (int i = 0; i < 8; i++)
        #pragma unroll
        for (int j = 0; j < 8; j++) acc[i][j] = 0.f;

    int nkt = K >> 3;
    {
        float4 av = *(const float4*)(aPtr);
        As[0][aCol+0][aRow] = av.x; As[0][aCol+1][aRow] = av.y;
        As[0][aCol+2][aRow] = av.z; As[0][aCol+3][aRow] = av.w;
        float4 bv = *(const float4*)(bPtr);
        *(float4*)&Bs[0][bRow][bCol] = bv;
    }
    __syncthreads();
    for (int kt = 0; kt < nkt; kt++) {
        int cur = kt & 1;
        if (kt + 1 < nkt) {
            float4 av = *(const float4*)(aPtr + (size_t)(kt + 1) * 8);
            As[cur^1][aCol+0][aRow] = av.x; As[cur^1][aCol+1][aRow] = av.y;
            As[cur^1][aCol+2][aRow] = av.z; As[cur^1][aCol+3][aRow] = av.w;
            float4 bv = *(const float4*)(bPtr + (size_t)(kt + 1) * 8 * N);
            *(float4*)&Bs[cur^1][bRow][bCol] = bv;
        }
        #pragma unroll
        for (int kk = 0; kk < 8; kk++) {
            float a[8], b[8];
            *(float4*)&a[0] = *(const float4*)&As[cur][kk][ty * 4];
            *(float4*)&a[4] = *(const float4*)&As[cur][kk][64 + ty * 4];
            *(float4*)&b[0] = *(const float4*)&Bs[cur][kk][tx * 4];
            *(float4*)&b[4] = *(const float4*)&Bs[cur][kk][64 + tx * 4];
            #pragma unroll
            for (int i = 0; i < 8; i++)
                #pragma unroll
                for (int j = 0; j < 8; j++) acc[i][j] += a[i] * b[j];
        }
        __syncthreads();
    }
    #pragma unroll
    for (int i = 0; i < 8; i++) {
        int r = (i < 4) ? (ty * 4 + i) : (64 + ty * 4 + (i - 4));
        int grow = m0 + r;
        float* crow = C + (size_t)grow * N + n0;
        const float* rr = Res + (size_t)grow * N + n0;
        float4 lo, hi;
        float4 r0 = *(const float4*)(rr + tx * 4);
        float4 r1 = *(const float4*)(rr + 64 + tx * 4);
        lo.x = acc[i][0] + r0.x; lo.y = acc[i][1] + r0.y;
        lo.z = acc[i][2] + r0.z; lo.w = acc[i][3] + r0.w;
        hi.x = acc[i][4] + r1.x; hi.y = acc[i][5] + r1.y;
        hi.z = acc[i][6] + r1.z; hi.w = acc[i][7] + r1.w;
        *(float4*)(crow + tx * 4) = lo;
        *(float4*)(crow + 64 + tx * 4) = hi;
    }
}

// ------- weight transpose+convert: W[e][K][N] fp32 -> Wt[e][N][K] fp16 ------
__global__ void transpose_w16_k(const float* __restrict__ W, __half* __restrict__ Wt,
                                int K, int N) {
    __shared__ float t[32][33];
    int e = blockIdx.z;
    int k0 = blockIdx.x * 32, n0 = blockIdx.y * 32;
    const float* We = W + (size_t)e * K * N;
    __half* Wte = Wt + (size_t)e * K * N;
    int tx = threadIdx.x, ty = threadIdx.y;   // 32 x 8
    #pragma unroll
    for (int i = 0; i < 32; i += 8)
        t[ty + i][tx] = We[(size_t)(k0 + ty + i) * N + n0 + tx];
    __syncthreads();
    #pragma unroll
    for (int i = 0; i < 32; i += 8)
        Wte[(size_t)(n0 + ty + i) * K + k0 + tx] = __float2half(t[tx][ty + i]);
}

// ---------------- fp16 tensor-core grouped expert GEMM (ldmatrix) -----------
__device__ __forceinline__ float gelu_f(float x) {
    return 0.5f * x * (1.0f + erff(x * 0.70710678118654752f));
}
__device__ __forceinline__ void cp16(uint32_t dst, const void* src) {
    asm volatile("cp.async.cg.shared.global [%0], [%1], 16;\n" :: "r"(dst), "l"(src));
}
__device__ __forceinline__ void ldsm4(uint32_t& r0, uint32_t& r1, uint32_t& r2,
                                      uint32_t& r3, uint32_t addr) {
    asm volatile("ldmatrix.sync.aligned.m8n8.x4.shared.b16 {%0,%1,%2,%3}, [%4];"
                 : "=r"(r0), "=r"(r1), "=r"(r2), "=r"(r3) : "r"(addr));
}

// smem tile: 128 rows x 64 halves (128 B/row), XOR-swizzled 16B segs
#define TB 16384              /* bytes per tile buffer */
#define SMEM_H2 (4*TB)        /* A x2 + B x2 = 64 KB */

// C[slot, n0..n0+127] = act( A[row(slot), :K] @ Wt[e, n, :K]^T )
template<bool GATHER, bool GELU, bool OUT16>
__global__ __launch_bounds__(256, 2)
void hgemm_grp2(const __half* __restrict__ Abase, const __half* __restrict__ Wt,
                void* __restrict__ Cout, int N, int K) {
    extern __shared__ char sm8[];
    int bx = blockIdx.x;
    if (bx >= g_ntiles) return;
    const int e = g_tile_e[bx], row0 = g_tile_row[bx], rend = g_tile_end[bx];
    const int n0 = blockIdx.y * 128;

    const int tid = threadIdx.x;
    const int lane = tid & 31, wid = tid >> 5;
    const int wm = wid >> 2, wn = wid & 3;      // warp tile (wm*64, wn*32)
    const int lr = lane >> 2, lc = lane & 3;

    const uint32_t sb = (uint32_t)__cvta_generic_to_shared(sm8);

    // ---- loader: row = tid>>1, 4 x 16B segs per thread per chunk ----
    const int ldR = tid >> 1;
    const int segb = (tid & 1) * 4;
    int grow = row0 + ldR;
    int gsafe = grow < rend ? grow : rend - 1;
    int arow = GATHER ? g_slot_token[gsafe] : gsafe;
    const __half* aRow = Abase + (size_t)arow * K + segb * 8;
    const __half* bRow = Wt + ((size_t)e * N + n0 + ldR) * K + segb * 8;
    const int ldRm = ldR & 7;
    uint32_t aD[4], bD[4];
    #pragma unroll
    for (int p = 0; p < 4; p++) {
        uint32_t off = ldR * 128 + (((segb + p) ^ ldRm) << 4);
        aD[p] = sb + off;
        bD[p] = sb + 2 * TB + off;
    }

    // ---- ldmatrix lane addressing ----
    const int lane7 = lane & 7, lsub = (lane >> 3) & 1, lhi = lane >> 4;
    uint32_t aRowOff[4]; int aMod[4];
    #pragma unroll
    for (int am = 0; am < 4; am++) {
        int r = wm * 64 + am * 16 + lane7 + lsub * 8;
        aRowOff[am] = r * 128; aMod[am] = r & 7;
    }
    uint32_t bRowOff[2]; int bMod[2];
    #pragma unroll
    for (int p = 0; p < 2; p++) {
        int r = wn * 32 + p * 16 + lane7 + lsub * 8;
        bRowOff[p] = r * 128; bMod[p] = r & 7;
    }

    float acc[4][4][4];
    #pragma unroll
    for (int i = 0; i < 4; i++)
        #pragma unroll
        for (int j = 0; j < 4; j++)
            #pragma unroll
            for (int r = 0; r < 4; r++) acc[i][j][r] = 0.f;

    const int nkb = K >> 6;   // 64-half chunks
    #pragma unroll
    for (int p = 0; p < 4; p++) {
        cp16(aD[p], aRow + p * 8);
        cp16(bD[p], bRow + p * 8);
    }
    asm volatile("cp.async.commit_group;\n");

    int buf = 0;
    for (int kb = 0; kb < nkb; kb++) {
        if (kb + 1 < nkb) {
            int ko = (kb + 1) * 64;
            #pragma unroll
            for (int p = 0; p < 4; p++) {
                cp16(aD[p] + (buf ^ 1) * TB, aRow + ko + p * 8);
                cp16(bD[p] + (buf ^ 1) * TB + (buf ^ 1) * 0, bRow + ko + p * 8);
            }
            asm volatile("cp.async.commit_group;\n");
            asm volatile("cp.async.wait_group 1;\n");
        } else {
            asm volatile("cp.async.wait_group 0;\n");
        }
        __syncthreads();

        const uint32_t Ab = sb + buf * TB;
        const uint32_t Bb = sb + 2 * TB + buf * TB;
        #pragma unroll
        for (int ks = 0; ks < 4; ks++) {
            uint32_t af[4][4], bf[4][2];
            #pragma unroll
            for (int am = 0; am < 4; am++) {
                uint32_t addr = Ab + aRowOff[am] + ((((ks << 1) + lhi) ^ aMod[am]) << 4);
                ldsm4(af[am][0], af[am][1], af[am][2], af[am][3], addr);
            }
            #pragma unroll
            for (int p = 0; p < 2; p++) {
                uint32_t addr = Bb + bRowOff[p] + ((((ks << 1) + lhi) ^ bMod[p]) << 4);
                uint32_t r0, r1, r2, r3;
                ldsm4(r0, r1, r2, r3, addr);
                bf[2*p][0] = r0; bf[2*p+1][0] = r1;
                bf[2*p][1] = r2; bf[2*p+1][1] = r3;
            }
            #pragma unroll
            for (int am = 0; am < 4; am++)
                #pragma unroll
                for (int an = 0; an < 4; an++)
                    asm volatile(
                        "mma.sync.aligned.m16n8k16.row.col.f32.f16.f16.f32 "
                        "{%0,%1,%2,%3}, {%4,%5,%6,%7}, {%8,%9}, {%0,%1,%2,%3};\n"
                        : "+f"(acc[am][an][0]), "+f"(acc[am][an][1]),
                          "+f"(acc[am][an][2]), "+f"(acc[am][an][3])
                        : "r"(af[am][0]), "r"(af[am][1]), "r"(af[am][2]), "r"(af[am][3]),
                          "r"(bf[an][0]), "r"(bf[an][1]));
        }
        __syncthreads();
        buf ^= 1;
    }

    #pragma unroll
    for (int am = 0; am < 4; am++) {
        int s0 = row0 + wm * 64 + am * 16 + lr;
        #pragma unroll
        for (int an = 0; an < 4; an++) {
            int gc = n0 + wn * 32 + an * 8 + 2 * lc;
            float v0 = acc[am][an][0], v1 = acc[am][an][1];
            float v2 = acc[am][an][2], v3 = acc[am][an][3];
            if (GELU) {
                v0 = gelu_f(v0); v1 = gelu_f(v1);
                v2 = gelu_f(v2); v3 = gelu_f(v3);
            }
            if (OUT16) {
                __half* Ch = (__half*)Cout;
                if (s0 < rend)
                    *(__half2*)&Ch[(size_t)s0 * N + gc] = __floats2half2_rn(v0, v1);
                if (s0 + 8 < rend)
                    *(__half2*)&Ch[(size_t)(s0 + 8) * N + gc] = __floats2half2_rn(v2, v3);
            } else {
                float* Cf = (float*)Cout;
                if (s0 < rend) {
                    float2 t; t.x = v0; t.y = v1;
                    *(float2*)&Cf[(size_t)s0 * N + gc] = t;
                }
                if (s0 + 8 < rend) {
                    float2 t; t.x = v2; t.y = v3;
                    *(float2*)&Cf[(size_t)(s0 + 8) * N + gc] = t;
                }
            }
        }
    }
}

// ---------------- RoPE ------------------------------------------------------
__global__ void rope_k(float* __restrict__ qk) {
    int gid = blockIdx.x * blockDim.x + threadIdx.x;
    if (gid >= Td * 256) return;
    int t = gid >> 8;
    int within = gid & 255;
    int i = within & 31;
    int s = t & (Sd - 1);
    float freq = expf(-(float)(2 * i) * (9.210340371976184f / 64.f));
    float ang = (float)s * freq;
    float sn, cs;
    sincosf(ang, &sn, &cs);
    size_t base = (size_t)t * Dd + within * 2;
    float x1 = qk[base], x2 = qk[base + 1];
    qk[base]     = x1 * cs - x2 * sn;
    qk[base + 1] = x1 * sn + x2 * cs;
}

// ---------------- flash-style causal attention (64x64 tiles, fp32) ---------
__global__ __launch_bounds__(256)
void attn_k(const float* __restrict__ q, const float* __restrict__ k,
            const float* __restrict__ v, float* __restrict__ o) {
    __shared__ float QsT[64][64];
    __shared__ float KPs[64][64];
    __shared__ float Vs[64][64];
    int bh = blockIdx.x;
    int b = bh >> 3, h = bh & 7;
    int qt = (gridDim.y - 1) - blockIdx.y;   // big tiles scheduled first
    int tid = threadIdx.x, tx = tid & 15, ty = tid >> 4;
    size_t tok0 = (size_t)b * Sd;

    #pragma unroll
    for (int l = 0; l < 4; l++) {
        int fidx = tid + l * 256;
        int r = fidx >> 4, dbase = (fidx & 15) * 4;
        float4 qv = *(const float4*)(q + (tok0 + qt * 64 + r) * Dd + h * DHd + dbase);
        QsT[dbase + 0][r] = qv.x * 0.125f; QsT[dbase + 1][r] = qv.y * 0.125f;
        QsT[dbase + 2][r] = qv.z * 0.125f; QsT[dbase + 3][r] = qv.w * 0.125f;
    }

    float m[4], lsum[4], accO[4][4];
    #pragma unroll
    for (int i = 0; i < 4; i++) {
        m[i] = -1e30f; lsum[i] = 0.f;
        #pragma unroll
        for (int j = 0; j < 4; j++) accO[i][j] = 0.f;
    }

    for (int kt = 0; kt <= qt; kt++) {
        __syncthreads();
        #pragma unroll
        for (int l = 0; l < 4; l++) {
            int fidx = tid + l * 256;
            int r = fidx >> 4, dbase = (fidx & 15) * 4;
            size_t gi = (tok0 + kt * 64 + r) * Dd + h * DHd + dbase;
            float4 kv = *(const float4*)(k + gi);
            KPs[dbase + 0][r] = kv.x; KPs[dbase + 1][r] = kv.y;
            KPs[dbase + 2][r] = kv.z; KPs[dbase + 3][r] = kv.w;
            float4 vv = *(const float4*)(v + gi);
            *(float4*)&Vs[r][dbase] = vv;
        }
        __syncthreads();

        float sc[4][4];
        #pragma unroll
        for (int i = 0; i < 4; i++)
            #pragma unroll
            for (int j = 0; j < 4; j++) sc[i][j] = 0.f;
        #pragma unroll 8
        for (int d = 0; d < 64; d++) {
            float a[4], bb[4];
            *(float4*)a  = *(const float4*)&QsT[d][ty * 4];
            *(float4*)bb = *(const float4*)&KPs[d][tx * 4];
            #pragma unroll
            for (int i = 0; i < 4; i++)
                #pragma unroll
                for (int j = 0; j < 4; j++) sc[i][j] += a[i] * bb[j];
        }
        if (kt == qt) {
            #pragma unroll
            for (int i = 0; i < 4; i++)
                #pragma unroll
                for (int j = 0; j < 4; j++) {
                    int qr = ty * 4 + i, kc = tx * 4 + j;
                    if (kc > qr) sc[i][j] = -1e30f;
                }
        }

        float p[4][4];
        #pragma unroll
        for (int i = 0; i < 4; i++) {
            float tm = sc[i][0];
            tm = fmaxf(tm, sc[i][1]); tm = fmaxf(tm, sc[i][2]); tm = fmaxf(tm, sc[i][3]);
            #pragma unroll
            for (int ofs = 8; ofs; ofs >>= 1)
                tm = fmaxf(tm, __shfl_xor_sync(0xffffffffu, tm, ofs));
            float mn = fmaxf(m[i], tm);
            float alpha = fexp(m[i] - mn);
            float rs = 0.f;
            #pragma unroll
            for (int j = 0; j < 4; j++) { p[i][j] = fexp(sc[i][j] - mn); rs += p[i][j]; }
            #pragma unroll
            for (int ofs = 8; ofs; ofs >>= 1)
                rs += __shfl_xor_sync(0xffffffffu, rs, ofs);
            lsum[i] = lsum[i] * alpha + rs;
            m[i] = mn;
            #pragma unroll
            for (int j = 0; j < 4; j++) accO[i][j] *= alpha;
        }

        __syncthreads();
        #pragma unroll
        for (int i = 0; i < 4; i++)
            #pragma unroll
            for (int j = 0; j < 4; j++)
                KPs[tx * 4 + j][ty * 4 + i] = p[i][j];
        __syncthreads();

        #pragma unroll 8
        for (int kk = 0; kk < 64; kk++) {
            float a[4], bb[4];
            *(float4*)a  = *(const float4*)&KPs[kk][ty * 4];
            *(float4*)bb = *(const float4*)&Vs[kk][tx * 4];
            #pragma unroll
            for (int i = 0; i < 4; i++)
                #pragma unroll
                for (int j = 0; j < 4; j++) accO[i][j] += a[i] * bb[j];
        }
    }

    #pragma unroll
    for (int i = 0; i < 4; i++) {
        float inv = 1.0f / lsum[i];
        float4 ov;
        ov.x = accO[i][0] * inv; ov.y = accO[i][1] * inv;
        ov.z = accO[i][2] * inv; ov.w = accO[i][3] * inv;
        *(float4*)(o + (tok0 + qt * 64 + ty * 4 + i) * Dd + h * DHd + tx * 4) = ov;
    }
}

// ---------------- router / scatter -----------------------------------------
__global__ void zero_cnt_k() { if (threadIdx.x < Ed) g_cnt[threadIdx.x] = 0; }

__global__ void router_k(const float* __restrict__ hn, const float* __restrict__ rw) {
    int warp = (blockIdx.x * blockDim.x + threadIdx.x) >> 5;
    int lane = threadIdx.x & 31;
    if (warp >= Td) return;
    const float* row = hn + (size_t)warp * Dd;
    float acc[Ed];
    #pragma unroll
    for (int e = 0; e < Ed; e++) acc[e] = 0.f;
    for (int d = lane; d < Dd; d += 32) {
        float x = row[d];
        #pragma unroll
        for (int e = 0; e < Ed; e++) acc[e] += x * rw[d * Ed + e];
    }
    #pragma unroll
    for (int e = 0; e < Ed; e++)
        #pragma unroll
        for (int o = 16; o; o >>= 1)
            acc[e] += __shfl_xor_sync(0xffffffffu, acc[e], o);
    if (lane == 0) {
        int i0 = 0;
        #pragma unroll
        for (int e = 1; e < Ed; e++) if (acc[e] > acc[i0]) i0 = e;
        int i1 = (i0 == 0) ? 1 : 0;
        #pragma unroll
        for (int e = 0; e < Ed; e++) if (e != i0 && acc[e] > acc[i1]) i1 = e;
        float ex = expf(acc[i1] - acc[i0]);
        float g0 = 1.f / (1.f + ex);
        float g1 = ex / (1.f + ex);
        g_eidx[warp * 2] = i0; g_eidx[warp * 2 + 1] = i1;
        g_gate[warp * 2] = g0; g_gate[warp * 2 + 1] = g1;
        atomicAdd(&g_cnt[i0], 1);
        atomicAdd(&g_cnt[i1], 1);
    }
}

__global__ void tiles_k() {
    int off = 0, nt = 0;
    for (int e = 0; e < Ed; e++) {
        g_off[e] = off; g_pos[e] = 0;
        int c = g_cnt[e];
        for (int r = 0; r < c; r += 128) {
            g_tile_e[nt] = e; g_tile_row[nt] = off + r; g_tile_end[nt] = off + c; nt++;
        }
        off += c;
    }
    g_off[Ed] = off;
    g_ntiles = nt;
}

__global__ void assign_k() {
    int t = blockIdx.x * blockDim.x + threadIdx.x;
    if (t >= Td) return;
    #pragma unroll
    for (int kk = 0; kk < 2; kk++) {
        int e = g_eidx[t * 2 + kk];
        int p = atomicAdd(&g_pos[e], 1);
        int slot = g_off[e] + p;
        g_slot_token[slot] = t;
        g_slot_of[t * 2 + kk] = slot;
    }
}

__global__ void final_k(float* __restrict__ out) {
    int idx = blockIdx.x * blockDim.x + threadIdx.x;
    if (idx >= Td * Dd) return;
    int t = idx >> 9, d = idx & 511;
    float r = g_h[idx];
    r += g_gate[t * 2]     * g_yslot[(size_t)g_slot_of[t * 2]     * Dd + d];
    r += g_gate[t * 2 + 1] * g_yslot[(size_t)g_slot_of[t * 2 + 1] * Dd + d];
    out[idx] = r;
}

// ---------------- launch -----------------------------------------------------
extern "C" void kernel_launch(void* const* d_in, const int* in_sizes, int n_in,
                              void* d_out, int out_size) {
    const float* x   = (const float*)d_in[0];
    const float* anw = (const float*)d_in[1];
    const float* wq  = (const float*)d_in[2];
    const float* wk  = (const float*)d_in[3];
    const float* wv  = (const float*)d_in[4];
    const float* wo  = (const float*)d_in[5];
    const float* fnw = (const float*)d_in[6];
    const float* rw  = (const float*)d_in[7];
    const float* w1  = (const float*)d_in[8];
    const float* w2  = (const float*)d_in[9];
    float* out = (float*)d_out;

    float *p_xn, *p_q, *p_k, *p_v, *p_att, *p_h, *p_hn, *p_yslot;
    __half *p_hn16, *p_hidden16, *p_w1t, *p_w2t;
    cudaGetSymbolAddress((void**)&p_xn, g_xn);
    cudaGetSymbolAddress((void**)&p_q, g_q);
    cudaGetSymbolAddress((void**)&p_k, g_k);
    cudaGetSymbolAddress((void**)&p_v, g_v);
    cudaGetSymbolAddress((void**)&p_att, g_att);
    cudaGetSymbolAddress((void**)&p_h, g_h);
    cudaGetSymbolAddress((void**)&p_hn, g_hn);
    cudaGetSymbolAddress((void**)&p_hn16, g_hn16);
    cudaGetSymbolAddress((void**)&p_hidden16, g_hidden16);
    cudaGetSymbolAddress((void**)&p_yslot, g_yslot);
    cudaGetSymbolAddress((void**)&p_w1t, g_w1t);
    cudaGetSymbolAddress((void**)&p_w2t, g_w2t);

    cudaFuncSetAttribute(hgemm_grp2<true, true, true>,
                         cudaFuncAttributeMaxDynamicSharedMemorySize, SMEM_H2);
    cudaFuncSetAttribute(hgemm_grp2<false, false, false>,
                         cudaFuncAttributeMaxDynamicSharedMemorySize, SMEM_H2);

    // 0) transpose+convert expert weights to fp16 K-major
    transpose_w16_k<<<dim3(Dd / 32, HFd / 32, Ed), dim3(32, 8)>>>(w1, p_w1t, Dd, HFd);
    transpose_w16_k<<<dim3(HFd / 32, Dd / 32, Ed), dim3(32, 8)>>>(w2, p_w2t, HFd, Dd);
    // 1) rmsnorm(x)
    rmsnorm_k<<<Td, 256>>>(x, anw, p_xn, nullptr);
    // 2) fused q,k,v GEMMs (one launch, fp32)
    sgemm_qkv<<<dim3(Td / 128, Dd / 128, 3), 256>>>(p_xn, wq, wk, wv,
                                                    p_q, p_k, p_v, Td, Dd, Dd);
    // 3) RoPE on q,k
    rope_k<<<(Td * 256) / 256, 256>>>(p_q);
    rope_k<<<(Td * 256) / 256, 256>>>(p_k);
    // 4) causal attention (big tiles first)
    attn_k<<<dim3(Bd * Hd, Sd / 64), 256>>>(p_q, p_k, p_v, p_att);
    // 5) O projection + residual
    sgemm_res<<<dim3(Td / 128, Dd / 128), 256>>>(p_att, wo, p_h, x, Td, Dd, Dd);
    // 6) rmsnorm(h) + fp16 copy for MoE
    rmsnorm_k<<<Td, 256>>>(p_h, fnw, p_hn, p_hn16);
    // 7) router + expert grouping (fp32 logits — bit-stable routing)
    zero_cnt_k<<<1, 32>>>();
    router_k<<<Td / 8, 256>>>(p_hn, rw);
    tiles_k<<<1, 1>>>();
    assign_k<<<Td / 256, 256>>>();
    // 8) expert GEMM 1: hidden16 = gelu(hn16 @ w1[e])   [fp16 mma + ldmatrix]
    hgemm_grp2<true, true, true><<<dim3(MAXTILES, HFd / 128), 256, SMEM_H2>>>(
        p_hn16, p_w1t, p_hidden16, HFd, Dd);
    // 9) expert GEMM 2: yslot = hidden16 @ w2[e]        [fp16 mma + ldmatrix]
    hgemm_grp2<false, false, false><<<dim3(MAXTILES, Dd / 128), 256, SMEM_H2>>>(
        p_hidden16, p_w2t, p_yslot, Dd, HFd);
    // 10) final gather + residual
    final_k<<<(Td * Dd) / 256, 256>>>(out);
}

// round 10
// speedup vs baseline: 2.1077x; 1.1140x over previous
#include <cuda_runtime.h>
#include <cuda_fp16.h>
#include <math.h>
#include <stdint.h>

#define Bd 4
#define Sd 2048
#define Dd 512
#define Hd 8
#define DHd 64
#define Ed 8
#define HFd 2048
#define Td (Bd*Sd)        /* 8192 tokens */
#define NSLOT (2*Td)      /* 16384 expert-slots */
#define MAXTILES 144

// ---------------- scratch (device globals; no allocation allowed) ----------
__device__ float  g_q[Td*Dd];
__device__ float  g_k[Td*Dd];
__device__ float  g_v[Td*Dd];
__device__ float  g_h[Td*Dd];
__device__ float  g_hn[Td*Dd];
__device__ __half g_xnh[Td*Dd];
__device__ __half g_xnl[Td*Dd];
__device__ __half g_atth[Td*Dd];
__device__ __half g_attl[Td*Dd];
__device__ __half g_hn16[Td*Dd];
__device__ __half g_wqkvh[3*Dd*Dd];   /* [z][n][k] hi */
__device__ __half g_wqkvl[3*Dd*Dd];   /* [z][n][k] lo */
__device__ __half g_woh[Dd*Dd];
__device__ __half g_wol[Dd*Dd];
__device__ float  g_gate[Td*2];
__device__ int    g_eidx[Td*2];
__device__ int    g_slot_of[Td*2];
__device__ int    g_slot_token[NSLOT];
__device__ int    g_cnt[Ed];
__device__ int    g_off[Ed+1];
__device__ int    g_pos[Ed];
__device__ int    g_tile_e[MAXTILES];
__device__ int    g_tile_row[MAXTILES];
__device__ int    g_tile_end[MAXTILES];
__device__ int    g_ntiles;
__device__ __half g_hidden16[(size_t)NSLOT*HFd]; /* 64 MB */
__device__ float  g_yslot[(size_t)NSLOT*Dd];     /* 32 MB */
__device__ __half g_w1t[(size_t)Ed*HFd*Dd];      /* 16 MB: [e][n][k] fp16 */
__device__ __half g_w2t[(size_t)Ed*Dd*HFd];      /* 16 MB: [e][n][k] fp16 */

// ---------------- fast exp on the FMA pipe ----------------------------------
__device__ __forceinline__ float fexp(float x) {
    x = fmaxf(x, -80.0f);
    float i = rintf(x * 1.44269504088896341f);
    float r = fmaf(i, -0.693359375f, x);
    r = fmaf(i, 2.12194440e-4f, r);
    float z = r * r;
    float p = 1.9875691500e-4f;
    p = fmaf(p, r, 1.3981999507e-3f);
    p = fmaf(p, r, 8.3334519073e-3f);
    p = fmaf(p, r, 4.1665795894e-2f);
    p = fmaf(p, r, 1.6666665459e-1f);
    p = fmaf(p, r, 5.0000001201e-1f);
    float y = fmaf(z, p, r) + 1.0f;
    int j = __float2int_rn(i);
    float sc2 = __int_as_float((j + 127) << 23);
    return y * sc2;
}

// ---------------- rmsnorm (fp32 out nullable; optional hi/lo fp16) ----------
__global__ void rmsnorm_k(const float* __restrict__ in, const float* __restrict__ w,
                          float* __restrict__ out,
                          __half* __restrict__ outh, __half* __restrict__ outl) {
    int t = blockIdx.x;
    int tid = threadIdx.x;
    const float* row = in + (size_t)t * Dd;
    float v0 = row[tid], v1 = row[tid + 256];
    float ss = v0 * v0 + v1 * v1;
    #pragma unroll
    for (int o = 16; o; o >>= 1) ss += __shfl_xor_sync(0xffffffffu, ss, o);
    __shared__ float red[8];
    __shared__ float sc;
    if ((tid & 31) == 0) red[tid >> 5] = ss;
    __syncthreads();
    if (tid == 0) {
        float s = 0.f;
        #pragma unroll
        for (int i = 0; i < 8; i++) s += red[i];
        sc = rsqrtf(s / (float)Dd + 1e-5f);
    }
    __syncthreads();
    float o0 = v0 * sc * w[tid];
    float o1 = v1 * sc * w[tid + 256];
    size_t i0 = (size_t)t * Dd + tid, i1 = i0 + 256;
    if (out) { out[i0] = o0; out[i1] = o1; }
    if (outh) {
        __half h0 = __float2half(o0), h1 = __float2half(o1);
        outh[i0] = h0; outh[i1] = h1;
        if (outl) {
            outl[i0] = __float2half(o0 - __half2float(h0));
            outl[i1] = __float2half(o1 - __half2float(h1));
        }
    }
}

// ------- dense weight transpose: W[K][N] fp32 -> Wh/Wl[N][K] hi/lo fp16 -----
__global__ void transpose_whl_k(const float* __restrict__ W,
                                __half* __restrict__ Wh, __half* __restrict__ Wl,
                                int K, int N) {
    __shared__ float t[32][33];
    int k0 = blockIdx.x * 32, n0 = blockIdx.y * 32;
    int tx = threadIdx.x, ty = threadIdx.y;   // 32 x 8
    #pragma unroll
    for (int i = 0; i < 32; i += 8)
        t[ty + i][tx] = W[(size_t)(k0 + ty + i) * N + n0 + tx];
    __syncthreads();
    #pragma unroll
    for (int i = 0; i < 32; i += 8) {
        float v = t[tx][ty + i];
        __half hi = __float2half(v);
        size_t idx = (size_t)(n0 + ty + i) * K + k0 + tx;
        Wh[idx] = hi;
        Wl[idx] = __float2half(v - __half2float(hi));
    }
}

// ------- expert weight transpose+convert: W[e][K][N] fp32 -> [e][N][K] fp16 -
__global__ void transpose_w16_k(const float* __restrict__ W, __half* __restrict__ Wt,
                                int K, int N) {
    __shared__ float t[32][33];
    int e = blockIdx.z;
    int k0 = blockIdx.x * 32, n0 = blockIdx.y * 32;
    const float* We = W + (size_t)e * K * N;
    __half* Wte = Wt + (size_t)e * K * N;
    int tx = threadIdx.x, ty = threadIdx.y;
    #pragma unroll
    for (int i = 0; i < 32; i += 8)
        t[ty + i][tx] = We[(size_t)(k0 + ty + i) * N + n0 + tx];
    __syncthreads();
    #pragma unroll
    for (int i = 0; i < 32; i += 8)
        Wte[(size_t)(n0 + ty + i) * K + k0 + tx] = __float2half(t[tx][ty + i]);
}

// ---------------- mma helpers -----------------------------------------------
__device__ __forceinline__ void cp16(uint32_t dst, const void* src) {
    asm volatile("cp.async.cg.shared.global [%0], [%1], 16;\n" :: "r"(dst), "l"(src));
}
__device__ __forceinline__ void ldsm4(uint32_t& r0, uint32_t& r1, uint32_t& r2,
                                      uint32_t& r3, uint32_t addr) {
    asm volatile("ldmatrix.sync.aligned.m8n8.x4.shared.b16 {%0,%1,%2,%3}, [%4];"
                 : "=r"(r0), "=r"(r1), "=r"(r2), "=r"(r3) : "r"(addr));
}
#define MMA16(ac, a, b0, b1) \
    asm volatile( \
        "mma.sync.aligned.m16n8k16.row.col.f32.f16.f16.f32 " \
        "{%0,%1,%2,%3}, {%4,%5,%6,%7}, {%8,%9}, {%0,%1,%2,%3};\n" \
        : "+f"((ac)[0]), "+f"((ac)[1]), "+f"((ac)[2]), "+f"((ac)[3]) \
        : "r"((a)[0]), "r"((a)[1]), "r"((a)[2]), "r"((a)[3]), "r"(b0), "r"(b1))

// ---------------- split-fp16 dense GEMM (fp32-accurate, tensor cores) -------
// Tile 128x128, k-chunk 32. smem row = [hi 32 halves | lo 32 halves] = 128 B,
// 8 x 16B segs XOR-swizzled by (row&7) — same proven scheme as hgemm_grp2.
#define STB 16384            /* bytes per tile buffer */
#define SMEM_S (4*STB)       /* A x2 bufs + B x2 bufs = 64 KB */

template<bool RES>
__global__ __launch_bounds__(256, 2)
void sgemm_split(const __half* __restrict__ Ah, const __half* __restrict__ Al,
                 const __half* __restrict__ Wh, const __half* __restrict__ Wl,
                 float* __restrict__ Cq, float* __restrict__ Ck, float* __restrict__ Cv,
                 const float* __restrict__ Res, int N, int K) {
    extern __shared__ char sms[];
    const int z = blockIdx.z;
    const __half* Bh_g = Wh + (size_t)z * N * K;
    const __half* Bl_g = Wl + (size_t)z * N * K;
    float* C = (z == 0) ? Cq : (z == 1) ? Ck : Cv;

    const int m0 = blockIdx.x * 128, n0 = blockIdx.y * 128;
    const int tid = threadIdx.x;
    const int lane = tid & 31, wid = tid >> 5;
    const int wm = wid >> 2, wn = wid & 3;      // warp tile (wm*64, wn*32)
    const int lr = lane >> 2, lc = lane & 3;
    const uint32_t sb = (uint32_t)__cvta_generic_to_shared(sms);

    // ---- loader: row = tid>>1; (tid&1)==0 loads hi segs 0-3, ==1 lo segs 4-7
    const int ldR = tid >> 1;
    const int hsel = tid & 1;
    const __half* aSrc = (hsel ? Al : Ah) + (size_t)(m0 + ldR) * K;
    const __half* bSrc = (hsel ? Bl_g : Bh_g) + (size_t)(n0 + ldR) * K;
    const int ldRm = ldR & 7;
    uint32_t aD[4], bD[4];
    #pragma unroll
    for (int p = 0; p < 4; p++) {
        uint32_t off = ldR * 128 + ((((hsel << 2) + p) ^ ldRm) << 4);
        aD[p] = sb + off;
        bD[p] = sb + 2 * STB + off;
    }

    // ---- ldmatrix lane addressing ----
    const int lane7 = lane & 7, lsub = (lane >> 3) & 1, lhi = lane >> 4;
    uint32_t aRowOff[4]; int aMod[4];
    #pragma unroll
    for (int am = 0; am < 4; am++) {
        int r = wm * 64 + am * 16 + lane7 + lsub * 8;
        aRowOff[am] = r * 128; aMod[am] = r & 7;
    }
    uint32_t bRowOff[2]; int bMod[2];
    #pragma unroll
    for (int p = 0; p < 2; p++) {
        int r = wn * 32 + p * 16 + lane7 + lsub * 8;
        bRowOff[p] = r * 128; bMod[p] = r & 7;
    }

    float acc[4][4][4];
    #pragma unroll
    for (int i = 0; i < 4; i++)
        #pragma unroll
        for (int j = 0; j < 4; j++)
            #pragma unroll
            for (int r = 0; r < 4; r++) acc[i][j][r] = 0.f;

    const int nkb = K >> 5;   // 32-half k-chunks
    #pragma unroll
    for (int p = 0; p < 4; p++) {
        cp16(aD[p], aSrc + p * 8);
        cp16(bD[p], bSrc + p * 8);
    }
    asm volatile("cp.async.commit_group;\n");

    int buf = 0;
    for (int kb = 0; kb < nkb; kb++) {
        if (kb + 1 < nkb) {
            int ko = (kb + 1) * 32;
            #pragma unroll
            for (int p = 0; p < 4; p++) {
                cp16(aD[p] + (buf ^ 1) * STB, aSrc + ko + p * 8);
                cp16(bD[p] + (buf ^ 1) * STB, bSrc + ko + p * 8);
            }
            asm volatile("cp.async.commit_group;\n");
            asm volatile("cp.async.wait_group 1;\n");
        } else {
            asm volatile("cp.async.wait_group 0;\n");
        }
        __syncthreads();

        const uint32_t Ab = sb + buf * STB;
        const uint32_t Bb = sb + 2 * STB + buf * STB;
        #pragma unroll
        for (int ks = 0; ks < 2; ks++) {
            const int segh = (ks << 1) + lhi;      // hi seg 0..3
            uint32_t af[4][4], bfh[4][2], bfl[4][2];
            // A hi fragments
            #pragma unroll
            for (int am = 0; am < 4; am++) {
                uint32_t addr = Ab + aRowOff[am] + ((segh ^ aMod[am]) << 4);
                ldsm4(af[am][0], af[am][1], af[am][2], af[am][3], addr);
            }
            // B hi + lo fragments
            #pragma unroll
            for (int p = 0; p < 2; p++) {
                uint32_t r0, r1, r2, r3;
                ldsm4(r0, r1, r2, r3, Bb + bRowOff[p] + ((segh ^ bMod[p]) << 4));
                bfh[2*p][0] = r0; bfh[2*p+1][0] = r1;
                bfh[2*p][1] = r2; bfh[2*p+1][1] = r3;
                ldsm4(r0, r1, r2, r3, Bb + bRowOff[p] + (((segh + 4) ^ bMod[p]) << 4));
                bfl[2*p][0] = r0; bfl[2*p+1][0] = r1;
                bfl[2*p][1] = r2; bfl[2*p+1][1] = r3;
            }
            // term 1: Ah * Bh ; term 2: Ah * Bl
            #pragma unroll
            for (int am = 0; am < 4; am++)
                #pragma unroll
                for (int an = 0; an < 4; an++) {
                    MMA16(acc[am][an], af[am], bfh[an][0], bfh[an][1]);
                    MMA16(acc[am][an], af[am], bfl[an][0], bfl[an][1]);
                }
            // A lo fragments (reuse af regs), term 3: Al * Bh
            #pragma unroll
            for (int am = 0; am < 4; am++) {
                uint32_t addr = Ab + aRowOff[am] + (((segh + 4) ^ aMod[am]) << 4);
                ldsm4(af[am][0], af[am][1], af[am][2], af[am][3], addr);
            }
            #pragma unroll
            for (int am = 0; am < 4; am++)
                #pragma unroll
                for (int an = 0; an < 4; an++)
                    MMA16(acc[am][an], af[am], bfh[an][0], bfh[an][1]);
        }
        __syncthreads();
        buf ^= 1;
    }

    // ---- epilogue: fp32 C (+ optional residual) ----
    #pragma unroll
    for (int am = 0; am < 4; am++) {
        #pragma unroll
        for (int hrow = 0; hrow < 2; hrow++) {
            int grow = m0 + wm * 64 + am * 16 + hrow * 8 + lr;
            float* crow = C + (size_t)grow * N + n0;
            const float* rrow = RES ? (Res + (size_t)grow * N + n0) : nullptr;
            #pragma unroll
            for (int an = 0; an < 4; an++) {
                int gc = wn * 32 + an * 8 + 2 * lc;
                float v0 = acc[am][an][hrow * 2 + 0];
                float v1 = acc[am][an][hrow * 2 + 1];
                if (RES) { v0 += rrow[gc]; v1 += rrow[gc + 1]; }
                float2 t; t.x = v0; t.y = v1;
                *(float2*)&crow[gc] = t;
            }
        }
    }
}

// ---------------- fp16 tensor-core grouped expert GEMM (ldmatrix) -----------
__device__ __forceinline__ float gelu_f(float x) {
    return 0.5f * x * (1.0f + erff(x * 0.70710678118654752f));
}

#define TB 16384              /* bytes per tile buffer */
#define SMEM_H2 (4*TB)        /* A x2 + B x2 = 64 KB */

template<bool GATHER, bool GELU, bool OUT16>
__global__ __launch_bounds__(256, 2)
void hgemm_grp2(const __half* __restrict__ Abase, const __half* __restrict__ Wt,
                void* __restrict__ Cout, int N, int K) {
    extern __shared__ char sm8[];
    int bx = blockIdx.x;
    if (bx >= g_ntiles) return;
    const int e = g_tile_e[bx], row0 = g_tile_row[bx], rend = g_tile_end[bx];
    const int n0 = blockIdx.y * 128;

    const int tid = threadIdx.x;
    const int lane = tid & 31, wid = tid >> 5;
    const int wm = wid >> 2, wn = wid & 3;
    const int lr = lane >> 2, lc = lane & 3;
    const uint32_t sb = (uint32_t)__cvta_generic_to_shared(sm8);

    const int ldR = tid >> 1;
    const int segb = (tid & 1) * 4;
    int grow = row0 + ldR;
    int gsafe = grow < rend ? grow : rend - 1;
    int arow = GATHER ? g_slot_token[gsafe] : gsafe;
    const __half* aRow = Abase + (size_t)arow * K + segb * 8;
    const __half* bRow = Wt + ((size_t)e * N + n0 + ldR) * K + segb * 8;
    const int ldRm = ldR & 7;
    uint32_t aD[4], bD[4];
    #pragma unroll
    for (int p = 0; p < 4; p++) {
        uint32_t off = ldR * 128 + (((segb + p) ^ ldRm) << 4);
        aD[p] = sb + off;
        bD[p] = sb + 2 * TB + off;
    }

    const int lane7 = lane & 7, lsub = (lane >> 3) & 1, lhi = lane >> 4;
    uint32_t aRowOff[4]; int aMod[4];
    #pragma unroll
    for (int am = 0; am < 4; am++) {
        int r = wm * 64 + am * 16 + lane7 + lsub * 8;
        aRowOff[am] = r * 128; aMod[am] = r & 7;
    }
    uint32_t bRowOff[2]; int bMod[2];
    #pragma unroll
    for (int p = 0; p < 2; p++) {
        int r = wn * 32 + p * 16 + lane7 + lsub * 8;
        bRowOff[p] = r * 128; bMod[p] = r & 7;
    }

    float acc[4][4][4];
    #pragma unroll
    for (int i = 0; i < 4; i++)
        #pragma unroll
        for (int j = 0; j < 4; j++)
            #pragma unroll
            for (int r = 0; r < 4; r++) acc[i][j][r] = 0.f;

    const int nkb = K >> 6;
    #pragma unroll
    for (int p = 0; p < 4; p++) {
        cp16(aD[p], aRow + p * 8);
        cp16(bD[p], bRow + p * 8);
    }
    asm volatile("cp.async.commit_group;\n");

    int buf = 0;
    for (int kb = 0; kb < nkb; kb++) {
        if (kb + 1 < nkb) {
            int ko = (kb + 1) * 64;
            #pragma unroll
            for (int p = 0; p < 4; p++) {
                cp16(aD[p] + (buf ^ 1) * TB, aRow + ko + p * 8);
                cp16(bD[p] + (buf ^ 1) * TB, bRow + ko + p * 8);
            }
            asm volatile("cp.async.commit_group;\n");
            asm volatile("cp.async.wait_group 1;\n");
        } else {
            asm volatile("cp.async.wait_group 0;\n");
        }
        __syncthreads();

        const uint32_t Ab = sb + buf * TB;
        const uint32_t Bb = sb + 2 * TB + buf * TB;
        #pragma unroll
        for (int ks = 0; ks < 4; ks++) {
            uint32_t af[4][4], bf[4][2];
            #pragma unroll
            for (int am = 0; am < 4; am++) {
                uint32_t addr = Ab + aRowOff[am] + ((((ks << 1) + lhi) ^ aMod[am]) << 4);
                ldsm4(af[am][0], af[am][1], af[am][2], af[am][3], addr);
            }
            #pragma unroll
            for (int p = 0; p < 2; p++) {
                uint32_t addr = Bb + bRowOff[p] + ((((ks << 1) + lhi) ^ bMod[p]) << 4);
                uint32_t r0, r1, r2, r3;
                ldsm4(r0, r1, r2, r3, addr);
                bf[2*p][0] = r0; bf[2*p+1][0] = r1;
                bf[2*p][1] = r2; bf[2*p+1][1] = r3;
            }
            #pragma unroll
            for (int am = 0; am < 4; am++)
                #pragma unroll
                for (int an = 0; an < 4; an++)
                    MMA16(acc[am][an], af[am], bf[an][0], bf[an][1]);
        }
        __syncthreads();
        buf ^= 1;
    }

    #pragma unroll
    for (int am = 0; am < 4; am++) {
        int s0 = row0 + wm * 64 + am * 16 + lr;
        #pragma unroll
        for (int an = 0; an < 4; an++) {
            int gc = n0 + wn * 32 + an * 8 + 2 * lc;
            float v0 = acc[am][an][0], v1 = acc[am][an][1];
            float v2 = acc[am][an][2], v3 = acc[am][an][3];
            if (GELU) {
                v0 = gelu_f(v0); v1 = gelu_f(v1);
                v2 = gelu_f(v2); v3 = gelu_f(v3);
            }
            if (OUT16) {
                __half* Ch = (__half*)Cout;
                if (s0 < rend)
                    *(__half2*)&Ch[(size_t)s0 * N + gc] = __floats2half2_rn(v0, v1);
                if (s0 + 8 < rend)
                    *(__half2*)&Ch[(size_t)(s0 + 8) * N + gc] = __floats2half2_rn(v2, v3);
            } else {
                float* Cf = (float*)Cout;
                if (s0 < rend) {
                    float2 t; t.x = v0; t.y = v1;
                    *(float2*)&Cf[(size_t)s0 * N + gc] = t;
                }
                if (s0 + 8 < rend) {
                    float2 t; t.x = v2; t.y = v3;
                    *(float2*)&Cf[(size_t)(s0 + 8) * N + gc] = t;
                }
            }
        }
    }
}

// ---------------- RoPE ------------------------------------------------------
__global__ void rope_k(float* __restrict__ qk) {
    int gid = blockIdx.x * blockDim.x + threadIdx.x;
    if (gid >= Td * 256) return;
    int t = gid >> 8;
    int within = gid & 255;
    int i = within & 31;
    int s = t & (Sd - 1);
    float freq = expf(-(float)(2 * i) * (9.210340371976184f / 64.f));
    float ang = (float)s * freq;
    float sn, cs;
    sincosf(ang, &sn, &cs);
    size_t base = (size_t)t * Dd + within * 2;
    float x1 = qk[base], x2 = qk[base + 1];
    qk[base]     = x1 * cs - x2 * sn;
    qk[base + 1] = x1 * sn + x2 * cs;
}

// ---------------- flash-style causal attention (fp32; hi/lo fp16 output) ---
__global__ __launch_bounds__(256)
void attn_k(const float* __restrict__ q, const float* __restrict__ k,
            const float* __restrict__ v,
            __half* __restrict__ oh, __half* __restrict__ ol) {
    __shared__ float QsT[64][64];
    __shared__ float KPs[64][64];
    __shared__ float Vs[64][64];
    int bh = blockIdx.x;
    int b = bh >> 3, h = bh & 7;
    int qt = (gridDim.y - 1) - blockIdx.y;   // big tiles first
    int tid = threadIdx.x, tx = tid & 15, ty = tid >> 4;
    size_t tok0 = (size_t)b * Sd;

    #pragma unroll
    for (int l = 0; l < 4; l++) {
        int fidx = tid + l * 256;
        int r = fidx >> 4, dbase = (fidx & 15) * 4;
        float4 qv = *(const float4*)(q + (tok0 + qt * 64 + r) * Dd + h * DHd + dbase);
        QsT[dbase + 0][r] = qv.x * 0.125f; QsT[dbase + 1][r] = qv.y * 0.125f;
        QsT[dbase + 2][r] = qv.z * 0.125f; QsT[dbase + 3][r] = qv.w * 0.125f;
    }

    float m[4], lsum[4], accO[4][4];
    #pragma unroll
    for (int i = 0; i < 4; i++) {
        m[i] = -1e30f; lsum[i] = 0.f;
        #pragma unroll
        for (int j = 0; j < 4; j++) accO[i][j] = 0.f;
    }

    for (int kt = 0; kt <= qt; kt++) {
        __syncthreads();
        #pragma unroll
        for (int l = 0; l < 4; l++) {
            int fidx = tid + l * 256;
            int r = fidx >> 4, dbase = (fidx & 15) * 4;
            size_t gi = (tok0 + kt * 64 + r) * Dd + h * DHd + dbase;
            float4 kv = *(const float4*)(k + gi);
            KPs[dbase + 0][r] = kv.x; KPs[dbase + 1][r] = kv.y;
            KPs[dbase + 2][r] = kv.z; KPs[dbase + 3][r] = kv.w;
            float4 vv = *(const float4*)(v + gi);
            *(float4*)&Vs[r][dbase] = vv;
        }
        __syncthreads();

        float sc[4][4];
        #pragma unroll
        for (int i = 0; i < 4; i++)
            #pragma unroll
            for (int j = 0; j < 4; j++) sc[i][j] = 0.f;
        #pragma unroll 8
        for (int d = 0; d < 64; d++) {
            float a[4], bb[4];
            *(float4*)a  = *(const float4*)&QsT[d][ty * 4];
            *(float4*)bb = *(const float4*)&KPs[d][tx * 4];
            #pragma unroll
            for (int i = 0; i < 4; i++)
                #pragma unroll
                for (int j = 0; j < 4; j++) sc[i][j] += a[i] * bb[j];
        }
        if (kt == qt) {
            #pragma unroll
            for (int i = 0; i < 4; i++)
                #pragma unroll
                for (int j = 0; j < 4; j++) {
                    int qr = ty * 4 + i, kc = tx * 4 + j;
                    if (kc > qr) sc[i][j] = -1e30f;
                }
        }

        float p[4][4];
        #pragma unroll
        for (int i = 0; i < 4; i++) {
            float tm = sc[i][0];
            tm = fmaxf(tm, sc[i][1]); tm = fmaxf(tm, sc[i][2]); tm = fmaxf(tm, sc[i][3]);
            #pragma unroll
            for (int ofs = 8; ofs; ofs >>= 1)
                tm = fmaxf(tm, __shfl_xor_sync(0xffffffffu, tm, ofs));
            float mn = fmaxf(m[i], tm);
            float alpha = fexp(m[i] - mn);
            float rs = 0.f;
            #pragma unroll
            for (int j = 0; j < 4; j++) { p[i][j] = fexp(sc[i][j] - mn); rs += p[i][j]; }
            #pragma unroll
            for (int ofs = 8; ofs; ofs >>= 1)
                rs += __shfl_xor_sync(0xffffffffu, rs, ofs);
            lsum[i] = lsum[i] * alpha + rs;
            m[i] = mn;
            #pragma unroll
            for (int j = 0; j < 4; j++) accO[i][j] *= alpha;
        }

        __syncthreads();
        #pragma unroll
        for (int i = 0; i < 4; i++)
            #pragma unroll
            for (int j = 0; j < 4; j++)
                KPs[tx * 4 + j][ty * 4 + i] = p[i][j];
        __syncthreads();

        #pragma unroll 8
        for (int kk = 0; kk < 64; kk++) {
            float a[4], bb[4];
            *(float4*)a  = *(const float4*)&KPs[kk][ty * 4];
            *(float4*)bb = *(const float4*)&Vs[kk][tx * 4];
            #pragma unroll
            for (int i = 0; i < 4; i++)
                #pragma unroll
                for (int j = 0; j < 4; j++) accO[i][j] += a[i] * bb[j];
        }
    }

    #pragma unroll
    for (int i = 0; i < 4; i++) {
        float inv = 1.0f / lsum[i];
        size_t off = (tok0 + qt * 64 + ty * 4 + i) * Dd + h * DHd + tx * 4;
        #pragma unroll
        for (int j = 0; j < 4; j += 2) {
            float v0 = accO[i][j] * inv, v1 = accO[i][j+1] * inv;
            __half h0 = __float2half(v0), h1 = __float2half(v1);
            *(__half2*)&oh[off + j] = __halves2half2(h0, h1);
            *(__half2*)&ol[off + j] = __halves2half2(
                __float2half(v0 - __half2float(h0)),
                __float2half(v1 - __half2float(h1)));
        }
    }
}

// ---------------- router / scatter -----------------------------------------
__global__ void zero_cnt_k() { if (threadIdx.x < Ed) g_cnt[threadIdx.x] = 0; }

__global__ void router_k(const float* __restrict__ hn, const float* __restrict__ rw) {
    int warp = (blockIdx.x * blockDim.x + threadIdx.x) >> 5;
    int lane = threadIdx.x & 31;
    if (warp >= Td) return;
    const float* row = hn + (size_t)warp * Dd;
    float acc[Ed];
    #pragma unroll
    for (int e = 0; e < Ed; e++) acc[e] = 0.f;
    for (int d = lane; d < Dd; d += 32) {
        float x = row[d];
        #pragma unroll
        for (int e = 0; e < Ed; e++) acc[e] += x * rw[d * Ed + e];
    }
    #pragma unroll
    for (int e = 0; e < Ed; e++)
        #pragma unroll
        for (int o = 16; o; o >>= 1)
            acc[e] += __shfl_xor_sync(0xffffffffu, acc[e], o);
    if (lane == 0) {
        int i0 = 0;
        #pragma unroll
        for (int e = 1; e < Ed; e++) if (acc[e] > acc[i0]) i0 = e;
        int i1 = (i0 == 0) ? 1 : 0;
        #pragma unroll
        for (int e = 0; e < Ed; e++) if (e != i0 && acc[e] > acc[i1]) i1 = e;
        float ex = expf(acc[i1] - acc[i0]);
        float g0 = 1.f / (1.f + ex);
        float g1 = ex / (1.f + ex);
        g_eidx[warp * 2] = i0; g_eidx[warp * 2 + 1] = i1;
        g_gate[warp * 2] = g0; g_gate[warp * 2 + 1] = g1;
        atomicAdd(&g_cnt[i0], 1);
        atomicAdd(&g_cnt[i1], 1);
    }
}

__global__ void tiles_k() {
    int off = 0, nt = 0;
    for (int e = 0; e < Ed; e++) {
        g_off[e] = off; g_pos[e] = 0;
        int c = g_cnt[e];
        for (int r = 0; r < c; r += 128) {
            g_tile_e[nt] = e; g_tile_row[nt] = off + r; g_tile_end[nt] = off + c; nt++;
        }
        off += c;
    }
    g_off[Ed] = off;
    g_ntiles = nt;
}

__global__ void assign_k() {
    int t = blockIdx.x * blockDim.x + threadIdx.x;
    if (t >= Td) return;
    #pragma unroll
    for (int kk = 0; kk < 2; kk++) {
        int e = g_eidx[t * 2 + kk];
        int p = atomicAdd(&g_pos[e], 1);
        int slot = g_off[e] + p;
        g_slot_token[slot] = t;
        g_slot_of[t * 2 + kk] = slot;
    }
}

__global__ void final_k(float* __restrict__ out) {
    int idx = blockIdx.x * blockDim.x + threadIdx.x;
    if (idx >= Td * Dd) return;
    int t = idx >> 9, d = idx & 511;
    float r = g_h[idx];
    r += g_gate[t * 2]     * g_yslot[(size_t)g_slot_of[t * 2]     * Dd + d];
    r += g_gate[t * 2 + 1] * g_yslot[(size_t)g_slot_of[t * 2 + 1] * Dd + d];
    out[idx] = r;
}

// ---------------- launch -----------------------------------------------------
extern "C" void kernel_launch(void* const* d_in, const int* in_sizes, int n_in,
                              void* d_out, int out_size) {
    const float* x   = (const float*)d_in[0];
    const float* anw = (const float*)d_in[1];
    const float* wq  = (const float*)d_in[2];
    const float* wk  = (const float*)d_in[3];
    const float* wv  = (const float*)d_in[4];
    const float* wo  = (const float*)d_in[5];
    const float* fnw = (const float*)d_in[6];
    const float* rw  = (const float*)d_in[7];
    const float* w1  = (const float*)d_in[8];
    const float* w2  = (const float*)d_in[9];
    float* out = (float*)d_out;

    float *p_q, *p_k, *p_v, *p_h, *p_hn, *p_yslot;
    __half *p_xnh, *p_xnl, *p_atth, *p_attl, *p_hn16, *p_hidden16;
    __half *p_wqkvh, *p_wqkvl, *p_woh, *p_wol, *p_w1t, *p_w2t;
    cudaGetSymbolAddress((void**)&p_q, g_q);
    cudaGetSymbolAddress((void**)&p_k, g_k);
    cudaGetSymbolAddress((void**)&p_v, g_v);
    cudaGetSymbolAddress((void**)&p_h, g_h);
    cudaGetSymbolAddress((void**)&p_hn, g_hn);
    cudaGetSymbolAddress((void**)&p_xnh, g_xnh);
    cudaGetSymbolAddress((void**)&p_xnl, g_xnl);
    cudaGetSymbolAddress((void**)&p_atth, g_atth);
    cudaGetSymbolAddress((void**)&p_attl, g_attl);
    cudaGetSymbolAddress((void**)&p_hn16, g_hn16);
    cudaGetSymbolAddress((void**)&p_hidden16, g_hidden16);
    cudaGetSymbolAddress((void**)&p_yslot, g_yslot);
    cudaGetSymbolAddress((void**)&p_wqkvh, g_wqkvh);
    cudaGetSymbolAddress((void**)&p_wqkvl, g_wqkvl);
    cudaGetSymbolAddress((void**)&p_woh, g_woh);
    cudaGetSymbolAddress((void**)&p_wol, g_wol);
    cudaGetSymbolAddress((void**)&p_w1t, g_w1t);
    cudaGetSymbolAddress((void**)&p_w2t, g_w2t);

    cudaFuncSetAttribute(sgemm_split<false>,
                         cudaFuncAttributeMaxDynamicSharedMemorySize, SMEM_S);
    cudaFuncSetAttribute(sgemm_split<true>,
                         cudaFuncAttributeMaxDynamicSharedMemorySize, SMEM_S);
    cudaFuncSetAttribute(hgemm_grp2<true, true, true>,
                         cudaFuncAttributeMaxDynamicSharedMemorySize, SMEM_H2);
    cudaFuncSetAttribute(hgemm_grp2<false, false, false>,
                         cudaFuncAttributeMaxDynamicSharedMemorySize, SMEM_H2);

    // 0) weight preprocessing (independent)
    transpose_w16_k<<<dim3(Dd / 32, HFd / 32, Ed), dim3(32, 8)>>>(w1, p_w1t, Dd, HFd);
    transpose_w16_k<<<dim3(HFd / 32, Dd / 32, Ed), dim3(32, 8)>>>(w2, p_w2t, HFd, Dd);
    transpose_whl_k<<<dim3(Dd / 32, Dd / 32), dim3(32, 8)>>>(wq, p_wqkvh, p_wqkvl, Dd, Dd);
    transpose_whl_k<<<dim3(Dd / 32, Dd / 32), dim3(32, 8)>>>(wk, p_wqkvh + Dd * Dd,
                                                             p_wqkvl + Dd * Dd, Dd, Dd);
    transpose_whl_k<<<dim3(Dd / 32, Dd / 32), dim3(32, 8)>>>(wv, p_wqkvh + 2 * Dd * Dd,
                                                             p_wqkvl + 2 * Dd * Dd, Dd, Dd);
    transpose_whl_k<<<dim3(Dd / 32, Dd / 32), dim3(32, 8)>>>(wo, p_woh, p_wol, Dd, Dd);
    // 1) rmsnorm(x) -> hi/lo fp16
    rmsnorm_k<<<Td, 256>>>(x, anw, nullptr, p_xnh, p_xnl);
    // 2) fused QKV split-fp16 GEMM (fp32-accurate)
    sgemm_split<false><<<dim3(Td / 128, Dd / 128, 3), 256, SMEM_S>>>(
        p_xnh, p_xnl, p_wqkvh, p_wqkvl, p_q, p_k, p_v, nullptr, Dd, Dd);
    // 3) RoPE on q,k
    rope_k<<<(Td * 256) / 256, 256>>>(p_q);
    rope_k<<<(Td * 256) / 256, 256>>>(p_k);
    // 4) causal attention (fp32 compute; hi/lo fp16 output)
    attn_k<<<dim3(Bd * Hd, Sd / 64), 256>>>(p_q, p_k, p_v, p_atth, p_attl);
    // 5) O projection + residual (split-fp16, fp32-accurate)
    sgemm_split<true><<<dim3(Td / 128, Dd / 128, 1), 256, SMEM_S>>>(
        p_atth, p_attl, p_woh, p_wol, p_h, nullptr, nullptr, x, Dd, Dd);
    // 6) rmsnorm(h) -> fp32 (router) + fp16 (MoE)
    rmsnorm_k<<<Td, 256>>>(p_h, fnw, p_hn, p_hn16, nullptr);
    // 7) router + expert grouping (fp32 logits)
    zero_cnt_k<<<1, 32>>>();
    router_k<<<Td / 8, 256>>>(p_hn, rw);
    tiles_k<<<1, 1>>>();
    assign_k<<<Td / 256, 256>>>();
    // 8) expert GEMM 1: hidden16 = gelu(hn16 @ w1[e])
    hgemm_grp2<true, true, true><<<dim3(MAXTILES, HFd / 128), 256, SMEM_H2>>>(
        p_hn16, p_w1t, p_hidden16, HFd, Dd);
    // 9) expert GEMM 2: yslot = hidden16 @ w2[e]
    hgemm_grp2<false, false, false><<<dim3(MAXTILES, Dd / 128), 256, SMEM_H2>>>(
        p_hidden16, p_w2t, p_yslot, Dd, HFd);
    // 10) final gather + residual
    final_k<<<(Td * Dd) / 256, 256>>>(out);
}

// round 11
// speedup vs baseline: 3.0256x; 1.4355x over previous
#include <cuda_runtime.h>
#include <cuda_fp16.h>
#include <math.h>
#include <stdint.h>

#define Bd 4
#define Sd 2048
#define Dd 512
#define Hd 8
#define DHd 64
#define Ed 8
#define HFd 2048
#define Td (Bd*Sd)        /* 8192 tokens */
#define NSLOT (2*Td)      /* 16384 expert-slots */
#define MAXTILES 144

// ---------------- scratch (device globals; no allocation allowed) ----------
__device__ float  g_q[Td*Dd];
__device__ float  g_k[Td*Dd];
__device__ float  g_v[Td*Dd];
__device__ float  g_h[Td*Dd];
__device__ float  g_hn[Td*Dd];
__device__ __half g_xnh[Td*Dd];
__device__ __half g_xnl[Td*Dd];
__device__ __half g_atth[Td*Dd];
__device__ __half g_attl[Td*Dd];
__device__ __half g_hn16[Td*Dd];
__device__ __half g_wqkvh[3*Dd*Dd];   /* [z][n][k] hi */
__device__ __half g_wqkvl[3*Dd*Dd];   /* [z][n][k] lo */
__device__ __half g_woh[Dd*Dd];
__device__ __half g_wol[Dd*Dd];
__device__ float  g_gate[Td*2];
__device__ int    g_eidx[Td*2];
__device__ int    g_slot_of[Td*2];
__device__ int    g_slot_token[NSLOT];
__device__ int    g_cnt[Ed];
__device__ int    g_off[Ed+1];
__device__ int    g_pos[Ed];
__device__ int    g_tile_e[MAXTILES];
__device__ int    g_tile_row[MAXTILES];
__device__ int    g_tile_end[MAXTILES];
__device__ int    g_ntiles;
__device__ __half g_hidden16[(size_t)NSLOT*HFd]; /* 64 MB */
__device__ float  g_yslot[(size_t)NSLOT*Dd];     /* 32 MB */
__device__ __half g_w1t[(size_t)Ed*HFd*Dd];      /* 16 MB: [e][n][k] fp16 */
__device__ __half g_w2t[(size_t)Ed*Dd*HFd];      /* 16 MB: [e][n][k] fp16 */

// ---------------- fast exp on the FMA pipe ----------------------------------
__device__ __forceinline__ float fexp(float x) {
    x = fmaxf(x, -80.0f);
    float i = rintf(x * 1.44269504088896341f);
    float r = fmaf(i, -0.693359375f, x);
    r = fmaf(i, 2.12194440e-4f, r);
    float z = r * r;
    float p = 1.9875691500e-4f;
    p = fmaf(p, r, 1.3981999507e-3f);
    p = fmaf(p, r, 8.3334519073e-3f);
    p = fmaf(p, r, 4.1665795894e-2f);
    p = fmaf(p, r, 1.6666665459e-1f);
    p = fmaf(p, r, 5.0000001201e-1f);
    float y = fmaf(z, p, r) + 1.0f;
    int j = __float2int_rn(i);
    float sc2 = __int_as_float((j + 127) << 23);
    return y * sc2;
}

// ---------------- small helpers --------------------------------------------
__device__ __forceinline__ void split2(float a, float b, uint32_t& hi, uint32_t& lo) {
    __half ha = __float2half(a), hb = __float2half(b);
    __half2 h = __halves2half2(ha, hb);
    hi = *(uint32_t*)&h;
    __half2 l = __halves2half2(__float2half(a - __half2float(ha)),
                               __float2half(b - __half2float(hb)));
    lo = *(uint32_t*)&l;
}

// ---------------- rmsnorm (fp32 out nullable; optional hi/lo fp16) ----------
__global__ void rmsnorm_k(const float* __restrict__ in, const float* __restrict__ w,
                          float* __restrict__ out,
                          __half* __restrict__ outh, __half* __restrict__ outl) {
    int t = blockIdx.x;
    int tid = threadIdx.x;
    const float* row = in + (size_t)t * Dd;
    float v0 = row[tid], v1 = row[tid + 256];
    float ss = v0 * v0 + v1 * v1;
    #pragma unroll
    for (int o = 16; o; o >>= 1) ss += __shfl_xor_sync(0xffffffffu, ss, o);
    __shared__ float red[8];
    __shared__ float sc;
    if ((tid & 31) == 0) red[tid >> 5] = ss;
    __syncthreads();
    if (tid == 0) {
        float s = 0.f;
        #pragma unroll
        for (int i = 0; i < 8; i++) s += red[i];
        sc = rsqrtf(s / (float)Dd + 1e-5f);
    }
    __syncthreads();
    float o0 = v0 * sc * w[tid];
    float o1 = v1 * sc * w[tid + 256];
    size_t i0 = (size_t)t * Dd + tid, i1 = i0 + 256;
    if (out) { out[i0] = o0; out[i1] = o1; }
    if (outh) {
        __half h0 = __float2half(o0), h1 = __float2half(o1);
        outh[i0] = h0; outh[i1] = h1;
        if (outl) {
            outl[i0] = __float2half(o0 - __half2float(h0));
            outl[i1] = __float2half(o1 - __half2float(h1));
        }
    }
}

// ------- dense weight transpose: W[K][N] fp32 -> Wh/Wl[N][K] hi/lo fp16 -----
__global__ void transpose_whl_k(const float* __restrict__ W,
                                __half* __restrict__ Wh, __half* __restrict__ Wl,
                                int K, int N) {
    __shared__ float t[32][33];
    int k0 = blockIdx.x * 32, n0 = blockIdx.y * 32;
    int tx = threadIdx.x, ty = threadIdx.y;   // 32 x 8
    #pragma unroll
    for (int i = 0; i < 32; i += 8)
        t[ty + i][tx] = W[(size_t)(k0 + ty + i) * N + n0 + tx];
    __syncthreads();
    #pragma unroll
    for (int i = 0; i < 32; i += 8) {
        float v = t[tx][ty + i];
        __half hi = __float2half(v);
        size_t idx = (size_t)(n0 + ty + i) * K + k0 + tx;
        Wh[idx] = hi;
        Wl[idx] = __float2half(v - __half2float(hi));
    }
}

// ------- expert weight transpose+convert: W[e][K][N] fp32 -> [e][N][K] fp16 -
__global__ void transpose_w16_k(const float* __restrict__ W, __half* __restrict__ Wt,
                                int K, int N) {
    __shared__ float t[32][33];
    int e = blockIdx.z;
    int k0 = blockIdx.x * 32, n0 = blockIdx.y * 32;
    const float* We = W + (size_t)e * K * N;
    __half* Wte = Wt + (size_t)e * K * N;
    int tx = threadIdx.x, ty = threadIdx.y;
    #pragma unroll
    for (int i = 0; i < 32; i += 8)
        t[ty + i][tx] = We[(size_t)(k0 + ty + i) * N + n0 + tx];
    __syncthreads();
    #pragma unroll
    for (int i = 0; i < 32; i += 8)
        Wte[(size_t)(n0 + ty + i) * K + k0 + tx] = __float2half(t[tx][ty + i]);
}

// ---------------- mma helpers -----------------------------------------------
__device__ __forceinline__ void cp16(uint32_t dst, const void* src) {
    asm volatile("cp.async.cg.shared.global [%0], [%1], 16;\n" :: "r"(dst), "l"(src));
}
__device__ __forceinline__ void ldsm4(uint32_t& r0, uint32_t& r1, uint32_t& r2,
                                      uint32_t& r3, uint32_t addr) {
    asm volatile("ldmatrix.sync.aligned.m8n8.x4.shared.b16 {%0,%1,%2,%3}, [%4];"
                 : "=r"(r0), "=r"(r1), "=r"(r2), "=r"(r3) : "r"(addr));
}
__device__ __forceinline__ void ldsm4t(uint32_t& r0, uint32_t& r1, uint32_t& r2,
                                       uint32_t& r3, uint32_t addr) {
    asm volatile("ldmatrix.sync.aligned.m8n8.x4.trans.shared.b16 {%0,%1,%2,%3}, [%4];"
                 : "=r"(r0), "=r"(r1), "=r"(r2), "=r"(r3) : "r"(addr));
}
#define MMA16(ac, a, b0, b1) \
    asm volatile( \
        "mma.sync.aligned.m16n8k16.row.col.f32.f16.f16.f32 " \
        "{%0,%1,%2,%3}, {%4,%5,%6,%7}, {%8,%9}, {%0,%1,%2,%3};\n" \
        : "+f"((ac)[0]), "+f"((ac)[1]), "+f"((ac)[2]), "+f"((ac)[3]) \
        : "r"((a)[0]), "r"((a)[1]), "r"((a)[2]), "r"((a)[3]), "r"(b0), "r"(b1))

// ---------------- split-fp16 dense GEMM (fp32-accurate, tensor cores) -------
#define STB 16384
#define SMEM_S (4*STB)

template<bool RES>
__global__ __launch_bounds__(256, 2)
void sgemm_split(const __half* __restrict__ Ah, const __half* __restrict__ Al,
                 const __half* __restrict__ Wh, const __half* __restrict__ Wl,
                 float* __restrict__ Cq, float* __restrict__ Ck, float* __restrict__ Cv,
                 const float* __restrict__ Res, int N, int K) {
    extern __shared__ char sms[];
    const int z = blockIdx.z;
    const __half* Bh_g = Wh + (size_t)z * N * K;
    const __half* Bl_g = Wl + (size_t)z * N * K;
    float* C = (z == 0) ? Cq : (z == 1) ? Ck : Cv;

    const int m0 = blockIdx.x * 128, n0 = blockIdx.y * 128;
    const int tid = threadIdx.x;
    const int lane = tid & 31, wid = tid >> 5;
    const int wm = wid >> 2, wn = wid & 3;
    const int lr = lane >> 2, lc = lane & 3;
    const uint32_t sb = (uint32_t)__cvta_generic_to_shared(sms);

    const int ldR = tid >> 1;
    const int hsel = tid & 1;
    const __half* aSrc = (hsel ? Al : Ah) + (size_t)(m0 + ldR) * K;
    const __half* bSrc = (hsel ? Bl_g : Bh_g) + (size_t)(n0 + ldR) * K;
    const int ldRm = ldR & 7;
    uint32_t aD[4], bD[4];
    #pragma unroll
    for (int p = 0; p < 4; p++) {
        uint32_t off = ldR * 128 + ((((hsel << 2) + p) ^ ldRm) << 4);
        aD[p] = sb + off;
        bD[p] = sb + 2 * STB + off;
    }

    const int lane7 = lane & 7, lsub = (lane >> 3) & 1, lhi = lane >> 4;
    uint32_t aRowOff[4]; int aMod[4];
    #pragma unroll
    for (int am = 0; am < 4; am++) {
        int r = wm * 64 + am * 16 + lane7 + lsub * 8;
        aRowOff[am] = r * 128; aMod[am] = r & 7;
    }
    uint32_t bRowOff[2]; int bMod[2];
    #pragma unroll
    for (int p = 0; p < 2; p++) {
        int r = wn * 32 + p * 16 + lane7 + lsub * 8;
        bRowOff[p] = r * 128; bMod[p] = r & 7;
    }

    float acc[4][4][4];
    #pragma unroll
    for (int i = 0; i < 4; i++)
        #pragma unroll
        for (int j = 0; j < 4; j++)
            #pragma unroll
            for (int r = 0; r < 4; r++) acc[i][j][r] = 0.f;

    const int nkb = K >> 5;
    #pragma unroll
    for (int p = 0; p < 4; p++) {
        cp16(aD[p], aSrc + p * 8);
        cp16(bD[p], bSrc + p * 8);
    }
    asm volatile("cp.async.commit_group;\n");

    int buf = 0;
    for (int kb = 0; kb < nkb; kb++) {
        if (kb + 1 < nkb) {
            int ko = (kb + 1) * 32;
            #pragma unroll
            for (int p = 0; p < 4; p++) {
                cp16(aD[p] + (buf ^ 1) * STB, aSrc + ko + p * 8);
                cp16(bD[p] + (buf ^ 1) * STB, bSrc + ko + p * 8);
            }
            asm volatile("cp.async.commit_group;\n");
            asm volatile("cp.async.wait_group 1;\n");
        } else {
            asm volatile("cp.async.wait_group 0;\n");
        }
        __syncthreads();

        const uint32_t Ab = sb + buf * STB;
        const uint32_t Bb = sb + 2 * STB + buf * STB;
        #pragma unroll
        for (int ks = 0; ks < 2; ks++) {
            const int segh = (ks << 1) + lhi;
            uint32_t af[4][4], bfh[4][2], bfl[4][2];
            #pragma unroll
            for (int am = 0; am < 4; am++) {
                uint32_t addr = Ab + aRowOff[am] + ((segh ^ aMod[am]) << 4);
                ldsm4(af[am][0], af[am][1], af[am][2], af[am][3], addr);
            }
            #pragma unroll
            for (int p = 0; p < 2; p++) {
                uint32_t r0, r1, r2, r3;
                ldsm4(r0, r1, r2, r3, Bb + bRowOff[p] + ((segh ^ bMod[p]) << 4));
                bfh[2*p][0] = r0; bfh[2*p+1][0] = r1;
                bfh[2*p][1] = r2; bfh[2*p+1][1] = r3;
                ldsm4(r0, r1, r2, r3, Bb + bRowOff[p] + (((segh + 4) ^ bMod[p]) << 4));
                bfl[2*p][0] = r0; bfl[2*p+1][0] = r1;
                bfl[2*p][1] = r2; bfl[2*p+1][1] = r3;
            }
            #pragma unroll
            for (int am = 0; am < 4; am++)
                #pragma unroll
                for (int an = 0; an < 4; an++) {
                    MMA16(acc[am][an], af[am], bfh[an][0], bfh[an][1]);
                    MMA16(acc[am][an], af[am], bfl[an][0], bfl[an][1]);
                }
            #pragma unroll
            for (int am = 0; am < 4; am++) {
                uint32_t addr = Ab + aRowOff[am] + (((segh + 4) ^ aMod[am]) << 4);
                ldsm4(af[am][0], af[am][1], af[am][2], af[am][3], addr);
            }
            #pragma unroll
            for (int am = 0; am < 4; am++)
                #pragma unroll
                for (int an = 0; an < 4; an++)
                    MMA16(acc[am][an], af[am], bfh[an][0], bfh[an][1]);
        }
        __syncthreads();
        buf ^= 1;
    }

    #pragma unroll
    for (int am = 0; am < 4; am++) {
        #pragma unroll
        for (int hrow = 0; hrow < 2; hrow++) {
            int grow = m0 + wm * 64 + am * 16 + hrow * 8 + lr;
            float* crow = C + (size_t)grow * N + n0;
            const float* rrow = RES ? (Res + (size_t)grow * N + n0) : nullptr;
            #pragma unroll
            for (int an = 0; an < 4; an++) {
                int gc = wn * 32 + an * 8 + 2 * lc;
                float v0 = acc[am][an][hrow * 2 + 0];
                float v1 = acc[am][an][hrow * 2 + 1];
                if (RES) { v0 += rrow[gc]; v1 += rrow[gc + 1]; }
                float2 t; t.x = v0; t.y = v1;
                *(float2*)&crow[gc] = t;
            }
        }
    }
}

// ---------------- fp16 tensor-core grouped expert GEMM (ldmatrix) -----------
__device__ __forceinline__ float gelu_f(float x) {
    return 0.5f * x * (1.0f + erff(x * 0.70710678118654752f));
}

#define TB 16384
#define SMEM_H2 (4*TB)

template<bool GATHER, bool GELU, bool OUT16>
__global__ __launch_bounds__(256, 2)
void hgemm_grp2(const __half* __restrict__ Abase, const __half* __restrict__ Wt,
                void* __restrict__ Cout, int N, int K) {
    extern __shared__ char sm8[];
    int bx = blockIdx.x;
    if (bx >= g_ntiles) return;
    const int e = g_tile_e[bx], row0 = g_tile_row[bx], rend = g_tile_end[bx];
    const int n0 = blockIdx.y * 128;

    const int tid = threadIdx.x;
    const int lane = tid & 31, wid = tid >> 5;
    const int wm = wid >> 2, wn = wid & 3;
    const int lr = lane >> 2, lc = lane & 3;
    const uint32_t sb = (uint32_t)__cvta_generic_to_shared(sm8);

    const int ldR = tid >> 1;
    const int segb = (tid & 1) * 4;
    int grow = row0 + ldR;
    int gsafe = grow < rend ? grow : rend - 1;
    int arow = GATHER ? g_slot_token[gsafe] : gsafe;
    const __half* aRow = Abase + (size_t)arow * K + segb * 8;
    const __half* bRow = Wt + ((size_t)e * N + n0 + ldR) * K + segb * 8;
    const int ldRm = ldR & 7;
    uint32_t aD[4], bD[4];
    #pragma unroll
    for (int p = 0; p < 4; p++) {
        uint32_t off = ldR * 128 + (((segb + p) ^ ldRm) << 4);
        aD[p] = sb + off;
        bD[p] = sb + 2 * TB + off;
    }

    const int lane7 = lane & 7, lsub = (lane >> 3) & 1, lhi = lane >> 4;
    uint32_t aRowOff[4]; int aMod[4];
    #pragma unroll
    for (int am = 0; am < 4; am++) {
        int r = wm * 64 + am * 16 + lane7 + lsub * 8;
        aRowOff[am] = r * 128; aMod[am] = r & 7;
    }
    uint32_t bRowOff[2]; int bMod[2];
    #pragma unroll
    for (int p = 0; p < 2; p++) {
        int r = wn * 32 + p * 16 + lane7 + lsub * 8;
        bRowOff[p] = r * 128; bMod[p] = r & 7;
    }

    float acc[4][4][4];
    #pragma unroll
    for (int i = 0; i < 4; i++)
        #pragma unroll
        for (int j = 0; j < 4; j++)
            #pragma unroll
            for (int r = 0; r < 4; r++) acc[i][j][r] = 0.f;

    const int nkb = K >> 6;
    #pragma unroll
    for (int p = 0; p < 4; p++) {
        cp16(aD[p], aRow + p * 8);
        cp16(bD[p], bRow + p * 8);
    }
    asm volatile("cp.async.commit_group;\n");

    int buf = 0;
    for (int kb = 0; kb < nkb; kb++) {
        if (kb + 1 < nkb) {
            int ko = (kb + 1) * 64;
            #pragma unroll
            for (int p = 0; p < 4; p++) {
                cp16(aD[p] + (buf ^ 1) * TB, aRow + ko + p * 8);
                cp16(bD[p] + (buf ^ 1) * TB, bRow + ko + p * 8);
            }
            asm volatile("cp.async.commit_group;\n");
            asm volatile("cp.async.wait_group 1;\n");
        } else {
            asm volatile("cp.async.wait_group 0;\n");
        }
        __syncthreads();

        const uint32_t Ab = sb + buf * TB;
        const uint32_t Bb = sb + 2 * TB + buf * TB;
        #pragma unroll
        for (int ks = 0; ks < 4; ks++) {
            uint32_t af[4][4], bf[4][2];
            #pragma unroll
            for (int am = 0; am < 4; am++) {
                uint32_t addr = Ab + aRowOff[am] + ((((ks << 1) + lhi) ^ aMod[am]) << 4);
                ldsm4(af[am][0], af[am][1], af[am][2], af[am][3], addr);
            }
            #pragma unroll
            for (int p = 0; p < 2; p++) {
                uint32_t addr = Bb + bRowOff[p] + ((((ks << 1) + lhi) ^ bMod[p]) << 4);
                uint32_t r0, r1, r2, r3;
                ldsm4(r0, r1, r2, r3, addr);
                bf[2*p][0] = r0; bf[2*p+1][0] = r1;
                bf[2*p][1] = r2; bf[2*p+1][1] = r3;
            }
            #pragma unroll
            for (int am = 0; am < 4; am++)
                #pragma unroll
                for (int an = 0; an < 4; an++)
                    MMA16(acc[am][an], af[am], bf[an][0], bf[an][1]);
        }
        __syncthreads();
        buf ^= 1;
    }

    #pragma unroll
    for (int am = 0; am < 4; am++) {
        int s0 = row0 + wm * 64 + am * 16 + lr;
        #pragma unroll
        for (int an = 0; an < 4; an++) {
            int gc = n0 + wn * 32 + an * 8 + 2 * lc;
            float v0 = acc[am][an][0], v1 = acc[am][an][1];
            float v2 = acc[am][an][2], v3 = acc[am][an][3];
            if (GELU) {
                v0 = gelu_f(v0); v1 = gelu_f(v1);
                v2 = gelu_f(v2); v3 = gelu_f(v3);
            }
            if (OUT16) {
                __half* Ch = (__half*)Cout;
                if (s0 < rend)
                    *(__half2*)&Ch[(size_t)s0 * N + gc] = __floats2half2_rn(v0, v1);
                if (s0 + 8 < rend)
                    *(__half2*)&Ch[(size_t)(s0 + 8) * N + gc] = __floats2half2_rn(v2, v3);
            } else {
                float* Cf = (float*)Cout;
                if (s0 < rend) {
                    float2 t; t.x = v0; t.y = v1;
                    *(float2*)&Cf[(size_t)s0 * N + gc] = t;
                }
                if (s0 + 8 < rend) {
                    float2 t; t.x = v2; t.y = v3;
                    *(float2*)&Cf[(size_t)(s0 + 8) * N + gc] = t;
                }
            }
        }
    }
}

// ---------------- RoPE ------------------------------------------------------
__global__ void rope_k(float* __restrict__ qk) {
    int gid = blockIdx.x * blockDim.x + threadIdx.x;
    if (gid >= Td * 256) return;
    int t = gid >> 8;
    int within = gid & 255;
    int i = within & 31;
    int s = t & (Sd - 1);
    float freq = expf(-(float)(2 * i) * (9.210340371976184f / 64.f));
    float ang = (float)s * freq;
    float sn, cs;
    sincosf(ang, &sn, &cs);
    size_t base = (size_t)t * Dd + within * 2;
    float x1 = qk[base], x2 = qk[base + 1];
    qk[base]     = x1 * cs - x2 * sn;
    qk[base + 1] = x1 * sn + x2 * cs;
}

// ---------------- split-fp16 tensor-core flash attention --------------------
// Block: 64 q-rows x 1 head; 4 warps, each warp one m16 strip.
// smem: Qh Ql Kh Kl Vh Vl, each 64 rows x 128B (swizzled 16B segs) = 48 KB.
#define SMEM_ATT 49152

__device__ __forceinline__ void fill_tile(char* dsth, char* dstl,
                                          const float* src, int r, int hsel,
                                          float scale) {
    int rm = r & 7;
    #pragma unroll
    for (int i = 0; i < 4; i++) {
        int seg = hsel * 4 + i;
        float4 f0 = *(const float4*)(src + seg * 8);
        float4 f1 = *(const float4*)(src + seg * 8 + 4);
        uint32_t off = r * 128 + ((seg ^ rm) << 4);
        uint4 hi, lo;
        split2(f0.x * scale, f0.y * scale, hi.x, lo.x);
        split2(f0.z * scale, f0.w * scale, hi.y, lo.y);
        split2(f1.x * scale, f1.y * scale, hi.z, lo.z);
        split2(f1.z * scale, f1.w * scale, hi.w, lo.w);
        *(uint4*)(dsth + off) = hi;
        *(uint4*)(dstl + off) = lo;
    }
}

__global__ __launch_bounds__(128)
void attn_mma(const float* __restrict__ q, const float* __restrict__ k,
              const float* __restrict__ v,
              __half* __restrict__ oh, __half* __restrict__ ol) {
    extern __shared__ char sma[];
    char* QHp = sma;             char* QLp = sma + 8192;
    char* KHp = sma + 16384;     char* KLp = sma + 24576;
    char* VHp = sma + 32768;     char* VLp = sma + 40960;
    const uint32_t sb = (uint32_t)__cvta_generic_to_shared(sma);

    const int bh = blockIdx.x, b = bh >> 3, h = bh & 7;
    const int qt = (gridDim.y - 1) - blockIdx.y;   // big tiles first
    const int tid = threadIdx.x, lane = tid & 31, wid = tid >> 5;
    const int lr = lane >> 2, lc = lane & 3;
    const size_t tok0 = (size_t)b * Sd;

    const int ldr = tid >> 1, hsel = tid & 1;

    // Q tile (scaled by 1/sqrt(dh), split hi/lo)
    fill_tile(QHp, QLp, q + (tok0 + qt * 64 + ldr) * Dd + h * DHd, ldr, hsel, 0.125f);

    // fragment addressing (identical pattern to proven GEMMs)
    const int lane7 = lane & 7, lsub = (lane >> 3) & 1, lhi = lane >> 4;
    const int rowA = wid * 16 + lane7 + lsub * 8;
    const uint32_t aOff = rowA * 128; const int aMod = rowA & 7;
    uint32_t xOff[4]; int xMod[4];
    #pragma unroll
    for (int i = 0; i < 4; i++) {
        int rx = i * 16 + lane7 + lsub * 8;
        xOff[i] = rx * 128; xMod[i] = rx & 7;
    }

    float accO[8][4];
    #pragma unroll
    for (int j = 0; j < 8; j++)
        #pragma unroll
        for (int i = 0; i < 4; i++) accO[j][i] = 0.f;
    float mrow[2] = {-1e30f, -1e30f}, lsum[2] = {0.f, 0.f};

    for (int kt = 0; kt <= qt; kt++) {
        __syncthreads();   // prior-iteration frag reads done
        {
            size_t gi = (tok0 + kt * 64 + ldr) * Dd + h * DHd;
            fill_tile(KHp, KLp, k + gi, ldr, hsel, 1.0f);
            fill_tile(VHp, VLp, v + gi, ldr, hsel, 1.0f);
        }
        __syncthreads();

        // ---- S = Q @ K^T (3 split terms) ----
        float accS[8][4];
        #pragma unroll
        for (int j = 0; j < 8; j++)
            #pragma unroll
            for (int i = 0; i < 4; i++) accS[j][i] = 0.f;

        #pragma unroll
        for (int kc = 0; kc < 4; kc++) {
            uint32_t ah[4], al[4];
            uint32_t sega = (uint32_t)(((kc * 2 + lhi) ^ aMod) << 4);
            ldsm4(ah[0], ah[1], ah[2], ah[3], sb + 0 + aOff + sega);
            ldsm4(al[0], al[1], al[2], al[3], sb + 8192 + aOff + sega);
            #pragma unroll
            for (int np = 0; np < 4; np++) {
                uint32_t segb = (uint32_t)(((kc * 2 + lhi) ^ xMod[np]) << 4);
                uint32_t h0, h1, h2, h3, l0, l1, l2, l3;
                ldsm4(h0, h1, h2, h3, sb + 16384 + xOff[np] + segb);
                ldsm4(l0, l1, l2, l3, sb + 24576 + xOff[np] + segb);
                MMA16(accS[2*np],   ah, h0, h2);
                MMA16(accS[2*np],   ah, l0, l2);
                MMA16(accS[2*np],   al, h0, h2);
                MMA16(accS[2*np+1], ah, h1, h3);
                MMA16(accS[2*np+1], ah, l1, l3);
                MMA16(accS[2*np+1], al, h1, h3);
            }
        }

        // ---- causal mask on diagonal tile ----
        if (kt == qt) {
            #pragma unroll
            for (int j = 0; j < 8; j++)
                #pragma unroll
                for (int idx = 0; idx < 4; idx++) {
                    int col = j * 8 + 2 * lc + (idx & 1);
                    int rowl = wid * 16 + lr + (idx >> 1) * 8;
                    if (col > rowl) accS[j][idx] = -1e30f;
                }
        }

        // ---- online softmax (quad shfl; p overwrites accS) ----
        #pragma unroll
        for (int rr = 0; rr < 2; rr++) {
            float tm = -1e30f;
            #pragma unroll
            for (int j = 0; j < 8; j++) {
                tm = fmaxf(tm, accS[j][2*rr]);
                tm = fmaxf(tm, accS[j][2*rr+1]);
            }
            tm = fmaxf(tm, __shfl_xor_sync(0xffffffffu, tm, 1));
            tm = fmaxf(tm, __shfl_xor_sync(0xffffffffu, tm, 2));
            float mn = fmaxf(mrow[rr], tm);
            float alpha = fexp(mrow[rr] - mn);
            float rs = 0.f;
            #pragma unroll
            for (int j = 0; j < 8; j++) {
                float p0 = fexp(accS[j][2*rr]   - mn);
                float p1 = fexp(accS[j][2*rr+1] - mn);
                accS[j][2*rr] = p0; accS[j][2*rr+1] = p1;
                rs += p0 + p1;
            }
            rs += __shfl_xor_sync(0xffffffffu, rs, 1);
            rs += __shfl_xor_sync(0xffffffffu, rs, 2);
            lsum[rr] = lsum[rr] * alpha + rs;
            mrow[rr] = mn;
            #pragma unroll
            for (int j = 0; j < 8; j++) {
                accO[j][2*rr]   *= alpha;
                accO[j][2*rr+1] *= alpha;
            }
        }

        // ---- O += P @ V (P from regs; V via ldmatrix.trans; 3 terms) ----
        #pragma unroll
        for (int kc2 = 0; kc2 < 4; kc2++) {
            uint32_t pah[4], pal[4];
            split2(accS[2*kc2][0],   accS[2*kc2][1],   pah[0], pal[0]);
            split2(accS[2*kc2][2],   accS[2*kc2][3],   pah[1], pal[1]);
            split2(accS[2*kc2+1][0], accS[2*kc2+1][1], pah[2], pal[2]);
            split2(accS[2*kc2+1][2], accS[2*kc2+1][3], pah[3], pal[3]);
            #pragma unroll
            for (int dp = 0; dp < 4; dp++) {
                uint32_t segv = (uint32_t)(((dp * 2 + lhi) ^ xMod[kc2]) << 4);
                uint32_t h0, h1, h2, h3, l0, l1, l2, l3;
                ldsm4t(h0, h1, h2, h3, sb + 32768 + xOff[kc2] + segv);
                ldsm4t(l0, l1, l2, l3, sb + 40960 + xOff[kc2] + segv);
                MMA16(accO[2*dp],   pah, h0, h1);
                MMA16(accO[2*dp],   pah, l0, l1);
                MMA16(accO[2*dp],   pal, h0, h1);
                MMA16(accO[2*dp+1], pah, h2, h3);
                MMA16(accO[2*dp+1], pah, l2, l3);
                MMA16(accO[2*dp+1], pal, h2, h3);
            }
        }
    }

    // ---- epilogue: O / lsum -> hi/lo fp16 ----
    #pragma unroll
    for (int rr = 0; rr < 2; rr++) {
        float inv = 1.0f / lsum[rr];
        size_t base = (tok0 + qt * 64 + wid * 16 + lr + rr * 8) * Dd + h * DHd;
        #pragma unroll
        for (int j = 0; j < 8; j++) {
            float v0 = accO[j][2*rr] * inv, v1 = accO[j][2*rr+1] * inv;
            uint32_t hi, lo;
            split2(v0, v1, hi, lo);
            *(uint32_t*)&oh[base + j * 8 + 2 * lc] = hi;
            *(uint32_t*)&ol[base + j * 8 + 2 * lc] = lo;
        }
    }
}

// ---------------- router / scatter -----------------------------------------
__global__ void zero_cnt_k() { if (threadIdx.x < Ed) g_cnt[threadIdx.x] = 0; }

__global__ void router_k(const float* __restrict__ hn, const float* __restrict__ rw) {
    int warp = (blockIdx.x * blockDim.x + threadIdx.x) >> 5;
    int lane = threadIdx.x & 31;
    if (warp >= Td) return;
    const float* row = hn + (size_t)warp * Dd;
    float acc[Ed];
    #pragma unroll
    for (int e = 0; e < Ed; e++) acc[e] = 0.f;
    for (int d = lane; d < Dd; d += 32) {
        float x = row[d];
        #pragma unroll
        for (int e = 0; e < Ed; e++) acc[e] += x * rw[d * Ed + e];
    }
    #pragma unroll
    for (int e = 0; e < Ed; e++)
        #pragma unroll
        for (int o = 16; o; o >>= 1)
            acc[e] += __shfl_xor_sync(0xffffffffu, acc[e], o);
    if (lane == 0) {
        int i0 = 0;
        #pragma unroll
        for (int e = 1; e < Ed; e++) if (acc[e] > acc[i0]) i0 = e;
        int i1 = (i0 == 0) ? 1 : 0;
        #pragma unroll
        for (int e = 0; e < Ed; e++) if (e != i0 && acc[e] > acc[i1]) i1 = e;
        float ex = expf(acc[i1] - acc[i0]);
        float g0 = 1.f / (1.f + ex);
        float g1 = ex / (1.f + ex);
        g_eidx[warp * 2] = i0; g_eidx[warp * 2 + 1] = i1;
        g_gate[warp * 2] = g0; g_gate[warp * 2 + 1] = g1;
        atomicAdd(&g_cnt[i0], 1);
        atomicAdd(&g_cnt[i1], 1);
    }
}

__global__ void tiles_k() {
    int off = 0, nt = 0;
    for (int e = 0; e < Ed; e++) {
        g_off[e] = off; g_pos[e] = 0;
        int c = g_cnt[e];
        for (int r = 0; r < c; r += 128) {
            g_tile_e[nt] = e; g_tile_row[nt] = off + r; g_tile_end[nt] = off + c; nt++;
        }
        off += c;
    }
    g_off[Ed] = off;
    g_ntiles = nt;
}

__global__ void assign_k() {
    int t = blockIdx.x * blockDim.x + threadIdx.x;
    if (t >= Td) return;
    #pragma unroll
    for (int kk = 0; kk < 2; kk++) {
        int e = g_eidx[t * 2 + kk];
        int p = atomicAdd(&g_pos[e], 1);
        int slot = g_off[e] + p;
        g_slot_token[slot] = t;
        g_slot_of[t * 2 + kk] = slot;
    }
}

__global__ void final_k(float* __restrict__ out) {
    int idx = blockIdx.x * blockDim.x + threadIdx.x;
    if (idx >= Td * Dd) return;
    int t = idx >> 9, d = idx & 511;
    float r = g_h[idx];
    r += g_gate[t * 2]     * g_yslot[(size_t)g_slot_of[t * 2]     * Dd + d];
    r += g_gate[t * 2 + 1] * g_yslot[(size_t)g_slot_of[t * 2 + 1] * Dd + d];
    out[idx] = r;
}

// ---------------- launch -----------------------------------------------------
extern "C" void kernel_launch(void* const* d_in, const int* in_sizes, int n_in,
                              void* d_out, int out_size) {
    const float* x   = (const float*)d_in[0];
    const float* anw = (const float*)d_in[1];
    const float* wq  = (const float*)d_in[2];
    const float* wk  = (const float*)d_in[3];
    const float* wv  = (const float*)d_in[4];
    const float* wo  = (const float*)d_in[5];
    const float* fnw = (const float*)d_in[6];
    const float* rw  = (const float*)d_in[7];
    const float* w1  = (const float*)d_in[8];
    const float* w2  = (const float*)d_in[9];
    float* out = (float*)d_out;

    float *p_q, *p_k, *p_v, *p_h, *p_hn, *p_yslot;
    __half *p_xnh, *p_xnl, *p_atth, *p_attl, *p_hn16, *p_hidden16;
    __half *p_wqkvh, *p_wqkvl, *p_woh, *p_wol, *p_w1t, *p_w2t;
    cudaGetSymbolAddress((void**)&p_q, g_q);
    cudaGetSymbolAddress((void**)&p_k, g_k);
    cudaGetSymbolAddress((void**)&p_v, g_v);
    cudaGetSymbolAddress((void**)&p_h, g_h);
    cudaGetSymbolAddress((void**)&p_hn, g_hn);
    cudaGetSymbolAddress((void**)&p_xnh, g_xnh);
    cudaGetSymbolAddress((void**)&p_xnl, g_xnl);
    cudaGetSymbolAddress((void**)&p_atth, g_atth);
    cudaGetSymbolAddress((void**)&p_attl, g_attl);
    cudaGetSymbolAddress((void**)&p_hn16, g_hn16);
    cudaGetSymbolAddress((void**)&p_hidden16, g_hidden16);
    cudaGetSymbolAddress((void**)&p_yslot, g_yslot);
    cudaGetSymbolAddress((void**)&p_wqkvh, g_wqkvh);
    cudaGetSymbolAddress((void**)&p_wqkvl, g_wqkvl);
    cudaGetSymbolAddress((void**)&p_woh, g_woh);
    cudaGetSymbolAddress((void**)&p_wol, g_wol);
    cudaGetSymbolAddress((void**)&p_w1t, g_w1t);
    cudaGetSymbolAddress((void**)&p_w2t, g_w2t);

    cudaFuncSetAttribute(sgemm_split<false>,
                         cudaFuncAttributeMaxDynamicSharedMemorySize, SMEM_S);
    cudaFuncSetAttribute(sgemm_split<true>,
                         cudaFuncAttributeMaxDynamicSharedMemorySize, SMEM_S);
    cudaFuncSetAttribute(hgemm_grp2<true, true, true>,
                         cudaFuncAttributeMaxDynamicSharedMemorySize, SMEM_H2);
    cudaFuncSetAttribute(hgemm_grp2<false, false, false>,
                         cudaFuncAttributeMaxDynamicSharedMemorySize, SMEM_H2);
    cudaFuncSetAttribute(attn_mma,
                         cudaFuncAttributeMaxDynamicSharedMemorySize, SMEM_ATT);

    // 0) weight preprocessing (independent)
    transpose_w16_k<<<dim3(Dd / 32, HFd / 32, Ed), dim3(32, 8)>>>(w1, p_w1t, Dd, HFd);
    transpose_w16_k<<<dim3(HFd / 32, Dd / 32, Ed), dim3(32, 8)>>>(w2, p_w2t, HFd, Dd);
    transpose_whl_k<<<dim3(Dd / 32, Dd / 32), dim3(32, 8)>>>(wq, p_wqkvh, p_wqkvl, Dd, Dd);
    transpose_whl_k<<<dim3(Dd / 32, Dd / 32), dim3(32, 8)>>>(wk, p_wqkvh + Dd * Dd,
                                                             p_wqkvl + Dd * Dd, Dd, Dd);
    transpose_whl_k<<<dim3(Dd / 32, Dd / 32), dim3(32, 8)>>>(wv, p_wqkvh + 2 * Dd * Dd,
                                                             p_wqkvl + 2 * Dd * Dd, Dd, Dd);
    transpose_whl_k<<<dim3(Dd / 32, Dd / 32), dim3(32, 8)>>>(wo, p_woh, p_wol, Dd, Dd);
    // 1) rmsnorm(x) -> hi/lo fp16
    rmsnorm_k<<<Td, 256>>>(x, anw, nullptr, p_xnh, p_xnl);
    // 2) fused QKV split-fp16 GEMM (fp32-accurate)
    sgemm_split<false><<<dim3(Td / 128, Dd / 128, 3), 256, SMEM_S>>>(
        p_xnh, p_xnl, p_wqkvh, p_wqkvl, p_q, p_k, p_v, nullptr, Dd, Dd);
    // 3) RoPE on q,k
    rope_k<<<(Td * 256) / 256, 256>>>(p_q);
    rope_k<<<(Td * 256) / 256, 256>>>(p_k);
    // 4) causal attention (split-fp16 tensor cores; hi/lo fp16 output)
    attn_mma<<<dim3(Bd * Hd, Sd / 64), 128, SMEM_ATT>>>(p_q, p_k, p_v, p_atth, p_attl);
    // 5) O projection + residual (split-fp16, fp32-accurate)
    sgemm_split<true><<<dim3(Td / 128, Dd / 128, 1), 256, SMEM_S>>>(
        p_atth, p_attl, p_woh, p_wol, p_h, nullptr, nullptr, x, Dd, Dd);
    // 6) rmsnorm(h) -> fp32 (router) + fp16 (MoE)
    rmsnorm_k<<<Td, 256>>>(p_h, fnw, p_hn, p_hn16, nullptr);
    // 7) router + expert grouping (fp32 logits)
    zero_cnt_k<<<1, 32>>>();
    router_k<<<Td / 8, 256>>>(p_hn, rw);
    tiles_k<<<1, 1>>>();
    assign_k<<<Td / 256, 256>>>();
    // 8) expert GEMM 1: hidden16 = gelu(hn16 @ w1[e])
    hgemm_grp2<true, true, true><<<dim3(MAXTILES, HFd / 128), 256, SMEM_H2>>>(
        p_hn16, p_w1t, p_hidden16, HFd, Dd);
    // 9) expert GEMM 2: yslot = hidden16 @ w2[e]
    hgemm_grp2<false, false, false><<<dim3(MAXTILES, Dd / 128), 256, SMEM_H2>>>(
        p_hidden16, p_w2t, p_yslot, Dd, HFd);
    // 10) final gather + residual
    final_k<<<(Td * Dd) / 256, 256>>>(out);
}

// round 12
// speedup vs baseline: 3.2488x; 1.0738x over previous
#include <cuda_runtime.h>
#include <cuda_fp16.h>
#include <math.h>
#include <stdint.h>

#define Bd 4
#define Sd 2048
#define Dd 512
#define Hd 8
#define DHd 64
#define Ed 8
#define HFd 2048
#define Td (Bd*Sd)        /* 8192 tokens */
#define NSLOT (2*Td)      /* 16384 expert-slots */
#define MAXTILES 144

// ---------------- scratch (device globals; no allocation allowed) ----------
__device__ float  g_h[Td*Dd];
__device__ float  g_hn[Td*Dd];
__device__ __half g_xnh[Td*Dd];
__device__ __half g_xnl[Td*Dd];
__device__ __half g_qh[Td*Dd];
__device__ __half g_ql[Td*Dd];
__device__ __half g_kh[Td*Dd];
__device__ __half g_kl[Td*Dd];
__device__ __half g_vh[Td*Dd];
__device__ __half g_vl[Td*Dd];
__device__ __half g_atth[Td*Dd];
__device__ __half g_attl[Td*Dd];
__device__ __half g_hn16[Td*Dd];
__device__ __half g_wqkvh[3*Dd*Dd];   /* [z][n][k] hi */
__device__ __half g_wqkvl[3*Dd*Dd];   /* [z][n][k] lo */
__device__ __half g_woh[Dd*Dd];
__device__ __half g_wol[Dd*Dd];
__device__ float  g_gate[Td*2];
__device__ int    g_eidx[Td*2];
__device__ int    g_slot_of[Td*2];
__device__ int    g_slot_token[NSLOT];
__device__ int    g_cnt[Ed];
__device__ int    g_off[Ed+1];
__device__ int    g_pos[Ed];
__device__ int    g_tile_e[MAXTILES];
__device__ int    g_tile_row[MAXTILES];
__device__ int    g_tile_end[MAXTILES];
__device__ int    g_ntiles;
__device__ __half g_hidden16[(size_t)NSLOT*HFd]; /* 64 MB */
__device__ float  g_yslot[(size_t)NSLOT*Dd];     /* 32 MB */
__device__ __half g_w1c[(size_t)Ed*Dd*HFd];      /* 16 MB: [e][k][n] fp16 (natural) */
__device__ __half g_w2c[(size_t)Ed*HFd*Dd];      /* 16 MB: [e][k][n] fp16 (natural) */

// ---------------- fast exp on the FMA pipe ----------------------------------
__device__ __forceinline__ float fexp(float x) {
    x = fmaxf(x, -80.0f);
    float i = rintf(x * 1.44269504088896341f);
    float r = fmaf(i, -0.693359375f, x);
    r = fmaf(i, 2.12194440e-4f, r);
    float z = r * r;
    float p = 1.9875691500e-4f;
    p = fmaf(p, r, 1.3981999507e-3f);
    p = fmaf(p, r, 8.3334519073e-3f);
    p = fmaf(p, r, 4.1665795894e-2f);
    p = fmaf(p, r, 1.6666665459e-1f);
    p = fmaf(p, r, 5.0000001201e-1f);
    float y = fmaf(z, p, r) + 1.0f;
    int j = __float2int_rn(i);
    float sc2 = __int_as_float((j + 127) << 23);
    return y * sc2;
}

// ---------------- small helpers --------------------------------------------
__device__ __forceinline__ void split2(float a, float b, uint32_t& hi, uint32_t& lo) {
    __half ha = __float2half(a), hb = __float2half(b);
    __half2 h = __halves2half2(ha, hb);
    hi = *(uint32_t*)&h;
    __half2 l = __halves2half2(__float2half(a - __half2float(ha)),
                               __float2half(b - __half2float(hb)));
    lo = *(uint32_t*)&l;
}

// ---------------- rmsnorm (fp32 out nullable; optional hi/lo fp16) ----------
__global__ void rmsnorm_k(const float* __restrict__ in, const float* __restrict__ w,
                          float* __restrict__ out,
                          __half* __restrict__ outh, __half* __restrict__ outl) {
    int t = blockIdx.x;
    int tid = threadIdx.x;
    const float* row = in + (size_t)t * Dd;
    float v0 = row[tid], v1 = row[tid + 256];
    float ss = v0 * v0 + v1 * v1;
    #pragma unroll
    for (int o = 16; o; o >>= 1) ss += __shfl_xor_sync(0xffffffffu, ss, o);
    __shared__ float red[8];
    __shared__ float sc;
    if ((tid & 31) == 0) red[tid >> 5] = ss;
    __syncthreads();
    if (tid == 0) {
        float s = 0.f;
        #pragma unroll
        for (int i = 0; i < 8; i++) s += red[i];
        sc = rsqrtf(s / (float)Dd + 1e-5f);
    }
    __syncthreads();
    float o0 = v0 * sc * w[tid];
    float o1 = v1 * sc * w[tid + 256];
    size_t i0 = (size_t)t * Dd + tid, i1 = i0 + 256;
    if (out) { out[i0] = o0; out[i1] = o1; }
    if (outh) {
        __half h0 = __float2half(o0), h1 = __float2half(o1);
        outh[i0] = h0; outh[i1] = h1;
        if (outl) {
            outl[i0] = __float2half(o0 - __half2float(h0));
            outl[i1] = __float2half(o1 - __half2float(h1));
        }
    }
}

// ------- dense weight transpose: W[K][N] fp32 -> Wh/Wl[N][K] hi/lo fp16 -----
__global__ void transpose_whl_k(const float* __restrict__ W,
                                __half* __restrict__ Wh, __half* __restrict__ Wl,
                                int K, int N) {
    __shared__ float t[32][33];
    int k0 = blockIdx.x * 32, n0 = blockIdx.y * 32;
    int tx = threadIdx.x, ty = threadIdx.y;   // 32 x 8
    #pragma unroll
    for (int i = 0; i < 32; i += 8)
        t[ty + i][tx] = W[(size_t)(k0 + ty + i) * N + n0 + tx];
    __syncthreads();
    #pragma unroll
    for (int i = 0; i < 32; i += 8) {
        float v = t[tx][ty + i];
        __half hi = __float2half(v);
        size_t idx = (size_t)(n0 + ty + i) * K + k0 + tx;
        Wh[idx] = hi;
        Wl[idx] = __float2half(v - __half2float(hi));
    }
}

// ------- expert weight convert (no transpose): fp32 -> fp16, coalesced ------
__global__ void convert16_k(const float* __restrict__ W, __half* __restrict__ O,
                            int n4) {
    int i = blockIdx.x * blockDim.x + threadIdx.x;
    if (i >= n4) return;
    float4 f = ((const float4*)W)[i];
    __half2 a = __floats2half2_rn(f.x, f.y);
    __half2 b2 = __floats2half2_rn(f.z, f.w);
    uint2 u; u.x = *(uint32_t*)&a; u.y = *(uint32_t*)&b2;
    ((uint2*)O)[i] = u;
}

// ---------------- mma helpers -----------------------------------------------
__device__ __forceinline__ void cp16(uint32_t dst, const void* src) {
    asm volatile("cp.async.cg.shared.global [%0], [%1], 16;\n" :: "r"(dst), "l"(src));
}
__device__ __forceinline__ void ldsm4(uint32_t& r0, uint32_t& r1, uint32_t& r2,
                                      uint32_t& r3, uint32_t addr) {
    asm volatile("ldmatrix.sync.aligned.m8n8.x4.shared.b16 {%0,%1,%2,%3}, [%4];"
                 : "=r"(r0), "=r"(r1), "=r"(r2), "=r"(r3) : "r"(addr));
}
__device__ __forceinline__ void ldsm4t(uint32_t& r0, uint32_t& r1, uint32_t& r2,
                                       uint32_t& r3, uint32_t addr) {
    asm volatile("ldmatrix.sync.aligned.m8n8.x4.trans.shared.b16 {%0,%1,%2,%3}, [%4];"
                 : "=r"(r0), "=r"(r1), "=r"(r2), "=r"(r3) : "r"(addr));
}
#define MMA16(ac, a, b0, b1) \
    asm volatile( \
        "mma.sync.aligned.m16n8k16.row.col.f32.f16.f16.f32 " \
        "{%0,%1,%2,%3}, {%4,%5,%6,%7}, {%8,%9}, {%0,%1,%2,%3};\n" \
        : "+f"((ac)[0]), "+f"((ac)[1]), "+f"((ac)[2]), "+f"((ac)[3]) \
        : "r"((a)[0]), "r"((a)[1]), "r"((a)[2]), "r"((a)[3]), "r"(b0), "r"(b1))

// ---------------- split-fp16 dense GEMM (fp32-accurate, tensor cores) -------
// MODE 0: QKV — fused RoPE (z<2) + q-scale (z==0), hi/lo fp16 outputs
// MODE 1: O-proj — fp32 out + residual
#define STB 16384
#define SMEM_S (4*STB)

template<int MODE>
__global__ __launch_bounds__(256, 2)
void sgemm_split(const __half* __restrict__ Ah, const __half* __restrict__ Al,
                 const __half* __restrict__ Wh, const __half* __restrict__ Wl,
                 __half* __restrict__ o0h, __half* __restrict__ o0l,
                 __half* __restrict__ o1h, __half* __restrict__ o1l,
                 __half* __restrict__ o2h, __half* __restrict__ o2l,
                 float* __restrict__ C, const float* __restrict__ Res,
                 int N, int K) {
    extern __shared__ char sms[];
    const int z = blockIdx.z;
    const __half* Bh_g = Wh + (size_t)z * N * K;
    const __half* Bl_g = Wl + (size_t)z * N * K;

    const int m0 = blockIdx.x * 128, n0 = blockIdx.y * 128;
    const int tid = threadIdx.x;
    const int lane = tid & 31, wid = tid >> 5;
    const int wm = wid >> 2, wn = wid & 3;
    const int lr = lane >> 2, lc = lane & 3;
    const uint32_t sb = (uint32_t)__cvta_generic_to_shared(sms);

    const int ldR = tid >> 1;
    const int hsel = tid & 1;
    const __half* aSrc = (hsel ? Al : Ah) + (size_t)(m0 + ldR) * K;
    const __half* bSrc = (hsel ? Bl_g : Bh_g) + (size_t)(n0 + ldR) * K;
    const int ldRm = ldR & 7;
    uint32_t aD[4], bD[4];
    #pragma unroll
    for (int p = 0; p < 4; p++) {
        uint32_t off = ldR * 128 + ((((hsel << 2) + p) ^ ldRm) << 4);
        aD[p] = sb + off;
        bD[p] = sb + 2 * STB + off;
    }

    const int lane7 = lane & 7, lsub = (lane >> 3) & 1, lhi = lane >> 4;
    uint32_t aRowOff[4]; int aMod[4];
    #pragma unroll
    for (int am = 0; am < 4; am++) {
        int r = wm * 64 + am * 16 + lane7 + lsub * 8;
        aRowOff[am] = r * 128; aMod[am] = r & 7;
    }
    uint32_t bRowOff[2]; int bMod[2];
    #pragma unroll
    for (int p = 0; p < 2; p++) {
        int r = wn * 32 + p * 16 + lane7 + lsub * 8;
        bRowOff[p] = r * 128; bMod[p] = r & 7;
    }

    float acc[4][4][4];
    #pragma unroll
    for (int i = 0; i < 4; i++)
        #pragma unroll
        for (int j = 0; j < 4; j++)
            #pragma unroll
            for (int r = 0; r < 4; r++) acc[i][j][r] = 0.f;

    const int nkb = K >> 5;
    #pragma unroll
    for (int p = 0; p < 4; p++) {
        cp16(aD[p], aSrc + p * 8);
        cp16(bD[p], bSrc + p * 8);
    }
    asm volatile("cp.async.commit_group;\n");

    int buf = 0;
    for (int kb = 0; kb < nkb; kb++) {
        if (kb + 1 < nkb) {
            int ko = (kb + 1) * 32;
            #pragma unroll
            for (int p = 0; p < 4; p++) {
                cp16(aD[p] + (buf ^ 1) * STB, aSrc + ko + p * 8);
                cp16(bD[p] + (buf ^ 1) * STB, bSrc + ko + p * 8);
            }
            asm volatile("cp.async.commit_group;\n");
            asm volatile("cp.async.wait_group 1;\n");
        } else {
            asm volatile("cp.async.wait_group 0;\n");
        }
        __syncthreads();

        const uint32_t Ab = sb + buf * STB;
        const uint32_t Bb = sb + 2 * STB + buf * STB;
        #pragma unroll
        for (int ks = 0; ks < 2; ks++) {
            const int segh = (ks << 1) + lhi;
            uint32_t af[4][4], bfh[4][2], bfl[4][2];
            #pragma unroll
            for (int am = 0; am < 4; am++) {
                uint32_t addr = Ab + aRowOff[am] + ((segh ^ aMod[am]) << 4);
                ldsm4(af[am][0], af[am][1], af[am][2], af[am][3], addr);
            }
            #pragma unroll
            for (int p = 0; p < 2; p++) {
                uint32_t r0, r1, r2, r3;
                ldsm4(r0, r1, r2, r3, Bb + bRowOff[p] + ((segh ^ bMod[p]) << 4));
                bfh[2*p][0] = r0; bfh[2*p+1][0] = r1;
                bfh[2*p][1] = r2; bfh[2*p+1][1] = r3;
                ldsm4(r0, r1, r2, r3, Bb + bRowOff[p] + (((segh + 4) ^ bMod[p]) << 4));
                bfl[2*p][0] = r0; bfl[2*p+1][0] = r1;
                bfl[2*p][1] = r2; bfl[2*p+1][1] = r3;
            }
            #pragma unroll
            for (int am = 0; am < 4; am++)
                #pragma unroll
                for (int an = 0; an < 4; an++) {
                    MMA16(acc[am][an], af[am], bfh[an][0], bfh[an][1]);
                    MMA16(acc[am][an], af[am], bfl[an][0], bfl[an][1]);
                }
            #pragma unroll
            for (int am = 0; am < 4; am++) {
                uint32_t addr = Ab + aRowOff[am] + (((segh + 4) ^ aMod[am]) << 4);
                ldsm4(af[am][0], af[am][1], af[am][2], af[am][3], addr);
            }
            #pragma unroll
            for (int am = 0; am < 4; am++)
                #pragma unroll
                for (int an = 0; an < 4; an++)
                    MMA16(acc[am][an], af[am], bfh[an][0], bfh[an][1]);
        }
        __syncthreads();
        buf ^= 1;
    }

    // ---- epilogue ----
    if (MODE == 0) {
        __half* Oh = (z == 0) ? o0h : (z == 1) ? o1h : o2h;
        __half* Ol = (z == 0) ? o0l : (z == 1) ? o1l : o2l;
        #pragma unroll
        for (int am = 0; am < 4; am++) {
            #pragma unroll
            for (int hrow = 0; hrow < 2; hrow++) {
                int grow = m0 + wm * 64 + am * 16 + hrow * 8 + lr;
                int s = grow & (Sd - 1);
                #pragma unroll
                for (int an = 0; an < 4; an++) {
                    int gc = wn * 32 + an * 8 + 2 * lc;
                    int gcg = n0 + gc;
                    float v0 = acc[am][an][hrow * 2 + 0];
                    float v1 = acc[am][an][hrow * 2 + 1];
                    if (z < 2) {
                        int i = (gcg & 63) >> 1;
                        float freq = exp2f(-(float)i * 0.41524101185467246f);
                        float sn, cs;
                        sincosf((float)s * freq, &sn, &cs);
                        float r0 = v0 * cs - v1 * sn;
                        float r1 = v0 * sn + v1 * cs;
                        if (z == 0) { r0 *= 0.125f; r1 *= 0.125f; }
                        v0 = r0; v1 = r1;
                    }
                    uint32_t hi, lo;
                    split2(v0, v1, hi, lo);
                    *(uint32_t*)&Oh[(size_t)grow * N + gcg] = hi;
                    *(uint32_t*)&Ol[(size_t)grow * N + gcg] = lo;
                }
            }
        }
    } else {
        #pragma unroll
        for (int am = 0; am < 4; am++) {
            #pragma unroll
            for (int hrow = 0; hrow < 2; hrow++) {
                int grow = m0 + wm * 64 + am * 16 + hrow * 8 + lr;
                float* crow = C + (size_t)grow * N + n0;
                const float* rrow = Res + (size_t)grow * N + n0;
                #pragma unroll
                for (int an = 0; an < 4; an++) {
                    int gc = wn * 32 + an * 8 + 2 * lc;
                    float v0 = acc[am][an][hrow * 2 + 0] + rrow[gc];
                    float v1 = acc[am][an][hrow * 2 + 1] + rrow[gc + 1];
                    float2 t; t.x = v0; t.y = v1;
                    *(float2*)&crow[gc] = t;
                }
            }
        }
    }
}

// ---------------- fp16 grouped expert GEMM (trans-B from natural [k][n]) ----
__device__ __forceinline__ float gelu_f(float x) {
    return 0.5f * x * (1.0f + erff(x * 0.70710678118654752f));
}

#define TB 16384
#define SMEM_H2 (4*TB)

template<bool GATHER, bool GELU, bool OUT16>
__global__ __launch_bounds__(256, 2)
void hgemm_grp2(const __half* __restrict__ Abase, const __half* __restrict__ Wc,
                void* __restrict__ Cout, int N, int K) {
    extern __shared__ char sm8[];
    int bx = blockIdx.x;
    if (bx >= g_ntiles) return;
    const int e = g_tile_e[bx], row0 = g_tile_row[bx], rend = g_tile_end[bx];
    const int n0 = blockIdx.y * 128;

    const int tid = threadIdx.x;
    const int lane = tid & 31, wid = tid >> 5;
    const int wm = wid >> 2, wn = wid & 3;
    const int lr = lane >> 2, lc = lane & 3;
    const uint32_t sb = (uint32_t)__cvta_generic_to_shared(sm8);

    // ---- A loader: 128 m-rows x 64 k-halves (unchanged, K-major A) ----
    const int ldR = tid >> 1;
    const int segb = (tid & 1) * 4;
    int grow = row0 + ldR;
    int gsafe = grow < rend ? grow : rend - 1;
    int arow = GATHER ? g_slot_token[gsafe] : gsafe;
    const __half* aRow = Abase + (size_t)arow * K + segb * 8;
    const int ldRm = ldR & 7;
    uint32_t aD[4];
    #pragma unroll
    for (int p = 0; p < 4; p++)
        aD[p] = sb + ldR * 128 + (((segb + p) ^ ldRm) << 4);

    // ---- B loader: 64 k-rows x 128 n-halves from natural [k][n]; two 64x64
    // sub-tiles (128B rows) stacked in smem ----
    const int bkr = tid >> 2;               // k-row 0..63
    const int bsegb = (tid & 3) * 4;        // seg 0..15 base
    const __half* bRow = Wc + (size_t)e * K * N + (size_t)bkr * N + n0;
    const int bkrm = bkr & 7;
    uint32_t bD[4];
    #pragma unroll
    for (int p = 0; p < 4; p++) {
        int s = bsegb + p;
        bD[p] = sb + 2 * TB + (s >> 3) * 8192 + bkr * 128 + (((s & 7) ^ bkrm) << 4);
    }

    const int lane7 = lane & 7, lsub = (lane >> 3) & 1, lhi = lane >> 4;
    uint32_t aRowOff[4]; int aMod[4];
    #pragma unroll
    for (int am = 0; am < 4; am++) {
        int r = wm * 64 + am * 16 + lane7 + lsub * 8;
        aRowOff[am] = r * 128; aMod[am] = r & 7;
    }
    uint32_t kRowOff[4]; int kMod[4];
    #pragma unroll
    for (int ks = 0; ks < 4; ks++) {
        int r = ks * 16 + lane7 + lsub * 8;
        kRowOff[ks] = r * 128; kMod[ks] = r & 7;
    }
    const uint32_t btile = (uint32_t)(wn >> 1) * 8192;
    const int segB0 = (wn & 1) * 4;

    float acc[4][4][4];
    #pragma unroll
    for (int i = 0; i < 4; i++)
        #pragma unroll
        for (int j = 0; j < 4; j++)
            #pragma unroll
            for (int r = 0; r < 4; r++) acc[i][j][r] = 0.f;

    const int nkb = K >> 6;
    #pragma unroll
    for (int p = 0; p < 4; p++) {
        cp16(aD[p], aRow + p * 8);
        cp16(bD[p], bRow + (bsegb + p) * 8);
    }
    asm volatile("cp.async.commit_group;\n");

    int buf = 0;
    for (int kb = 0; kb < nkb; kb++) {
        if (kb + 1 < nkb) {
            int ko = (kb + 1) * 64;
            #pragma unroll
            for (int p = 0; p < 4; p++) {
                cp16(aD[p] + (buf ^ 1) * TB, aRow + ko + p * 8);
                cp16(bD[p] + (buf ^ 1) * TB, bRow + (size_t)ko * N + (bsegb + p) * 8);
            }
            asm volatile("cp.async.commit_group;\n");
            asm volatile("cp.async.wait_group 1;\n");
        } else {
            asm volatile("cp.async.wait_group 0;\n");
        }
        __syncthreads();

        const uint32_t Ab = sb + buf * TB;
        const uint32_t Bb = sb + 2 * TB + buf * TB;
        #pragma unroll
        for (int ks = 0; ks < 4; ks++) {
            uint32_t af[4][4], bf[4][2];
            #pragma unroll
            for (int am = 0; am < 4; am++) {
                uint32_t addr = Ab + aRowOff[am] + ((((ks << 1) + lhi) ^ aMod[am]) << 4);
                ldsm4(af[am][0], af[am][1], af[am][2], af[am][3], addr);
            }
            #pragma unroll
            for (int anp = 0; anp < 2; anp++) {
                uint32_t addr = Bb + btile + kRowOff[ks]
                              + (((segB0 + anp * 2 + lhi) ^ kMod[ks]) << 4);
                uint32_t r0, r1, r2, r3;
                ldsm4t(r0, r1, r2, r3, addr);
                bf[2*anp][0] = r0; bf[2*anp][1] = r1;
                bf[2*anp+1][0] = r2; bf[2*anp+1][1] = r3;
            }
            #pragma unroll
            for (int am = 0; am < 4; am++)
                #pragma unroll
                for (int an = 0; an < 4; an++)
                    MMA16(acc[am][an], af[am], bf[an][0], bf[an][1]);
        }
        __syncthreads();
        buf ^= 1;
    }

    #pragma unroll
    for (int am = 0; am < 4; am++) {
        int s0 = row0 + wm * 64 + am * 16 + lr;
        #pragma unroll
        for (int an = 0; an < 4; an++) {
            int gc = n0 + wn * 32 + an * 8 + 2 * lc;
            float v0 = acc[am][an][0], v1 = acc[am][an][1];
            float v2 = acc[am][an][2], v3 = acc[am][an][3];
            if (GELU) {
                v0 = gelu_f(v0); v1 = gelu_f(v1);
                v2 = gelu_f(v2); v3 = gelu_f(v3);
            }
            if (OUT16) {
                __half* Ch = (__half*)Cout;
                if (s0 < rend)
                    *(__half2*)&Ch[(size_t)s0 * N + gc] = __floats2half2_rn(v0, v1);
                if (s0 + 8 < rend)
                    *(__half2*)&Ch[(size_t)(s0 + 8) * N + gc] = __floats2half2_rn(v2, v3);
            } else {
                float* Cf = (float*)Cout;
                if (s0 < rend) {
                    float2 t; t.x = v0; t.y = v1;
                    *(float2*)&Cf[(size_t)s0 * N + gc] = t;
                }
                if (s0 + 8 < rend) {
                    float2 t; t.x = v2; t.y = v3;
                    *(float2*)&Cf[(size_t)(s0 + 8) * N + gc] = t;
                }
            }
        }
    }
}

// ---------------- split-fp16 tensor-core flash attention --------------------
// q/k/v pre-split hi/lo fp16 (rope + scale already applied).
// smem: Q h/l 16KB + double-buffered K/V h/l 2x32KB = 80KB.
#define SMEM_ATT 81920

__global__ __launch_bounds__(128)
void attn_mma(const __half* __restrict__ qh, const __half* __restrict__ ql,
              const __half* __restrict__ kh, const __half* __restrict__ kl,
              const __half* __restrict__ vh, const __half* __restrict__ vl,
              __half* __restrict__ oh, __half* __restrict__ ol) {
    extern __shared__ char sma[];
    const uint32_t sb = (uint32_t)__cvta_generic_to_shared(sma);

    const int bh = blockIdx.x, b = bh >> 3, h = bh & 7;
    const int qt = (gridDim.y - 1) - blockIdx.y;   // big tiles first
    const int tid = threadIdx.x, lane = tid & 31, wid = tid >> 5;
    const int lr = lane >> 2, lc = lane & 3;
    const size_t tok0 = (size_t)b * Sd;

    const int ldr = tid >> 1, segb = (tid & 1) * 4;
    const int ldrm = ldr & 7;

    // Q tiles (hi + lo)
    {
        size_t qsrc = (tok0 + qt * 64 + ldr) * Dd + h * DHd;
        #pragma unroll
        for (int j = 0; j < 4; j++) {
            int seg = segb + j;
            uint32_t off = ldr * 128 + ((seg ^ ldrm) << 4);
            cp16(sb + off,        qh + qsrc + seg * 8);
            cp16(sb + 8192 + off, ql + qsrc + seg * 8);
        }
    }
    // KV(0) into buf 0 (same commit group as Q)
    {
        size_t src = (tok0 + 0 * 64 + ldr) * Dd + h * DHd;
        #pragma unroll
        for (int j = 0; j < 4; j++) {
            int seg = segb + j;
            uint32_t off = ldr * 128 + ((seg ^ ldrm) << 4);
            cp16(sb + 16384 + off, kh + src + seg * 8);
            cp16(sb + 24576 + off, kl + src + seg * 8);
            cp16(sb + 32768 + off, vh + src + seg * 8);
            cp16(sb + 40960 + off, vl + src + seg * 8);
        }
    }
    asm volatile("cp.async.commit_group;\n");

    const int lane7 = lane & 7, lsub = (lane >> 3) & 1, lhi = lane >> 4;
    const int rowA = wid * 16 + lane7 + lsub * 8;
    const uint32_t aOff = rowA * 128; const int aMod = rowA & 7;
    uint32_t xOff[4]; int xMod[4];
    #pragma unroll
    for (int i = 0; i < 4; i++) {
        int rx = i * 16 + lane7 + lsub * 8;
        xOff[i] = rx * 128; xMod[i] = rx & 7;
    }

    float accO[8][4];
    #pragma unroll
    for (int j = 0; j < 8; j++)
        #pragma unroll
        for (int i = 0; i < 4; i++) accO[j][i] = 0.f;
    float mrow[2] = {-1e30f, -1e30f}, lsum[2] = {0.f, 0.f};

    for (int kt = 0; kt <= qt; kt++) {
        __syncthreads();   // all warps done with buf[(kt+1)&1] from iter kt-1
        if (kt < qt) {     // prefetch next K/V
            size_t src = (tok0 + (kt + 1) * 64 + ldr) * Dd + h * DHd;
            uint32_t base = 16384 + ((kt + 1) & 1) * 32768;
            #pragma unroll
            for (int j = 0; j < 4; j++) {
                int seg = segb + j;
                uint32_t off = ldr * 128 + ((seg ^ ldrm) << 4);
                cp16(sb + base + off,         kh + src + seg * 8);
                cp16(sb + base + 8192 + off,  kl + src + seg * 8);
                cp16(sb + base + 16384 + off, vh + src + seg * 8);
                cp16(sb + base + 24576 + off, vl + src + seg * 8);
            }
            asm volatile("cp.async.commit_group;\n");
            asm volatile("cp.async.wait_group 1;\n");
        } else {
            asm volatile("cp.async.wait_group 0;\n");
        }
        __syncthreads();

        const uint32_t kb = sb + 16384 + (kt & 1) * 32768;
        const uint32_t vb = kb + 16384;

        // ---- S = Q @ K^T (3 split terms) ----
        float accS[8][4];
        #pragma unroll
        for (int j = 0; j < 8; j++)
            #pragma unroll
            for (int i = 0; i < 4; i++) accS[j][i] = 0.f;

        #pragma unroll
        for (int kc = 0; kc < 4; kc++) {
            uint32_t ah[4], al[4];
            uint32_t sega = (uint32_t)(((kc * 2 + lhi) ^ aMod) << 4);
            ldsm4(ah[0], ah[1], ah[2], ah[3], sb + aOff + sega);
            ldsm4(al[0], al[1], al[2], al[3], sb + 8192 + aOff + sega);
            #pragma unroll
            for (int np = 0; np < 4; np++) {
                uint32_t segk = (uint32_t)(((kc * 2 + lhi) ^ xMod[np]) << 4);
                uint32_t h0, h1, h2, h3, l0, l1, l2, l3;
                ldsm4(h0, h1, h2, h3, kb + xOff[np] + segk);
                ldsm4(l0, l1, l2, l3, kb + 8192 + xOff[np] + segk);
                MMA16(accS[2*np],   ah, h0, h2);
                MMA16(accS[2*np],   ah, l0, l2);
                MMA16(accS[2*np],   al, h0, h2);
                MMA16(accS[2*np+1], ah, h1, h3);
                MMA16(accS[2*np+1], ah, l1, l3);
                MMA16(accS[2*np+1], al, h1, h3);
            }
        }

        if (kt == qt) {
            #pragma unroll
            for (int j = 0; j < 8; j++)
                #pragma unroll
                for (int idx = 0; idx < 4; idx++) {
                    int col = j * 8 + 2 * lc + (idx & 1);
                    int rowl = wid * 16 + lr + (idx >> 1) * 8;
                    if (col > rowl) accS[j][idx] = -1e30f;
                }
        }

        #pragma unroll
        for (int rr = 0; rr < 2; rr++) {
            float tm = -1e30f;
            #pragma unroll
            for (int j = 0; j < 8; j++) {
                tm = fmaxf(tm, accS[j][2*rr]);
                tm = fmaxf(tm, accS[j][2*rr+1]);
            }
            tm = fmaxf(tm, __shfl_xor_sync(0xffffffffu, tm, 1));
            tm = fmaxf(tm, __shfl_xor_sync(0xffffffffu, tm, 2));
            float mn = fmaxf(mrow[rr], tm);
            float alpha = fexp(mrow[rr] - mn);
            float rs = 0.f;
            #pragma unroll
            for (int j = 0; j < 8; j++) {
                float p0 = fexp(accS[j][2*rr]   - mn);
                float p1 = fexp(accS[j][2*rr+1] - mn);
                accS[j][2*rr] = p0; accS[j][2*rr+1] = p1;
                rs += p0 + p1;
            }
            rs += __shfl_xor_sync(0xffffffffu, rs, 1);
            rs += __shfl_xor_sync(0xffffffffu, rs, 2);
            lsum[rr] = lsum[rr] * alpha + rs;
            mrow[rr] = mn;
            #pragma unroll
            for (int j = 0; j < 8; j++) {
                accO[j][2*rr]   *= alpha;
                accO[j][2*rr+1] *= alpha;
            }
        }

        // ---- O += P @ V ----
        #pragma unroll
        for (int kc2 = 0; kc2 < 4; kc2++) {
            uint32_t pah[4], pal[4];
            split2(accS[2*kc2][0],   accS[2*kc2][1],   pah[0], pal[0]);
            split2(accS[2*kc2][2],   accS[2*kc2][3],   pah[1], pal[1]);
            split2(accS[2*kc2+1][0], accS[2*kc2+1][1], pah[2], pal[2]);
            split2(accS[2*kc2+1][2], accS[2*kc2+1][3], pah[3], pal[3]);
            #pragma unroll
            for (int dp = 0; dp < 4; dp++) {
                uint32_t segv = (uint32_t)(((dp * 2 + lhi) ^ xMod[kc2]) << 4);
                uint32_t h0, h1, h2, h3, l0, l1, l2, l3;
                ldsm4t(h0, h1, h2, h3, vb + xOff[kc2] + segv);
                ldsm4t(l0, l1, l2, l3, vb + 8192 + xOff[kc2] + segv);
                MMA16(accO[2*dp],   pah, h0, h1);
                MMA16(accO[2*dp],   pah, l0, l1);
                MMA16(accO[2*dp],   pal, h0, h1);
                MMA16(accO[2*dp+1], pah, h2, h3);
                MMA16(accO[2*dp+1], pah, l2, l3);
                MMA16(accO[2*dp+1], pal, h2, h3);
            }
        }
    }

    #pragma unroll
    for (int rr = 0; rr < 2; rr++) {
        float inv = 1.0f / lsum[rr];
        size_t base = (tok0 + qt * 64 + wid * 16 + lr + rr * 8) * Dd + h * DHd;
        #pragma unroll
        for (int j = 0; j < 8; j++) {
            float v0 = accO[j][2*rr] * inv, v1 = accO[j][2*rr+1] * inv;
            uint32_t hi, lo;
            split2(v0, v1, hi, lo);
            *(uint32_t*)&oh[base + j * 8 + 2 * lc] = hi;
            *(uint32_t*)&ol[base + j * 8 + 2 * lc] = lo;
        }
    }
}

// ---------------- router / scatter -----------------------------------------
__global__ void zero_cnt_k() { if (threadIdx.x < Ed) g_cnt[threadIdx.x] = 0; }

__global__ void router_k(const float* __restrict__ hn, const float* __restrict__ rw) {
    int warp = (blockIdx.x * blockDim.x + threadIdx.x) >> 5;
    int lane = threadIdx.x & 31;
    if (warp >= Td) return;
    const float* row = hn + (size_t)warp * Dd;
    float acc[Ed];
    #pragma unroll
    for (int e = 0; e < Ed; e++) acc[e] = 0.f;
    for (int d = lane; d < Dd; d += 32) {
        float x = row[d];
        #pragma unroll
        for (int e = 0; e < Ed; e++) acc[e] += x * rw[d * Ed + e];
    }
    #pragma unroll
    for (int e = 0; e < Ed; e++)
        #pragma unroll
        for (int o = 16; o; o >>= 1)
            acc[e] += __shfl_xor_sync(0xffffffffu, acc[e], o);
    if (lane == 0) {
        int i0 = 0;
        #pragma unroll
        for (int e = 1; e < Ed; e++) if (acc[e] > acc[i0]) i0 = e;
        int i1 = (i0 == 0) ? 1 : 0;
        #pragma unroll
        for (int e = 0; e < Ed; e++) if (e != i0 && acc[e] > acc[i1]) i1 = e;
        float ex = expf(acc[i1] - acc[i0]);
        float g0 = 1.f / (1.f + ex);
        float g1 = ex / (1.f + ex);
        g_eidx[warp * 2] = i0; g_eidx[warp * 2 + 1] = i1;
        g_gate[warp * 2] = g0; g_gate[warp * 2 + 1] = g1;
        atomicAdd(&g_cnt[i0], 1);
        atomicAdd(&g_cnt[i1], 1);
    }
}

__global__ void tiles_k() {
    int off = 0, nt = 0;
    for (int e = 0; e < Ed; e++) {
        g_off[e] = off; g_pos[e] = 0;
        int c = g_cnt[e];
        for (int r = 0; r < c; r += 128) {
            g_tile_e[nt] = e; g_tile_row[nt] = off + r; g_tile_end[nt] = off + c; nt++;
        }
        off += c;
    }
    g_off[Ed] = off;
    g_ntiles = nt;
}

__global__ void assign_k() {
    int t = blockIdx.x * blockDim.x + threadIdx.x;
    if (t >= Td) return;
    #pragma unroll
    for (int kk = 0; kk < 2; kk++) {
        int e = g_eidx[t * 2 + kk];
        int p = atomicAdd(&g_pos[e], 1);
        int slot = g_off[e] + p;
        g_slot_token[slot] = t;
        g_slot_of[t * 2 + kk] = slot;
    }
}

__global__ void final_k(float* __restrict__ out) {
    int idx = blockIdx.x * blockDim.x + threadIdx.x;
    if (idx >= Td * Dd) return;
    int t = idx >> 9, d = idx & 511;
    float r = g_h[idx];
    r += g_gate[t * 2]     * g_yslot[(size_t)g_slot_of[t * 2]     * Dd + d];
    r += g_gate[t * 2 + 1] * g_yslot[(size_t)g_slot_of[t * 2 + 1] * Dd + d];
    out[idx] = r;
}

// ---------------- launch -----------------------------------------------------
extern "C" void kernel_launch(void* const* d_in, const int* in_sizes, int n_in,
                              void* d_out, int out_size) {
    const float* x   = (const float*)d_in[0];
    const float* anw = (const float*)d_in[1];
    const float* wq  = (const float*)d_in[2];
    const float* wk  = (const float*)d_in[3];
    const float* wv  = (const float*)d_in[4];
    const float* wo  = (const float*)d_in[5];
    const float* fnw = (const float*)d_in[6];
    const float* rw  = (const float*)d_in[7];
    const float* w1  = (const float*)d_in[8];
    const float* w2  = (const float*)d_in[9];
    float* out = (float*)d_out;

    float *p_h, *p_hn, *p_yslot;
    __half *p_xnh, *p_xnl, *p_qh, *p_ql, *p_kh, *p_kl, *p_vh, *p_vl;
    __half *p_atth, *p_attl, *p_hn16, *p_hidden16;
    __half *p_wqkvh, *p_wqkvl, *p_woh, *p_wol, *p_w1c, *p_w2c;
    cudaGetSymbolAddress((void**)&p_h, g_h);
    cudaGetSymbolAddress((void**)&p_hn, g_hn);
    cudaGetSymbolAddress((void**)&p_xnh, g_xnh);
    cudaGetSymbolAddress((void**)&p_xnl, g_xnl);
    cudaGetSymbolAddress((void**)&p_qh, g_qh);
    cudaGetSymbolAddress((void**)&p_ql, g_ql);
    cudaGetSymbolAddress((void**)&p_kh, g_kh);
    cudaGetSymbolAddress((void**)&p_kl, g_kl);
    cudaGetSymbolAddress((void**)&p_vh, g_vh);
    cudaGetSymbolAddress((void**)&p_vl, g_vl);
    cudaGetSymbolAddress((void**)&p_atth, g_atth);
    cudaGetSymbolAddress((void**)&p_attl, g_attl);
    cudaGetSymbolAddress((void**)&p_hn16, g_hn16);
    cudaGetSymbolAddress((void**)&p_hidden16, g_hidden16);
    cudaGetSymbolAddress((void**)&p_yslot, g_yslot);
    cudaGetSymbolAddress((void**)&p_wqkvh, g_wqkvh);
    cudaGetSymbolAddress((void**)&p_wqkvl, g_wqkvl);
    cudaGetSymbolAddress((void**)&p_woh, g_woh);
    cudaGetSymbolAddress((void**)&p_wol, g_wol);
    cudaGetSymbolAddress((void**)&p_w1c, g_w1c);
    cudaGetSymbolAddress((void**)&p_w2c, g_w2c);

    cudaFuncSetAttribute(sgemm_split<0>,
                         cudaFuncAttributeMaxDynamicSharedMemorySize, SMEM_S);
    cudaFuncSetAttribute(sgemm_split<1>,
                         cudaFuncAttributeMaxDynamicSharedMemorySize, SMEM_S);
    cudaFuncSetAttribute(hgemm_grp2<true, true, true>,
                         cudaFuncAttributeMaxDynamicSharedMemorySize, SMEM_H2);
    cudaFuncSetAttribute(hgemm_grp2<false, false, false>,
                         cudaFuncAttributeMaxDynamicSharedMemorySize, SMEM_H2);
    cudaFuncSetAttribute(attn_mma,
                         cudaFuncAttributeMaxDynamicSharedMemorySize, SMEM_ATT);

    // 0) weight preprocessing
    const int EW4 = (Ed * Dd * HFd) / 4;
    convert16_k<<<(EW4 + 255) / 256, 256>>>(w1, p_w1c, EW4);
    convert16_k<<<(EW4 + 255) / 256, 256>>>(w2, p_w2c, EW4);
    transpose_whl_k<<<dim3(Dd / 32, Dd / 32), dim3(32, 8)>>>(wq, p_wqkvh, p_wqkvl, Dd, Dd);
    transpose_whl_k<<<dim3(Dd / 32, Dd / 32), dim3(32, 8)>>>(wk, p_wqkvh + Dd * Dd,
                                                             p_wqkvl + Dd * Dd, Dd, Dd);
    transpose_whl_k<<<dim3(Dd / 32, Dd / 32), dim3(32, 8)>>>(wv, p_wqkvh + 2 * Dd * Dd,
                                                             p_wqkvl + 2 * Dd * Dd, Dd, Dd);
    transpose_whl_k<<<dim3(Dd / 32, Dd / 32), dim3(32, 8)>>>(wo, p_woh, p_wol, Dd, Dd);
    // 1) rmsnorm(x) -> hi/lo fp16
    rmsnorm_k<<<Td, 256>>>(x, anw, nullptr, p_xnh, p_xnl);
    // 2) fused QKV split-fp16 GEMM with fused RoPE + q-scale, hi/lo fp16 out
    sgemm_split<0><<<dim3(Td / 128, Dd / 128, 3), 256, SMEM_S>>>(
        p_xnh, p_xnl, p_wqkvh, p_wqkvl,
        p_qh, p_ql, p_kh, p_kl, p_vh, p_vl, nullptr, nullptr, Dd, Dd);
    // 3) causal attention (split-fp16 mma; double-buffered cp.async)
    attn_mma<<<dim3(Bd * Hd, Sd / 64), 128, SMEM_ATT>>>(
        p_qh, p_ql, p_kh, p_kl, p_vh, p_vl, p_atth, p_attl);
    // 4) O projection + residual (split-fp16, fp32 out)
    sgemm_split<1><<<dim3(Td / 128, Dd / 128, 1), 256, SMEM_S>>>(
        p_atth, p_attl, p_woh, p_wol,
        nullptr, nullptr, nullptr, nullptr, nullptr, nullptr, p_h, x, Dd, Dd);
    // 5) rmsnorm(h) -> fp32 (router) + fp16 (MoE)
    rmsnorm_k<<<Td, 256>>>(p_h, fnw, p_hn, p_hn16, nullptr);
    // 6) router + expert grouping (fp32 logits)
    zero_cnt_k<<<1, 32>>>();
    router_k<<<Td / 8, 256>>>(p_hn, rw);
    tiles_k<<<1, 1>>>();
    assign_k<<<Td / 256, 256>>>();
    // 7) expert GEMM 1: hidden16 = gelu(hn16 @ w1[e])   [trans-B, no pre-transpose]
    hgemm_grp2<true, true, true><<<dim3(MAXTILES, HFd / 128), 256, SMEM_H2>>>(
        p_hn16, p_w1c, p_hidden16, HFd, Dd);
    // 8) expert GEMM 2: yslot = hidden16 @ w2[e]
    hgemm_grp2<false, false, false><<<dim3(MAXTILES, Dd / 128), 256, SMEM_H2>>>(
        p_hidden16, p_w2c, p_yslot, Dd, HFd);
    // 9) final gather + residual
    final_k<<<(Td * Dd) / 256, 256>>>(out);
}

// round 17
// speedup vs baseline: 3.3824x; 1.0411x over previous
#include <cuda_runtime.h>
#include <cuda_fp16.h>
#include <math.h>
#include <stdint.h>

#define Bd 4
#define Sd 2048
#define Dd 512
#define Hd 8
#define DHd 64
#define Ed 8
#define HFd 2048
#define Td (Bd*Sd)        /* 8192 tokens */
#define NSLOT (2*Td)      /* 16384 expert-slots */
#define MAXTILES 144

// ---------------- scratch (device globals; no allocation allowed) ----------
__device__ float  g_h[Td*Dd];
__device__ float  g_hn[Td*Dd];
__device__ __half g_xnh[Td*Dd];
__device__ __half g_xnl[Td*Dd];
__device__ __half g_qh[Td*Dd];
__device__ __half g_ql[Td*Dd];
__device__ __half g_kh[Td*Dd];
__device__ __half g_kl[Td*Dd];
__device__ __half g_vh[Td*Dd];
__device__ __half g_vl[Td*Dd];
__device__ __half g_atth[Td*Dd];
__device__ __half g_attl[Td*Dd];
__device__ __half g_hn16[Td*Dd];
__device__ __half g_wqkvh[3*Dd*Dd];   /* [z][n][k] hi */
__device__ __half g_wqkvl[3*Dd*Dd];   /* [z][n][k] lo */
__device__ __half g_woh[Dd*Dd];
__device__ __half g_wol[Dd*Dd];
__device__ float  g_gate[Td*2];
__device__ int    g_eidx[Td*2];
__device__ int    g_slot_of[Td*2];
__device__ int    g_slot_token[NSLOT];
__device__ int    g_cnt[Ed];
__device__ int    g_off[Ed+1];
__device__ int    g_pos[Ed];
__device__ int    g_tile_e[MAXTILES];
__device__ int    g_tile_row[MAXTILES];
__device__ int    g_tile_end[MAXTILES];
__device__ int    g_ntiles;
__device__ __half g_hidden16[(size_t)NSLOT*HFd]; /* 64 MB */
__device__ __half g_yslot16[(size_t)NSLOT*Dd];   /* 16 MB */
__device__ __half g_w1c[(size_t)Ed*Dd*HFd];      /* 16 MB: [e][k][n] fp16 (natural) */
__device__ __half g_w2c[(size_t)Ed*HFd*Dd];      /* 16 MB: [e][k][n] fp16 (natural) */

// ---------------- fast exp on the FMA pipe ----------------------------------
__device__ __forceinline__ float fexp(float x) {
    x = fmaxf(x, -80.0f);
    float i = rintf(x * 1.44269504088896341f);
    float r = fmaf(i, -0.693359375f, x);
    r = fmaf(i, 2.12194440e-4f, r);
    float z = r * r;
    float p = 1.9875691500e-4f;
    p = fmaf(p, r, 1.3981999507e-3f);
    p = fmaf(p, r, 8.3334519073e-3f);
    p = fmaf(p, r, 4.1665795894e-2f);
    p = fmaf(p, r, 1.6666665459e-1f);
    p = fmaf(p, r, 5.0000001201e-1f);
    float y = fmaf(z, p, r) + 1.0f;
    int j = __float2int_rn(i);
    float sc2 = __int_as_float((j + 127) << 23);
    return y * sc2;
}

// ---------------- small helpers --------------------------------------------
__device__ __forceinline__ void split2(float a, float b, uint32_t& hi, uint32_t& lo) {
    __half ha = __float2half(a), hb = __float2half(b);
    __half2 h = __halves2half2(ha, hb);
    hi = *(uint32_t*)&h;
    __half2 l = __halves2half2(__float2half(a - __half2float(ha)),
                               __float2half(b - __half2float(hb)));
    lo = *(uint32_t*)&l;
}

// ---------------- rmsnorm (fp32 out nullable; optional hi/lo fp16) ----------
__global__ void rmsnorm_k(const float* __restrict__ in, const float* __restrict__ w,
                          float* __restrict__ out,
                          __half* __restrict__ outh, __half* __restrict__ outl) {
    int t = blockIdx.x;
    int tid = threadIdx.x;
    const float* row = in + (size_t)t * Dd;
    float v0 = row[tid], v1 = row[tid + 256];
    float ss = v0 * v0 + v1 * v1;
    #pragma unroll
    for (int o = 16; o; o >>= 1) ss += __shfl_xor_sync(0xffffffffu, ss, o);
    __shared__ float red[8];
    __shared__ float sc;
    if ((tid & 31) == 0) red[tid >> 5] = ss;
    __syncthreads();
    if (tid == 0) {
        float s = 0.f;
        #pragma unroll
        for (int i = 0; i < 8; i++) s += red[i];
        sc = rsqrtf(s / (float)Dd + 1e-5f);
    }
    __syncthreads();
    float o0 = v0 * sc * w[tid];
    float o1 = v1 * sc * w[tid + 256];
    size_t i0 = (size_t)t * Dd + tid, i1 = i0 + 256;
    if (out) { out[i0] = o0; out[i1] = o1; }
    if (outh) {
        __half h0 = __float2half(o0), h1 = __float2half(o1);
        outh[i0] = h0; outh[i1] = h1;
        if (outl) {
            outl[i0] = __float2half(o0 - __half2float(h0));
            outl[i1] = __float2half(o1 - __half2float(h1));
        }
    }
}

// ------- dense weight transpose: W[K][N] fp32 -> Wh/Wl[N][K] hi/lo fp16 -----
__global__ void transpose_whl_k(const float* __restrict__ W,
                                __half* __restrict__ Wh, __half* __restrict__ Wl,
                                int K, int N) {
    __shared__ float t[32][33];
    int k0 = blockIdx.x * 32, n0 = blockIdx.y * 32;
    int tx = threadIdx.x, ty = threadIdx.y;   // 32 x 8
    #pragma unroll
    for (int i = 0; i < 32; i += 8)
        t[ty + i][tx] = W[(size_t)(k0 + ty + i) * N + n0 + tx];
    __syncthreads();
    #pragma unroll
    for (int i = 0; i < 32; i += 8) {
        float v = t[tx][ty + i];
        __half hi = __float2half(v);
        size_t idx = (size_t)(n0 + ty + i) * K + k0 + tx;
        Wh[idx] = hi;
        Wl[idx] = __float2half(v - __half2float(hi));
    }
}

// ------- expert weight convert (no transpose): fp32 -> fp16, coalesced ------
__global__ void convert16_k(const float* __restrict__ W, __half* __restrict__ O,
                            int n4) {
    int i = blockIdx.x * blockDim.x + threadIdx.x;
    if (i >= n4) return;
    float4 f = ((const float4*)W)[i];
    __half2 a = __floats2half2_rn(f.x, f.y);
    __half2 b2 = __floats2half2_rn(f.z, f.w);
    uint2 u; u.x = *(uint32_t*)&a; u.y = *(uint32_t*)&b2;
    ((uint2*)O)[i] = u;
}

// ---------------- mma helpers -----------------------------------------------
__device__ __forceinline__ void cp16(uint32_t dst, const void* src) {
    asm volatile("cp.async.cg.shared.global [%0], [%1], 16;\n" :: "r"(dst), "l"(src));
}
__device__ __forceinline__ void ldsm4(uint32_t& r0, uint32_t& r1, uint32_t& r2,
                                      uint32_t& r3, uint32_t addr) {
    asm volatile("ldmatrix.sync.aligned.m8n8.x4.shared.b16 {%0,%1,%2,%3}, [%4];"
                 : "=r"(r0), "=r"(r1), "=r"(r2), "=r"(r3) : "r"(addr));
}
__device__ __forceinline__ void ldsm4t(uint32_t& r0, uint32_t& r1, uint32_t& r2,
                                       uint32_t& r3, uint32_t addr) {
    asm volatile("ldmatrix.sync.aligned.m8n8.x4.trans.shared.b16 {%0,%1,%2,%3}, [%4];"
                 : "=r"(r0), "=r"(r1), "=r"(r2), "=r"(r3) : "r"(addr));
}
#define MMA16(ac, a, b0, b1) \
    asm volatile( \
        "mma.sync.aligned.m16n8k16.row.col.f32.f16.f16.f32 " \
        "{%0,%1,%2,%3}, {%4,%5,%6,%7}, {%8,%9}, {%0,%1,%2,%3};\n" \
        : "+f"((ac)[0]), "+f"((ac)[1]), "+f"((ac)[2]), "+f"((ac)[3]) \
        : "r"((a)[0]), "r"((a)[1]), "r"((a)[2]), "r"((a)[3]), "r"(b0), "r"(b1))

// ---------------- split-fp16 dense GEMM (fp32-accurate, tensor cores) -------
// MODE 0: QKV — fused RoPE (z<2) + q-scale (z==0), hi/lo fp16 outputs
// MODE 1: O-proj — fp32 out + residual
#define STB 16384
#define SMEM_S (4*STB)

template<int MODE>
__global__ __launch_bounds__(256, 2)
void sgemm_split(const __half* __restrict__ Ah, const __half* __restrict__ Al,
                 const __half* __restrict__ Wh, const __half* __restrict__ Wl,
                 __half* __restrict__ o0h, __half* __restrict__ o0l,
                 __half* __restrict__ o1h, __half* __restrict__ o1l,
                 __half* __restrict__ o2h, __half* __restrict__ o2l,
                 float* __restrict__ C, const float* __restrict__ Res,
                 int N, int K) {
    extern __shared__ char sms[];
    const int z = blockIdx.z;
    const __half* Bh_g = Wh + (size_t)z * N * K;
    const __half* Bl_g = Wl + (size_t)z * N * K;

    const int m0 = blockIdx.x * 128, n0 = blockIdx.y * 128;
    const int tid = threadIdx.x;
    const int lane = tid & 31, wid = tid >> 5;
    const int wm = wid >> 2, wn = wid & 3;
    const int lr = lane >> 2, lc = lane & 3;
    const uint32_t sb = (uint32_t)__cvta_generic_to_shared(sms);

    const int ldR = tid >> 1;
    const int hsel = tid & 1;
    const __half* aSrc = (hsel ? Al : Ah) + (size_t)(m0 + ldR) * K;
    const __half* bSrc = (hsel ? Bl_g : Bh_g) + (size_t)(n0 + ldR) * K;
    const int ldRm = ldR & 7;
    uint32_t aD[4], bD[4];
    #pragma unroll
    for (int p = 0; p < 4; p++) {
        uint32_t off = ldR * 128 + ((((hsel << 2) + p) ^ ldRm) << 4);
        aD[p] = sb + off;
        bD[p] = sb + 2 * STB + off;
    }

    const int lane7 = lane & 7, lsub = (lane >> 3) & 1, lhi = lane >> 4;
    uint32_t aRowOff[4]; int aMod[4];
    #pragma unroll
    for (int am = 0; am < 4; am++) {
        int r = wm * 64 + am * 16 + lane7 + lsub * 8;
        aRowOff[am] = r * 128; aMod[am] = r & 7;
    }
    uint32_t bRowOff[2]; int bMod[2];
    #pragma unroll
    for (int p = 0; p < 2; p++) {
        int r = wn * 32 + p * 16 + lane7 + lsub * 8;
        bRowOff[p] = r * 128; bMod[p] = r & 7;
    }

    float acc[4][4][4];
    #pragma unroll
    for (int i = 0; i < 4; i++)
        #pragma unroll
        for (int j = 0; j < 4; j++)
            #pragma unroll
            for (int r = 0; r < 4; r++) acc[i][j][r] = 0.f;

    const int nkb = K >> 5;
    #pragma unroll
    for (int p = 0; p < 4; p++) {
        cp16(aD[p], aSrc + p * 8);
        cp16(bD[p], bSrc + p * 8);
    }
    asm volatile("cp.async.commit_group;\n");

    int buf = 0;
    for (int kb = 0; kb < nkb; kb++) {
        if (kb + 1 < nkb) {
            int ko = (kb + 1) * 32;
            #pragma unroll
            for (int p = 0; p < 4; p++) {
                cp16(aD[p] + (buf ^ 1) * STB, aSrc + ko + p * 8);
                cp16(bD[p] + (buf ^ 1) * STB, bSrc + ko + p * 8);
            }
            asm volatile("cp.async.commit_group;\n");
            asm volatile("cp.async.wait_group 1;\n");
        } else {
            asm volatile("cp.async.wait_group 0;\n");
        }
        __syncthreads();

        const uint32_t Ab = sb + buf * STB;
        const uint32_t Bb = sb + 2 * STB + buf * STB;
        #pragma unroll
        for (int ks = 0; ks < 2; ks++) {
            const int segh = (ks << 1) + lhi;
            uint32_t af[4][4], bfh[4][2], bfl[4][2];
            #pragma unroll
            for (int am = 0; am < 4; am++) {
                uint32_t addr = Ab + aRowOff[am] + ((segh ^ aMod[am]) << 4);
                ldsm4(af[am][0], af[am][1], af[am][2], af[am][3], addr);
            }
            #pragma unroll
            for (int p = 0; p < 2; p++) {
                uint32_t r0, r1, r2, r3;
                ldsm4(r0, r1, r2, r3, Bb + bRowOff[p] + ((segh ^ bMod[p]) << 4));
                bfh[2*p][0] = r0; bfh[2*p+1][0] = r1;
                bfh[2*p][1] = r2; bfh[2*p+1][1] = r3;
                ldsm4(r0, r1, r2, r3, Bb + bRowOff[p] + (((segh + 4) ^ bMod[p]) << 4));
                bfl[2*p][0] = r0; bfl[2*p+1][0] = r1;
                bfl[2*p][1] = r2; bfl[2*p+1][1] = r3;
            }
            #pragma unroll
            for (int am = 0; am < 4; am++)
                #pragma unroll
                for (int an = 0; an < 4; an++) {
                    MMA16(acc[am][an], af[am], bfh[an][0], bfh[an][1]);
                    MMA16(acc[am][an], af[am], bfl[an][0], bfl[an][1]);
                }
            #pragma unroll
            for (int am = 0; am < 4; am++) {
                uint32_t addr = Ab + aRowOff[am] + (((segh + 4) ^ aMod[am]) << 4);
                ldsm4(af[am][0], af[am][1], af[am][2], af[am][3], addr);
            }
            #pragma unroll
            for (int am = 0; am < 4; am++)
                #pragma unroll
                for (int an = 0; an < 4; an++)
                    MMA16(acc[am][an], af[am], bfh[an][0], bfh[an][1]);
        }
        __syncthreads();
        buf ^= 1;
    }

    // ---- epilogue ----
    if (MODE == 0) {
        __half* Oh = (z == 0) ? o0h : (z == 1) ? o1h : o2h;
        __half* Ol = (z == 0) ? o0l : (z == 1) ? o1l : o2l;
        #pragma unroll
        for (int am = 0; am < 4; am++) {
            #pragma unroll
            for (int hrow = 0; hrow < 2; hrow++) {
                int grow = m0 + wm * 64 + am * 16 + hrow * 8 + lr;
                int s = grow & (Sd - 1);
                #pragma unroll
                for (int an = 0; an < 4; an++) {
                    int gc = wn * 32 + an * 8 + 2 * lc;
                    int gcg = n0 + gc;
                    float v0 = acc[am][an][hrow * 2 + 0];
                    float v1 = acc[am][an][hrow * 2 + 1];
                    if (z < 2) {
                        int i = (gcg & 63) >> 1;
                        float freq = exp2f(-(float)i * 0.41524101185467246f);
                        float sn, cs;
                        sincosf((float)s * freq, &sn, &cs);
                        float r0 = v0 * cs - v1 * sn;
                        float r1 = v0 * sn + v1 * cs;
                        if (z == 0) { r0 *= 0.125f; r1 *= 0.125f; }
                        v0 = r0; v1 = r1;
                    }
                    uint32_t hi, lo;
                    split2(v0, v1, hi, lo);
                    *(uint32_t*)&Oh[(size_t)grow * N + gcg] = hi;
                    *(uint32_t*)&Ol[(size_t)grow * N + gcg] = lo;
                }
            }
        }
    } else {
        #pragma unroll
        for (int am = 0; am < 4; am++) {
            #pragma unroll
            for (int hrow = 0; hrow < 2; hrow++) {
                int grow = m0 + wm * 64 + am * 16 + hrow * 8 + lr;
                float* crow = C + (size_t)grow * N + n0;
                const float* rrow = Res + (size_t)grow * N + n0;
                #pragma unroll
                for (int an = 0; an < 4; an++) {
                    int gc = wn * 32 + an * 8 + 2 * lc;
                    float v0 = acc[am][an][hrow * 2 + 0] + rrow[gc];
                    float v1 = acc[am][an][hrow * 2 + 1] + rrow[gc + 1];
                    float2 t; t.x = v0; t.y = v1;
                    *(float2*)&crow[gc] = t;
                }
            }
        }
    }
}

// ---------------- fp16 grouped expert GEMM (trans-B from natural [k][n]) ----
__device__ __forceinline__ float gelu_f(float x) {
    return 0.5f * x * (1.0f + erff(x * 0.70710678118654752f));
}

#define TB 16384
#define SMEM_H2 (4*TB)

template<bool GATHER, bool GELU, bool OUT16>
__global__ __launch_bounds__(256, 2)
void hgemm_grp2(const __half* __restrict__ Abase, const __half* __restrict__ Wc,
                void* __restrict__ Cout, int N, int K) {
    extern __shared__ char sm8[];
    int bx = blockIdx.x;
    if (bx >= g_ntiles) return;
    const int e = g_tile_e[bx], row0 = g_tile_row[bx], rend = g_tile_end[bx];
    const int n0 = blockIdx.y * 128;

    const int tid = threadIdx.x;
    const int lane = tid & 31, wid = tid >> 5;
    const int wm = wid >> 2, wn = wid & 3;
    const int lr = lane >> 2, lc = lane & 3;
    const uint32_t sb = (uint32_t)__cvta_generic_to_shared(sm8);

    const int ldR = tid >> 1;
    const int segb = (tid & 1) * 4;
    int grow = row0 + ldR;
    int gsafe = grow < rend ? grow : rend - 1;
    int arow = GATHER ? g_slot_token[gsafe] : gsafe;
    const __half* aRow = Abase + (size_t)arow * K + segb * 8;
    const int ldRm = ldR & 7;
    uint32_t aD[4];
    #pragma unroll
    for (int p = 0; p < 4; p++)
        aD[p] = sb + ldR * 128 + (((segb + p) ^ ldRm) << 4);

    const int bkr = tid >> 2;
    const int bsegb = (tid & 3) * 4;
    const __half* bRow = Wc + (size_t)e * K * N + (size_t)bkr * N + n0;
    const int bkrm = bkr & 7;
    uint32_t bD[4];
    #pragma unroll
    for (int p = 0; p < 4; p++) {
        int s = bsegb + p;
        bD[p] = sb + 2 * TB + (s >> 3) * 8192 + bkr * 128 + (((s & 7) ^ bkrm) << 4);
    }

    const int lane7 = lane & 7, lsub = (lane >> 3) & 1, lhi = lane >> 4;
    uint32_t aRowOff[4]; int aMod[4];
    #pragma unroll
    for (int am = 0; am < 4; am++) {
        int r = wm * 64 + am * 16 + lane7 + lsub * 8;
        aRowOff[am] = r * 128; aMod[am] = r & 7;
    }
    uint32_t kRowOff[4]; int kMod[4];
    #pragma unroll
    for (int ks = 0; ks < 4; ks++) {
        int r = ks * 16 + lane7 + lsub * 8;
        kRowOff[ks] = r * 128; kMod[ks] = r & 7;
    }
    const uint32_t btile = (uint32_t)(wn >> 1) * 8192;
    const int segB0 = (wn & 1) * 4;

    float acc[4][4][4];
    #pragma unroll
    for (int i = 0; i < 4; i++)
        #pragma unroll
        for (int j = 0; j < 4; j++)
            #pragma unroll
            for (int r = 0; r < 4; r++) acc[i][j][r] = 0.f;

    const int nkb = K >> 6;
    #pragma unroll
    for (int p = 0; p < 4; p++) {
        cp16(aD[p], aRow + p * 8);
        cp16(bD[p], bRow + (bsegb + p) * 8);
    }
    asm volatile("cp.async.commit_group;\n");

    int buf = 0;
    for (int kb = 0; kb < nkb; kb++) {
        if (kb + 1 < nkb) {
            int ko = (kb + 1) * 64;
            #pragma unroll
            for (int p = 0; p < 4; p++) {
                cp16(aD[p] + (buf ^ 1) * TB, aRow + ko + p * 8);
                cp16(bD[p] + (buf ^ 1) * TB, bRow + (size_t)ko * N + (bsegb + p) * 8);
            }
            asm volatile("cp.async.commit_group;\n");
            asm volatile("cp.async.wait_group 1;\n");
        } else {
            asm volatile("cp.async.wait_group 0;\n");
        }
        __syncthreads();

        const uint32_t Ab = sb + buf * TB;
        const uint32_t Bb = sb + 2 * TB + buf * TB;
        #pragma unroll
        for (int ks = 0; ks < 4; ks++) {
            uint32_t af[4][4], bf[4][2];
            #pragma unroll
            for (int am = 0; am < 4; am++) {
                uint32_t addr = Ab + aRowOff[am] + ((((ks << 1) + lhi) ^ aMod[am]) << 4);
                ldsm4(af[am][0], af[am][1], af[am][2], af[am][3], addr);
            }
            #pragma unroll
            for (int anp = 0; anp < 2; anp++) {
                uint32_t addr = Bb + btile + kRowOff[ks]
                              + (((segB0 + anp * 2 + lhi) ^ kMod[ks]) << 4);
                uint32_t r0, r1, r2, r3;
                ldsm4t(r0, r1, r2, r3, addr);
                bf[2*anp][0] = r0; bf[2*anp][1] = r1;
                bf[2*anp+1][0] = r2; bf[2*anp+1][1] = r3;
            }
            #pragma unroll
            for (int am = 0; am < 4; am++)
                #pragma unroll
                for (int an = 0; an < 4; an++)
                    MMA16(acc[am][an], af[am], bf[an][0], bf[an][1]);
        }
        __syncthreads();
        buf ^= 1;
    }

    #pragma unroll
    for (int am = 0; am < 4; am++) {
        int s0 = row0 + wm * 64 + am * 16 + lr;
        #pragma unroll
        for (int an = 0; an < 4; an++) {
            int gc = n0 + wn * 32 + an * 8 + 2 * lc;
            float v0 = acc[am][an][0], v1 = acc[am][an][1];
            float v2 = acc[am][an][2], v3 = acc[am][an][3];
            if (GELU) {
                v0 = gelu_f(v0); v1 = gelu_f(v1);
                v2 = gelu_f(v2); v3 = gelu_f(v3);
            }
            if (OUT16) {
                __half* Ch = (__half*)Cout;
                if (s0 < rend)
                    *(__half2*)&Ch[(size_t)s0 * N + gc] = __floats2half2_rn(v0, v1);
                if (s0 + 8 < rend)
                    *(__half2*)&Ch[(size_t)(s0 + 8) * N + gc] = __floats2half2_rn(v2, v3);
            } else {
                float* Cf = (float*)Cout;
                if (s0 < rend) {
                    float2 t; t.x = v0; t.y = v1;
                    *(float2*)&Cf[(size_t)s0 * N + gc] = t;
                }
                if (s0 + 8 < rend) {
                    float2 t; t.x = v2; t.y = v3;
                    *(float2*)&Cf[(size_t)(s0 + 8) * N + gc] = t;
                }
            }
        }
    }
}

// ---------------- split-fp16 tensor-core flash attention (128-row q tile) ---
// 8 warps / 256 threads; q/k/v pre-split hi/lo fp16 (rope+scale applied).
// smem: Q h/l 32KB + double-buffered K/V h/l 2x32KB = 96KB.
#define SMEM_ATT 98304

__global__ __launch_bounds__(256, 2)
void attn_mma(const __half* __restrict__ qh, const __half* __restrict__ ql,
              const __half* __restrict__ kh, const __half* __restrict__ kl,
              const __half* __restrict__ vh, const __half* __restrict__ vl,
              __half* __restrict__ oh, __half* __restrict__ ol) {
    extern __shared__ char sma[];
    const uint32_t sb = (uint32_t)__cvta_generic_to_shared(sma);

    const int bh = blockIdx.x, b = bh >> 3, h = bh & 7;
    const int qt = (gridDim.y - 1) - blockIdx.y;   // big tiles first
    const int tid = threadIdx.x, lane = tid & 31, wid = tid >> 5;
    const int lr = lane >> 2, lc = lane & 3;
    const size_t tok0 = (size_t)b * Sd;

    // Q loader: 128 rows, thread covers 4 segs of hi + 4 of lo for one row-half
    const int ldr = tid >> 1, segq = (tid & 1) * 4;
    const int ldrm = ldr & 7;
    {
        size_t qsrc = (tok0 + qt * 128 + ldr) * Dd + h * DHd;
        #pragma unroll
        for (int j = 0; j < 4; j++) {
            int seg = segq + j;
            uint32_t off = ldr * 128 + ((seg ^ ldrm) << 4);
            cp16(sb + off,         qh + qsrc + seg * 8);
            cp16(sb + 16384 + off, ql + qsrc + seg * 8);
        }
    }
    // KV loader: 64 rows x 4 arrays; thread covers 2 segs of each array
    const int ldk = tid >> 2, segk0 = (tid & 3) * 2;
    const int ldkm = ldk & 7;
    {
        size_t src = (tok0 + ldk) * Dd + h * DHd;
        #pragma unroll
        for (int j = 0; j < 2; j++) {
            int seg = segk0 + j;
            uint32_t off = ldk * 128 + ((seg ^ ldkm) << 4);
            cp16(sb + 32768 + off,         kh + src + seg * 8);
            cp16(sb + 32768 + 8192 + off,  kl + src + seg * 8);
            cp16(sb + 32768 + 16384 + off, vh + src + seg * 8);
            cp16(sb + 32768 + 24576 + off, vl + src + seg * 8);
        }
    }
    asm volatile("cp.async.commit_group;\n");

    const int lane7 = lane & 7, lsub = (lane >> 3) & 1, lhi = lane >> 4;
    const int rowA = wid * 16 + lane7 + lsub * 8;
    const uint32_t aOff = rowA * 128; const int aMod = rowA & 7;
    uint32_t xOff[4]; int xMod[4];
    #pragma unroll
    for (int i = 0; i < 4; i++) {
        int rx = i * 16 + lane7 + lsub * 8;
        xOff[i] = rx * 128; xMod[i] = rx & 7;
    }

    float accO[8][4];
    #pragma unroll
    for (int j = 0; j < 8; j++)
        #pragma unroll
        for (int i = 0; i < 4; i++) accO[j][i] = 0.f;
    float mrow[2] = {-1e30f, -1e30f}, lsum[2] = {0.f, 0.f};

    const int kend = 2 * qt + 1;
    for (int kt = 0; kt <= kend; kt++) {
        __syncthreads();
        if (kt < kend) {     // prefetch next K/V
            size_t src = (tok0 + (kt + 1) * 64 + ldk) * Dd + h * DHd;
            uint32_t base = 32768 + ((kt + 1) & 1) * 32768;
            #pragma unroll
            for (int j = 0; j < 2; j++) {
                int seg = segk0 + j;
                uint32_t off = ldk * 128 + ((seg ^ ldkm) << 4);
                cp16(sb + base + off,         kh + src + seg * 8);
                cp16(sb + base + 8192 + off,  kl + src + seg * 8);
                cp16(sb + base + 16384 + off, vh + src + seg * 8);
                cp16(sb + base + 24576 + off, vl + src + seg * 8);
            }
            asm volatile("cp.async.commit_group;\n");
            asm volatile("cp.async.wait_group 1;\n");
        } else {
            asm volatile("cp.async.wait_group 0;\n");
        }
        __syncthreads();

        const uint32_t kb = sb + 32768 + (kt & 1) * 32768;
        const uint32_t vb = kb + 16384;

        // ---- S = Q @ K^T (3 split terms) ----
        float accS[8][4];
        #pragma unroll
        for (int j = 0; j < 8; j++)
            #pragma unroll
            for (int i = 0; i < 4; i++) accS[j][i] = 0.f;

        #pragma unroll
        for (int kc = 0; kc < 4; kc++) {
            uint32_t ah[4], al[4];
            uint32_t sega = (uint32_t)(((kc * 2 + lhi) ^ aMod) << 4);
            ldsm4(ah[0], ah[1], ah[2], ah[3], sb + aOff + sega);
            ldsm4(al[0], al[1], al[2], al[3], sb + 16384 + aOff + sega);
            #pragma unroll
            for (int np = 0; np < 4; np++) {
                uint32_t segkk = (uint32_t)(((kc * 2 + lhi) ^ xMod[np]) << 4);
                uint32_t h0, h1, h2, h3, l0, l1, l2, l3;
                ldsm4(h0, h1, h2, h3, kb + xOff[np] + segkk);
                ldsm4(l0, l1, l2, l3, kb + 8192 + xOff[np] + segkk);
                MMA16(accS[2*np],   ah, h0, h2);
                MMA16(accS[2*np],   ah, l0, l2);
                MMA16(accS[2*np],   al, h0, h2);
                MMA16(accS[2*np+1], ah, h1, h3);
                MMA16(accS[2*np+1], ah, l1, l3);
                MMA16(accS[2*np+1], al, h1, h3);
            }
        }

        // ---- causal mask (global compare on boundary tiles) ----
        if (kt >= 2 * qt) {
            const int growb = qt * 128 + wid * 16 + lr;
            const int gcolb = kt * 64 + 2 * lc;
            #pragma unroll
            for (int j = 0; j < 8; j++)
                #pragma unroll
                for (int idx = 0; idx < 4; idx++) {
                    int gcol = gcolb + j * 8 + (idx & 1);
                    int grow = growb + (idx >> 1) * 8;
                    if (gcol > grow) accS[j][idx] = -1e30f;
                }
        }

        #pragma unroll
        for (int rr = 0; rr < 2; rr++) {
            float tm = -1e30f;
            #pragma unroll
            for (int j = 0; j < 8; j++) {
                tm = fmaxf(tm, accS[j][2*rr]);
                tm = fmaxf(tm, accS[j][2*rr+1]);
            }
            tm = fmaxf(tm, __shfl_xor_sync(0xffffffffu, tm, 1));
            tm = fmaxf(tm, __shfl_xor_sync(0xffffffffu, tm, 2));
            float mn = fmaxf(mrow[rr], tm);
            float alpha = fexp(mrow[rr] - mn);
            float rs = 0.f;
            #pragma unroll
            for (int j = 0; j < 8; j++) {
                float p0 = fexp(accS[j][2*rr]   - mn);
                float p1 = fexp(accS[j][2*rr+1] - mn);
                accS[j][2*rr] = p0; accS[j][2*rr+1] = p1;
                rs += p0 + p1;
            }
            rs += __shfl_xor_sync(0xffffffffu, rs, 1);
            rs += __shfl_xor_sync(0xffffffffu, rs, 2);
            lsum[rr] = lsum[rr] * alpha + rs;
            mrow[rr] = mn;
            #pragma unroll
            for (int j = 0; j < 8; j++) {
                accO[j][2*rr]   *= alpha;
                accO[j][2*rr+1] *= alpha;
            }
        }

        // ---- O += P @ V ----
        #pragma unroll
        for (int kc2 = 0; kc2 < 4; kc2++) {
            uint32_t pah[4], pal[4];
            split2(accS[2*kc2][0],   accS[2*kc2][1],   pah[0], pal[0]);
            split2(accS[2*kc2][2],   accS[2*kc2][3],   pah[1], pal[1]);
            split2(accS[2*kc2+1][0], accS[2*kc2+1][1], pah[2], pal[2]);
            split2(accS[2*kc2+1][2], accS[2*kc2+1][3], pah[3], pal[3]);
            #pragma unroll
            for (int dp = 0; dp < 4; dp++) {
                uint32_t segv = (uint32_t)(((dp * 2 + lhi) ^ xMod[kc2]) << 4);
                uint32_t h0, h1, h2, h3, l0, l1, l2, l3;
                ldsm4t(h0, h1, h2, h3, vb + xOff[kc2] + segv);
                ldsm4t(l0, l1, l2, l3, vb + 8192 + xOff[kc2] + segv);
                MMA16(accO[2*dp],   pah, h0, h1);
                MMA16(accO[2*dp],   pah, l0, l1);
                MMA16(accO[2*dp],   pal, h0, h1);
                MMA16(accO[2*dp+1], pah, h2, h3);
                MMA16(accO[2*dp+1], pah, l2, l3);
                MMA16(accO[2*dp+1], pal, h2, h3);
            }
        }
    }

    #pragma unroll
    for (int rr = 0; rr < 2; rr++) {
        float inv = 1.0f / lsum[rr];
        size_t base = (tok0 + qt * 128 + wid * 16 + lr + rr * 8) * Dd + h * DHd;
        #pragma unroll
        for (int j = 0; j < 8; j++) {
            float v0 = accO[j][2*rr] * inv, v1 = accO[j][2*rr+1] * inv;
            uint32_t hi, lo;
            split2(v0, v1, hi, lo);
            *(uint32_t*)&oh[base + j * 8 + 2 * lc] = hi;
            *(uint32_t*)&ol[base + j * 8 + 2 * lc] = lo;
        }
    }
}

// ---------------- router / scatter -----------------------------------------
__global__ void zero_cnt_k() { if (threadIdx.x < Ed) g_cnt[threadIdx.x] = 0; }

__global__ void router_k(const float* __restrict__ hn, const float* __restrict__ rw) {
    int warp = (blockIdx.x * blockDim.x + threadIdx.x) >> 5;
    int lane = threadIdx.x & 31;
    if (warp >= Td) return;
    const float* row = hn + (size_t)warp * Dd;
    float acc[Ed];
    #pragma unroll
    for (int e = 0; e < Ed; e++) acc[e] = 0.f;
    for (int d = lane; d < Dd; d += 32) {
        float x = row[d];
        #pragma unroll
        for (int e = 0; e < Ed; e++) acc[e] += x * rw[d * Ed + e];
    }
    #pragma unroll
    for (int e = 0; e < Ed; e++)
        #pragma unroll
        for (int o = 16; o; o >>= 1)
            acc[e] += __shfl_xor_sync(0xffffffffu, acc[e], o);
    if (lane == 0) {
        int i0 = 0;
        #pragma unroll
        for (int e = 1; e < Ed; e++) if (acc[e] > acc[i0]) i0 = e;
        int i1 = (i0 == 0) ? 1 : 0;
        #pragma unroll
        for (int e = 0; e < Ed; e++) if (e != i0 && acc[e] > acc[i1]) i1 = e;
        float ex = expf(acc[i1] - acc[i0]);
        float g0 = 1.f / (1.f + ex);
        float g1 = ex / (1.f + ex);
        g_eidx[warp * 2] = i0; g_eidx[warp * 2 + 1] = i1;
        g_gate[warp * 2] = g0; g_gate[warp * 2 + 1] = g1;
        atomicAdd(&g_cnt[i0], 1);
        atomicAdd(&g_cnt[i1], 1);
    }
}

__global__ void tiles_k() {
    int off = 0, nt = 0;
    for (int e = 0; e < Ed; e++) {
        g_off[e] = off; g_pos[e] = 0;
        int c = g_cnt[e];
        for (int r = 0; r < c; r += 128) {
            g_tile_e[nt] = e; g_tile_row[nt] = off + r; g_tile_end[nt] = off + c; nt++;
        }
        off += c;
    }
    g_off[Ed] = off;
    g_ntiles = nt;
}

__global__ void assign_k() {
    int t = blockIdx.x * blockDim.x + threadIdx.x;
    if (t >= Td) return;
    #pragma unroll
    for (int kk = 0; kk < 2; kk++) {
        int e = g_eidx[t * 2 + kk];
        int p = atomicAdd(&g_pos[e], 1);
        int slot = g_off[e] + p;
        g_slot_token[slot] = t;
        g_slot_of[t * 2 + kk] = slot;
    }
}

__global__ void final_k(float* __restrict__ out) {
    int idx = blockIdx.x * blockDim.x + threadIdx.x;
    if (idx >= Td * Dd) return;
    int t = idx >> 9, d = idx & 511;
    float r = g_h[idx];
    r += g_gate[t * 2]     * __half2float(g_yslot16[(size_t)g_slot_of[t * 2]     * Dd + d]);
    r += g_gate[t * 2 + 1] * __half2float(g_yslot16[(size_t)g_slot_of[t * 2 + 1] * Dd + d]);
    out[idx] = r;
}

// ---------------- launch -----------------------------------------------------
extern "C" void kernel_launch(void* const* d_in, const int* in_sizes, int n_in,
                              void* d_out, int out_size) {
    const float* x   = (const float*)d_in[0];
    const float* anw = (const float*)d_in[1];
    const float* wq  = (const float*)d_in[2];
    const float* wk  = (const float*)d_in[3];
    const float* wv  = (const float*)d_in[4];
    const float* wo  = (const float*)d_in[5];
    const float* fnw = (const float*)d_in[6];
    const float* rw  = (const float*)d_in[7];
    const float* w1  = (const float*)d_in[8];
    const float* w2  = (const float*)d_in[9];
    float* out = (float*)d_out;

    float *p_h, *p_hn;
    __half *p_xnh, *p_xnl, *p_qh, *p_ql, *p_kh, *p_kl, *p_vh, *p_vl;
    __half *p_atth, *p_attl, *p_hn16, *p_hidden16, *p_yslot16;
    __half *p_wqkvh, *p_wqkvl, *p_woh, *p_wol, *p_w1c, *p_w2c;
    cudaGetSymbolAddress((void**)&p_h, g_h);
    cudaGetSymbolAddress((void**)&p_hn, g_hn);
    cudaGetSymbolAddress((void**)&p_xnh, g_xnh);
    cudaGetSymbolAddress((void**)&p_xnl, g_xnl);
    cudaGetSymbolAddress((void**)&p_qh, g_qh);
    cudaGetSymbolAddress((void**)&p_ql, g_ql);
    cudaGetSymbolAddress((void**)&p_kh, g_kh);
    cudaGetSymbolAddress((void**)&p_kl, g_kl);
    cudaGetSymbolAddress((void**)&p_vh, g_vh);
    cudaGetSymbolAddress((void**)&p_vl, g_vl);
    cudaGetSymbolAddress((void**)&p_atth, g_atth);
    cudaGetSymbolAddress((void**)&p_attl, g_attl);
    cudaGetSymbolAddress((void**)&p_hn16, g_hn16);
    cudaGetSymbolAddress((void**)&p_hidden16, g_hidden16);
    cudaGetSymbolAddress((void**)&p_yslot16, g_yslot16);
    cudaGetSymbolAddress((void**)&p_wqkvh, g_wqkvh);
    cudaGetSymbolAddress((void**)&p_wqkvl, g_wqkvl);
    cudaGetSymbolAddress((void**)&p_woh, g_woh);
    cudaGetSymbolAddress((void**)&p_wol, g_wol);
    cudaGetSymbolAddress((void**)&p_w1c, g_w1c);
    cudaGetSymbolAddress((void**)&p_w2c, g_w2c);

    cudaFuncSetAttribute(sgemm_split<0>,
                         cudaFuncAttributeMaxDynamicSharedMemorySize, SMEM_S);
    cudaFuncSetAttribute(sgemm_split<1>,
                         cudaFuncAttributeMaxDynamicSharedMemorySize, SMEM_S);
    cudaFuncSetAttribute(hgemm_grp2<true, true, true>,
                         cudaFuncAttributeMaxDynamicSharedMemorySize, SMEM_H2);
    cudaFuncSetAttribute(hgemm_grp2<false, false, true>,
                         cudaFuncAttributeMaxDynamicSharedMemorySize, SMEM_H2);
    cudaFuncSetAttribute(attn_mma,
                         cudaFuncAttributeMaxDynamicSharedMemorySize, SMEM_ATT);

    // 0) weight preprocessing
    const int EW4 = (Ed * Dd * HFd) / 4;
    convert16_k<<<(EW4 + 255) / 256, 256>>>(w1, p_w1c, EW4);
    convert16_k<<<(EW4 + 255) / 256, 256>>>(w2, p_w2c, EW4);
    transpose_whl_k<<<dim3(Dd / 32, Dd / 32), dim3(32, 8)>>>(wq, p_wqkvh, p_wqkvl, Dd, Dd);
    transpose_whl_k<<<dim3(Dd / 32, Dd / 32), dim3(32, 8)>>>(wk, p_wqkvh + Dd * Dd,
                                                             p_wqkvl + Dd * Dd, Dd, Dd);
    transpose_whl_k<<<dim3(Dd / 32, Dd / 32), dim3(32, 8)>>>(wv, p_wqkvh + 2 * Dd * Dd,
                                                             p_wqkvl + 2 * Dd * Dd, Dd, Dd);
    transpose_whl_k<<<dim3(Dd / 32, Dd / 32), dim3(32, 8)>>>(wo, p_woh, p_wol, Dd, Dd);
    // 1) rmsnorm(x) -> hi/lo fp16
    rmsnorm_k<<<Td, 256>>>(x, anw, nullptr, p_xnh, p_xnl);
    // 2) fused QKV split-fp16 GEMM with fused RoPE + q-scale, hi/lo fp16 out
    sgemm_split<0><<<dim3(Td / 128, Dd / 128, 3), 256, SMEM_S>>>(
        p_xnh, p_xnl, p_wqkvh, p_wqkvl,
        p_qh, p_ql, p_kh, p_kl, p_vh, p_vl, nullptr, nullptr, Dd, Dd);
    // 3) causal attention (split-fp16 mma; 128-row q tiles; double-buffered KV)
    attn_mma<<<dim3(Bd * Hd, Sd / 128), 256, SMEM_ATT>>>(
        p_qh, p_ql, p_kh, p_kl, p_vh, p_vl, p_atth, p_attl);
    // 4) O projection + residual (split-fp16, fp32 out)
    sgemm_split<1><<<dim3(Td / 128, Dd / 128, 1), 256, SMEM_S>>>(
        p_atth, p_attl, p_woh, p_wol,
        nullptr, nullptr, nullptr, nullptr, nullptr, nullptr, p_h, x, Dd, Dd);
    // 5) rmsnorm(h) -> fp32 (router) + fp16 (MoE)
    rmsnorm_k<<<Td, 256>>>(p_h, fnw, p_hn, p_hn16, nullptr);
    // 6) router + expert grouping (fp32 logits)
    zero_cnt_k<<<1, 32>>>();
    router_k<<<Td / 8, 256>>>(p_hn, rw);
    tiles_k<<<1, 1>>>();
    assign_k<<<Td / 256, 256>>>();
    // 7) expert GEMM 1: hidden16 = gelu(hn16 @ w1[e])   [trans-B]
    hgemm_grp2<true, true, true><<<dim3(MAXTILES, HFd / 128), 256, SMEM_H2>>>(
        p_hn16, p_w1c, p_hidden16, HFd, Dd);
    // 8) expert GEMM 2: yslot16 = hidden16 @ w2[e] (fp16 out)
    hgemm_grp2<false, false, true><<<dim3(MAXTILES, Dd / 128), 256, SMEM_H2>>>(
        p_hidden16, p_w2c, p_yslot16, Dd, HFd);
    // 9) final gather + residual
    final_k<<<(Td * Dd) / 256, 256>>>(out);
}